// round 4
// baseline (speedup 1.0000x reference)
#include <cuda_runtime.h>
#include <cuda_bf16.h>
#include <math.h>
#include <stdint.h>

// Shapes (fixed): B=64, TQ=64, TP=1024, H=A=1024
#define NB  64
#define Hn  1024

// ---------------- scratch (__device__ globals) --------------------------------
__device__ float g_PK[67108864];                 // 256MB logits-GEMM output
__device__ __nv_bfloat16 g_Ah[67108864];         // passage hi
__device__ __nv_bfloat16 g_Al[67108864];         // passage lo
__device__ __nv_bfloat16 g_Qh[4194304];          // question hi
__device__ __nv_bfloat16 g_Ql[4194304];          // question lo
__device__ __nv_bfloat16 g_Bqh[1048576], g_Bql[1048576];  // Wk_q hi/lo [k][n]
__device__ __nv_bfloat16 g_Bph[1048576], g_Bpl[1048576];  // Wk_p hi/lo [k][n]
__device__ float g_sq[NB * 64];
__device__ float g_alpha[NB * 1024];
__device__ float g_hidden[NB * Hn];
__device__ float g_inputs[NB * Hn];
__device__ float g_gout[NB * Hn];
__device__ float g_Q1[NB * Hn];
__device__ float g_Q2[NB * Hn];
__device__ float g_cq[Hn];
__device__ float g_gi[NB * 3 * Hn];
__device__ float g_gh[NB * 3 * Hn];

// ---------------- helpers -----------------------------------------------------
__device__ __forceinline__ float fast_tanh(float x) {
    float e = __expf(fminf(2.0f * x, 80.0f));
    return 1.0f - __fdividef(2.0f, e + 1.0f);
}
__device__ __forceinline__ uint32_t smem_u32(const void* p) {
    uint32_t a;
    asm("{ .reg .u64 t; cvta.to.shared.u64 t, %1; cvt.u32.u64 %0, t; }" : "=r"(a) : "l"(p));
    return a;
}
__device__ __forceinline__ void cpa16(uint32_t s, const void* g) {
    asm volatile("cp.async.cg.shared.global [%0], [%1], 16;" :: "r"(s), "l"(g));
}
__device__ __forceinline__ void ldsm_x4u(uint32_t* r, uint32_t a) {
    asm volatile("ldmatrix.sync.aligned.m8n8.x4.shared.b16 {%0,%1,%2,%3}, [%4];"
                 : "=r"(r[0]), "=r"(r[1]), "=r"(r[2]), "=r"(r[3]) : "r"(a));
}
__device__ __forceinline__ void ldsm_x4t_u(uint32_t* r, uint32_t a) {
    asm volatile("ldmatrix.sync.aligned.m8n8.x4.trans.shared.b16 {%0,%1,%2,%3}, [%4];"
                 : "=r"(r[0]), "=r"(r[1]), "=r"(r[2]), "=r"(r[3]) : "r"(a));
}
__device__ __forceinline__ void mma_bf16(float* d, const uint32_t* a, const uint32_t* b) {
    asm volatile(
        "mma.sync.aligned.m16n8k16.row.col.f32.bf16.bf16.f32 "
        "{%0,%1,%2,%3}, {%4,%5,%6,%7}, {%8,%9}, {%0,%1,%2,%3};"
        : "+f"(d[0]), "+f"(d[1]), "+f"(d[2]), "+f"(d[3])
        : "r"(a[0]), "r"(a[1]), "r"(a[2]), "r"(a[3]), "r"(b[0]), "r"(b[1]));
}

// ---------------- pre-split: fp32 -> bf16 hi + lo -----------------------------
__global__ __launch_bounds__(256) void split_k(const float* __restrict__ src,
                                               __nv_bfloat16* __restrict__ hi,
                                               __nv_bfloat16* __restrict__ lo) {
    int i = blockIdx.x * 256 + threadIdx.x;  // one float4
    float4 v = ((const float4*)src)[i];
    __nv_bfloat16 h0 = __float2bfloat16(v.x), h1 = __float2bfloat16(v.y);
    __nv_bfloat16 h2 = __float2bfloat16(v.z), h3 = __float2bfloat16(v.w);
    __nv_bfloat162* hp = (__nv_bfloat162*)hi;
    __nv_bfloat162* lp = (__nv_bfloat162*)lo;
    hp[2 * i]     = __halves2bfloat162(h0, h1);
    hp[2 * i + 1] = __halves2bfloat162(h2, h3);
    lp[2 * i]     = __halves2bfloat162(__float2bfloat16(v.x - __bfloat162float(h0)),
                                       __float2bfloat16(v.y - __bfloat162float(h1)));
    lp[2 * i + 1] = __halves2bfloat162(__float2bfloat16(v.z - __bfloat162float(h2)),
                                       __float2bfloat16(v.w - __bfloat162float(h3)));
}

// ---------------- pipelined split-bf16 mma.sync GEMM --------------------------
// C[M,1024] = A[M,1024] @ W[1024,1024]; pre-split bf16 (A [m][k], W [k][n]).
// CTA 128x128, K-chunk 64, 3-stage cp.async pipeline, 8 warps (2x4), 3 passes.
// Stage layout (bytes, from stage base):
//   Ah: 128 rows x 144B (72 halves)   @ 0       (18432)
//   Al:                                @ 18432
//   Bh: 64 rows x 272B (136 halves)    @ 36864   (17408)
//   Bl:                                @ 54272
#define STG 71680
__device__ __forceinline__ void load_chunk(uint32_t st,
                                           const __nv_bfloat16* Ah, const __nv_bfloat16* Al,
                                           const __nv_bfloat16* Bh, const __nv_bfloat16* Bl,
                                           int row0, int col0, int k0, int tid) {
#pragma unroll
    for (int j = 0; j < 4; j++) {          // A: 128 rows x 64 halves (hi+lo)
        int s = tid + j * 256;
        int r = s >> 3, c8 = s & 7;
        uint32_t so = (uint32_t)(r * 144 + c8 * 16);
        size_t go = (size_t)(row0 + r) * 1024 + k0 + c8 * 8;
        cpa16(st + so,          Ah + go);
        cpa16(st + 18432 + so,  Al + go);
    }
#pragma unroll
    for (int j = 0; j < 4; j++) {          // B: 64 k-rows x 128 halves (hi+lo)
        int s = tid + j * 256;
        int r = s >> 4, c8 = s & 15;
        uint32_t so = (uint32_t)(r * 272 + c8 * 16);
        size_t go = (size_t)(k0 + r) * 1024 + col0 + c8 * 8;
        cpa16(st + 36864 + so,  Bh + go);
        cpa16(st + 54272 + so,  Bl + go);
    }
    asm volatile("cp.async.commit_group;" ::: "memory");
}

__global__ __launch_bounds__(256, 1) void mma2_k(const __nv_bfloat16* __restrict__ Ah,
                                                 const __nv_bfloat16* __restrict__ Al,
                                                 const __nv_bfloat16* __restrict__ Bh,
                                                 const __nv_bfloat16* __restrict__ Bl,
                                                 float* __restrict__ C) {
    extern __shared__ char dsm[];
    uint32_t sb  = smem_u32(dsm);
    uint32_t sba = (sb + 1023u) & ~1023u;
    const int tid = threadIdx.x;
    const int warp = tid >> 5, lane = tid & 31;
    const int wm = warp >> 2, wn = warp & 3;
    const int row0 = blockIdx.y * 128, col0 = blockIdx.x * 128;

    float acc[4][4][4];
#pragma unroll
    for (int i = 0; i < 4; i++)
#pragma unroll
        for (int j = 0; j < 4; j++)
#pragma unroll
            for (int v = 0; v < 4; v++) acc[i][j][v] = 0.f;

    load_chunk(sba,       Ah, Al, Bh, Bl, row0, col0, 0,  tid);
    load_chunk(sba + STG, Ah, Al, Bh, Bl, row0, col0, 64, tid);

    for (int c = 0; c < 16; c++) {
        if (c < 14) asm volatile("cp.async.wait_group 1;" ::: "memory");
        else        asm volatile("cp.async.wait_group 0;" ::: "memory");
        __syncthreads();
        if (c + 2 < 16)
            load_chunk(sba + ((c + 2) % 3) * STG, Ah, Al, Bh, Bl, row0, col0, (c + 2) * 64, tid);

        const uint32_t st   = sba + (c % 3) * STG;
        const uint32_t aB   = st;
        const uint32_t alB  = st + 18432;
        const uint32_t bB   = st + 36864;
        const uint32_t blB  = st + 54272;
        const int arow = lane & 15, acol = (lane >> 4) << 3;
        const int bkrl = lane & 15, bcb = wn * 32 + ((lane >> 4) << 3);
#pragma unroll
        for (int kk = 0; kk < 64; kk += 16) {
            uint32_t ah[4][4], al[4][4], bh[2][4], bl[2][4];
#pragma unroll
            for (int mi = 0; mi < 4; mi++) {
                uint32_t off = (uint32_t)((wm * 64 + mi * 16 + arow) * 144 + (kk + acol) * 2);
                ldsm_x4u(ah[mi], aB + off);
                ldsm_x4u(al[mi], alB + off);
            }
#pragma unroll
            for (int ni = 0; ni < 2; ni++) {
                uint32_t off = (uint32_t)((kk + bkrl) * 272 + (bcb + ni * 16) * 2);
                ldsm_x4t_u(bh[ni], bB + off);
                ldsm_x4t_u(bl[ni], blB + off);
            }
#pragma unroll
            for (int mi = 0; mi < 4; mi++)
#pragma unroll
                for (int nj = 0; nj < 4; nj++) {
                    int ni = nj >> 1, p = (nj & 1) * 2;
                    mma_bf16(acc[mi][nj], ah[mi], &bh[ni][p]);   // hi*hi
                    mma_bf16(acc[mi][nj], ah[mi], &bl[ni][p]);   // hi*lo
                    mma_bf16(acc[mi][nj], al[mi], &bh[ni][p]);   // lo*hi
                }
        }
    }

    const int rbase = row0 + wm * 64, cbase = col0 + wn * 32;
    const int lr = lane >> 2, lc = (lane & 3) * 2;
#pragma unroll
    for (int mi = 0; mi < 4; mi++)
#pragma unroll
        for (int nj = 0; nj < 4; nj++) {
            int rr = rbase + mi * 16 + lr;
            int cc = cbase + nj * 8 + lc;
            *(float2*)&C[(size_t)rr * 1024 + cc] =
                make_float2(acc[mi][nj][0], acc[mi][nj][1]);
            *(float2*)&C[(size_t)(rr + 8) * 1024 + cc] =
                make_float2(acc[mi][nj][2], acc[mi][nj][3]);
        }
}

// ---------------- score / softmax / pool / linears / GRU (proven) -------------
__global__ __launch_bounds__(256) void score_k(const float* __restrict__ C,
                                               const float* __restrict__ qterm,
                                               const float* __restrict__ wv,
                                               const float* __restrict__ mask,
                                               float* __restrict__ outs, int per_row) {
    const int r = blockIdx.x, tid = threadIdx.x;
    __shared__ float red[8];
    const float* crow = C + (size_t)r * 1024;
    const float* q = per_row ? (qterm + (size_t)(r >> 10) * 1024) : qterm;
    float acc = 0.f;
    for (int c = tid; c < 1024; c += 256)
        acc += wv[c] * fast_tanh(crow[c] + q[c]);
    for (int o = 16; o; o >>= 1) acc += __shfl_xor_sync(0xffffffffu, acc, o);
    if ((tid & 31) == 0) red[tid >> 5] = acc;
    __syncthreads();
    if (tid == 0) {
        float s = 0.f;
#pragma unroll
        for (int w = 0; w < 8; w++) s += red[w];
        outs[r] = (mask[r] > 0.f) ? s : -1e30f;
    }
}

__global__ __launch_bounds__(256) void softmax_k(const float* __restrict__ s,
                                                 float* __restrict__ alpha, int T) {
    const int b = blockIdx.x, tid = threadIdx.x;
    __shared__ float red[8];
    __shared__ float sh;
    const float* sb = s + (size_t)b * T;
    float mx = -3.0e38f;
    for (int t = tid; t < T; t += 256) mx = fmaxf(mx, sb[t]);
    for (int o = 16; o; o >>= 1) mx = fmaxf(mx, __shfl_xor_sync(0xffffffffu, mx, o));
    if ((tid & 31) == 0) red[tid >> 5] = mx;
    __syncthreads();
    if (tid == 0) {
        float v = red[0];
#pragma unroll
        for (int w = 1; w < 8; w++) v = fmaxf(v, red[w]);
        sh = v;
    }
    __syncthreads();
    mx = sh;
    float sum = 0.f;
    for (int t = tid; t < T; t += 256) {
        float e = expf(sb[t] - mx);
        alpha[(size_t)b * T + t] = e;
        sum += e;
    }
    for (int o = 16; o; o >>= 1) sum += __shfl_xor_sync(0xffffffffu, sum, o);
    __syncthreads();
    if ((tid & 31) == 0) red[tid >> 5] = sum;
    __syncthreads();
    if (tid == 0) {
        float v = 0.f;
#pragma unroll
        for (int w = 0; w < 8; w++) v += red[w];
        sh = 1.f / v;
    }
    __syncthreads();
    float inv = sh;
    for (int t = tid; t < T; t += 256) alpha[(size_t)b * T + t] *= inv;
}

__global__ __launch_bounds__(256) void pool_k(const float* __restrict__ key,
                                              const float* __restrict__ alpha,
                                              float* __restrict__ out, int T) {
    const int b = blockIdx.x;
    const int h = blockIdx.y * 256 + threadIdx.x;
    const float* kb = key + (size_t)b * T * 1024 + h;
    const float* ab = alpha + (size_t)b * T;
    float a0 = 0.f, a1 = 0.f, a2 = 0.f, a3 = 0.f;
    for (int t = 0; t < T; t += 4) {
        a0 += ab[t + 0] * kb[(size_t)(t + 0) * 1024];
        a1 += ab[t + 1] * kb[(size_t)(t + 1) * 1024];
        a2 += ab[t + 2] * kb[(size_t)(t + 2) * 1024];
        a3 += ab[t + 3] * kb[(size_t)(t + 3) * 1024];
    }
    out[(size_t)b * 1024 + h] = (a0 + a1) + (a2 + a3);
}

__global__ __launch_bounds__(256) void xw_k(const float* __restrict__ x,
                                            const float* __restrict__ W,
                                            float* __restrict__ out) {
    const int b = blockIdx.y;
    const int j = blockIdx.x * 256 + threadIdx.x;
    __shared__ float xs[1024];
    for (int i = threadIdx.x; i < 1024; i += 256) xs[i] = x[(size_t)b * 1024 + i];
    __syncthreads();
    const float* Wc = W + j;
    float a0 = 0.f, a1 = 0.f, a2 = 0.f, a3 = 0.f;
    for (int h = 0; h < 1024; h += 4) {
        a0 += xs[h + 0] * Wc[(size_t)(h + 0) * 1024];
        a1 += xs[h + 1] * Wc[(size_t)(h + 1) * 1024];
        a2 += xs[h + 2] * Wc[(size_t)(h + 2) * 1024];
        a3 += xs[h + 3] * Wc[(size_t)(h + 3) * 1024];
    }
    out[(size_t)b * 1024 + j] = (a0 + a1) + (a2 + a3);
}

__global__ __launch_bounds__(256) void rowdot_k(const float* __restrict__ x,
                                                const float* __restrict__ W,
                                                const float* __restrict__ bias,
                                                float* __restrict__ out, int N) {
    const int b = blockIdx.y;
    const int w = threadIdx.x >> 5, lane = threadIdx.x & 31;
    const int j = blockIdx.x * 8 + w;
    const float* xr = x + (size_t)b * 1024;
    const float* wr = W + (size_t)j * 1024;
    float a0 = 0.f, a1 = 0.f;
    for (int h = lane; h < 1024; h += 64) {
        a0 += xr[h] * wr[h];
        a1 += xr[h + 32] * wr[h + 32];
    }
    float acc = a0 + a1;
    for (int o = 16; o; o >>= 1) acc += __shfl_xor_sync(0xffffffffu, acc, o);
    if (!lane) out[(size_t)b * N + j] = acc + bias[j];
}

__global__ __launch_bounds__(256) void gru_k() {
    const int i = blockIdx.x * 256 + threadIdx.x;
    const int b = i >> 10, h = i & 1023;
    const float* gi = g_gi + (size_t)b * 3072;
    const float* gh = g_gh + (size_t)b * 3072;
    float r = 1.f / (1.f + expf(-(gi[h] + gh[h])));
    float z = 1.f / (1.f + expf(-(gi[1024 + h] + gh[1024 + h])));
    float n = tanhf(gi[2048 + h] + r * gh[2048 + h]);
    g_gout[i] = (1.f - z) * n + z * g_hidden[i];
}

// ---------------- launch ------------------------------------------------------
extern "C" void kernel_launch(void* const* d_in, const int* in_sizes, int n_in,
                              void* d_out, int out_size) {
    const float* question = (const float*)d_in[0];
    const float* qmask    = (const float*)d_in[1];
    const float* passage  = (const float*)d_in[2];
    const float* pmask    = (const float*)d_in[3];
    const float* Vq       = (const float*)d_in[4];
    const float* Wk_q     = (const float*)d_in[5];
    const float* Wq_q     = (const float*)d_in[6];
    const float* w_q      = (const float*)d_in[7];
    const float* Wk_p     = (const float*)d_in[8];
    const float* Wq_p     = (const float*)d_in[9];
    const float* w_p      = (const float*)d_in[10];
    const float* W_ih     = (const float*)d_in[11];
    const float* W_hh     = (const float*)d_in[12];
    const float* b_ih     = (const float*)d_in[13];
    const float* b_hh     = (const float*)d_in[14];
    float* out = (float*)d_out;

    float *pPK, *psq, *palpha, *phid, *pinp, *pgout, *pQ1, *pQ2, *pcq, *pgi, *pgh;
    __nv_bfloat16 *pAh, *pAl, *pQh, *pQl, *pBqh, *pBql, *pBph, *pBpl;
    cudaGetSymbolAddress((void**)&pPK,   g_PK);
    cudaGetSymbolAddress((void**)&psq,   g_sq);
    cudaGetSymbolAddress((void**)&palpha,g_alpha);
    cudaGetSymbolAddress((void**)&phid,  g_hidden);
    cudaGetSymbolAddress((void**)&pinp,  g_inputs);
    cudaGetSymbolAddress((void**)&pgout, g_gout);
    cudaGetSymbolAddress((void**)&pQ1,   g_Q1);
    cudaGetSymbolAddress((void**)&pQ2,   g_Q2);
    cudaGetSymbolAddress((void**)&pcq,   g_cq);
    cudaGetSymbolAddress((void**)&pgi,   g_gi);
    cudaGetSymbolAddress((void**)&pgh,   g_gh);
    cudaGetSymbolAddress((void**)&pAh,   g_Ah);
    cudaGetSymbolAddress((void**)&pAl,   g_Al);
    cudaGetSymbolAddress((void**)&pQh,   g_Qh);
    cudaGetSymbolAddress((void**)&pQl,   g_Ql);
    cudaGetSymbolAddress((void**)&pBqh,  g_Bqh);
    cudaGetSymbolAddress((void**)&pBql,  g_Bql);
    cudaGetSymbolAddress((void**)&pBph,  g_Bph);
    cudaGetSymbolAddress((void**)&pBpl,  g_Bpl);

    cudaFuncSetAttribute(mma2_k, cudaFuncAttributeMaxDynamicSharedMemorySize, 3 * STG + 1024);

    // pre-split conversions (Wk_* already [k][n]; no transpose needed)
    split_k<<<1024, 256>>>(Wk_q, pBqh, pBql);
    split_k<<<1024, 256>>>(Wk_p, pBph, pBpl);
    split_k<<<4096, 256>>>(question, pQh, pQl);
    split_k<<<65536, 256>>>(passage, pAh, pAl);

    // question branch
    xw_k<<<dim3(4, 1), 256>>>(Vq, Wq_q, pcq);
    mma2_k<<<dim3(8, 32), 256, 3 * STG + 1024>>>(pQh, pQl, pBqh, pBql, pPK);
    score_k<<<4096, 256>>>(pPK, pcq, w_q, qmask, psq, 0);
    softmax_k<<<64, 256>>>(psq, palpha, 64);
    pool_k<<<dim3(64, 4), 256>>>(question, palpha, phid, 64);
    xw_k<<<dim3(4, 64), 256>>>(phid, Wq_p, pQ1);

    // passage branch (dominant GEMM, computed once)
    mma2_k<<<dim3(8, 512), 256, 3 * STG + 1024>>>(pAh, pAl, pBph, pBpl, pPK);
    score_k<<<65536, 256>>>(pPK, pQ1, w_p, pmask, out, 1);
    softmax_k<<<64, 256>>>(out, palpha, 1024);
    pool_k<<<dim3(64, 4), 256>>>(passage, palpha, pinp, 1024);

    // GRU + end logits
    rowdot_k<<<dim3(384, 64), 256>>>(pinp, W_ih, b_ih, pgi, 3072);
    rowdot_k<<<dim3(384, 64), 256>>>(phid, W_hh, b_hh, pgh, 3072);
    gru_k<<<256, 256>>>();
    xw_k<<<dim3(4, 64), 256>>>(pgout, Wq_p, pQ2);
    score_k<<<65536, 256>>>(pPK, pQ2, w_p, pmask, out + 65536, 1);
}

// round 5
// speedup vs baseline: 1.1895x; 1.1895x over previous
#include <cuda_runtime.h>
#include <cuda_fp16.h>
#include <math.h>
#include <stdint.h>

// Shapes (fixed): B=64, TQ=64, TP=1024, H=A=1024
#define NB  64
#define Hn  1024

// ---------------- scratch (__device__ globals) --------------------------------
__device__ float g_PK[67108864];                 // 256MB logits-GEMM output
__device__ __half g_Ah[67108864];                // passage hi (fp16)
__device__ __half g_Al[67108864];                // passage lo (fp16)
__device__ __half g_Qh[4194304];                 // question hi
__device__ __half g_Ql[4194304];                 // question lo
__device__ __half g_Bqh[1048576];                // Wk_q fp16 [k][n]
__device__ __half g_Bph[1048576];                // Wk_p fp16 [k][n]
__device__ float g_sq[NB * 64];
__device__ float g_alpha[NB * 1024];
__device__ float g_hidden[NB * Hn];
__device__ float g_inputs[NB * Hn];
__device__ float g_gout[NB * Hn];
__device__ float g_Q1[NB * Hn];
__device__ float g_Q2[NB * Hn];
__device__ float g_cq[Hn];
__device__ float g_gi[NB * 3 * Hn];
__device__ float g_gh[NB * 3 * Hn];

// ---------------- helpers -----------------------------------------------------
__device__ __forceinline__ float fast_tanh(float x) {
    float e = __expf(fminf(2.0f * x, 80.0f));
    return 1.0f - __fdividef(2.0f, e + 1.0f);
}
__device__ __forceinline__ uint32_t smem_u32(const void* p) {
    uint32_t a;
    asm("{ .reg .u64 t; cvta.to.shared.u64 t, %1; cvt.u32.u64 %0, t; }" : "=r"(a) : "l"(p));
    return a;
}
__device__ __forceinline__ void cpa16(uint32_t s, const void* g) {
    asm volatile("cp.async.cg.shared.global [%0], [%1], 16;" :: "r"(s), "l"(g));
}
__device__ __forceinline__ void ldsm_x4u(uint32_t* r, uint32_t a) {
    asm volatile("ldmatrix.sync.aligned.m8n8.x4.shared.b16 {%0,%1,%2,%3}, [%4];"
                 : "=r"(r[0]), "=r"(r[1]), "=r"(r[2]), "=r"(r[3]) : "r"(a));
}
__device__ __forceinline__ void ldsm_x4t_u(uint32_t* r, uint32_t a) {
    asm volatile("ldmatrix.sync.aligned.m8n8.x4.trans.shared.b16 {%0,%1,%2,%3}, [%4];"
                 : "=r"(r[0]), "=r"(r[1]), "=r"(r[2]), "=r"(r[3]) : "r"(a));
}
__device__ __forceinline__ void mma_f16(float* d, const uint32_t* a, const uint32_t* b) {
    asm volatile(
        "mma.sync.aligned.m16n8k16.row.col.f32.f16.f16.f32 "
        "{%0,%1,%2,%3}, {%4,%5,%6,%7}, {%8,%9}, {%0,%1,%2,%3};"
        : "+f"(d[0]), "+f"(d[1]), "+f"(d[2]), "+f"(d[3])
        : "r"(a[0]), "r"(a[1]), "r"(a[2]), "r"(a[3]), "r"(b[0]), "r"(b[1]));
}

// ---------------- pre-split: fp32 -> fp16 hi + lo -----------------------------
__global__ __launch_bounds__(256) void splitA_k(const float* __restrict__ src,
                                                __half* __restrict__ hi,
                                                __half* __restrict__ lo) {
    int i = blockIdx.x * 256 + threadIdx.x;  // one float4
    float4 v = ((const float4*)src)[i];
    __half h0 = __float2half(v.x), h1 = __float2half(v.y);
    __half h2 = __float2half(v.z), h3 = __float2half(v.w);
    __half2* hp = (__half2*)hi;
    __half2* lp = (__half2*)lo;
    hp[2 * i]     = __halves2half2(h0, h1);
    hp[2 * i + 1] = __halves2half2(h2, h3);
    lp[2 * i]     = __halves2half2(__float2half(v.x - __half2float(h0)),
                                   __float2half(v.y - __half2float(h1)));
    lp[2 * i + 1] = __halves2half2(__float2half(v.z - __half2float(h2)),
                                   __float2half(v.w - __half2float(h3)));
}
__global__ __launch_bounds__(256) void cvtB_k(const float* __restrict__ src,
                                              __half* __restrict__ hi) {
    int i = blockIdx.x * 256 + threadIdx.x;
    float4 v = ((const float4*)src)[i];
    __half2* hp = (__half2*)hi;
    hp[2 * i]     = __halves2half2(__float2half(v.x), __float2half(v.y));
    hp[2 * i + 1] = __halves2half2(__float2half(v.z), __float2half(v.w));
}

// ---------------- pipelined 2-pass fp16 mma.sync GEMM -------------------------
// C[M,1024] = A[M,1024] @ W[1024,1024]; A = Ah+Al fp16, W = Bh fp16 [k][n].
// CTA 128x128, K-chunk 64, 3-stage cp.async pipeline, 8 warps (2x4), 2 passes.
// Stage layout: Ah 128x144B @0 (18432) | Al @18432 | Bh 64x272B @36864 (17408)
#define STG 54272
__device__ __forceinline__ void load_chunk(uint32_t st,
                                           const __half* Ah, const __half* Al,
                                           const __half* Bh,
                                           int row0, int col0, int k0, int tid) {
#pragma unroll
    for (int j = 0; j < 4; j++) {          // A: 128 rows x 64 halves (hi+lo)
        int s = tid + j * 256;
        int r = s >> 3, c8 = s & 7;
        uint32_t so = (uint32_t)(r * 144 + c8 * 16);
        size_t go = (size_t)(row0 + r) * 1024 + k0 + c8 * 8;
        cpa16(st + so,         Ah + go);
        cpa16(st + 18432 + so, Al + go);
    }
#pragma unroll
    for (int j = 0; j < 4; j++) {          // B: 64 k-rows x 128 halves
        int s = tid + j * 256;
        int r = s >> 4, c8 = s & 15;
        uint32_t so = (uint32_t)(r * 272 + c8 * 16);
        size_t go = (size_t)(k0 + r) * 1024 + col0 + c8 * 8;
        cpa16(st + 36864 + so, Bh + go);
    }
    asm volatile("cp.async.commit_group;" ::: "memory");
}

__global__ __launch_bounds__(256, 1) void mma2_k(const __half* __restrict__ Ah,
                                                 const __half* __restrict__ Al,
                                                 const __half* __restrict__ Bh,
                                                 float* __restrict__ C) {
    extern __shared__ char dsm[];
    uint32_t sb  = smem_u32(dsm);
    uint32_t sba = (sb + 1023u) & ~1023u;
    const int tid = threadIdx.x;
    const int warp = tid >> 5, lane = tid & 31;
    const int wm = warp >> 2, wn = warp & 3;
    const int row0 = blockIdx.y * 128, col0 = blockIdx.x * 128;

    float acc[4][4][4];
#pragma unroll
    for (int i = 0; i < 4; i++)
#pragma unroll
        for (int j = 0; j < 4; j++)
#pragma unroll
            for (int v = 0; v < 4; v++) acc[i][j][v] = 0.f;

    load_chunk(sba,       Ah, Al, Bh, row0, col0, 0,  tid);
    load_chunk(sba + STG, Ah, Al, Bh, row0, col0, 64, tid);

    for (int c = 0; c < 16; c++) {
        if (c < 14) asm volatile("cp.async.wait_group 1;" ::: "memory");
        else        asm volatile("cp.async.wait_group 0;" ::: "memory");
        __syncthreads();
        if (c + 2 < 16)
            load_chunk(sba + ((c + 2) % 3) * STG, Ah, Al, Bh, row0, col0, (c + 2) * 64, tid);

        const uint32_t st  = sba + (c % 3) * STG;
        const uint32_t aB  = st;
        const uint32_t alB = st + 18432;
        const uint32_t bB  = st + 36864;
        const int arow = lane & 15, acol = (lane >> 4) << 3;
        const int bkrl = lane & 15, bcb = wn * 32 + ((lane >> 4) << 3);
#pragma unroll
        for (int kk = 0; kk < 64; kk += 16) {
            uint32_t ah[4][4], al[4][4], bh[2][4];
#pragma unroll
            for (int mi = 0; mi < 4; mi++) {
                uint32_t off = (uint32_t)((wm * 64 + mi * 16 + arow) * 144 + (kk + acol) * 2);
                ldsm_x4u(ah[mi], aB + off);
                ldsm_x4u(al[mi], alB + off);
            }
#pragma unroll
            for (int ni = 0; ni < 2; ni++) {
                uint32_t off = (uint32_t)((kk + bkrl) * 272 + (bcb + ni * 16) * 2);
                ldsm_x4t_u(bh[ni], bB + off);
            }
#pragma unroll
            for (int mi = 0; mi < 4; mi++)
#pragma unroll
                for (int nj = 0; nj < 4; nj++) {
                    int ni = nj >> 1, p = (nj & 1) * 2;
                    mma_f16(acc[mi][nj], ah[mi], &bh[ni][p]);   // hi*B
                    mma_f16(acc[mi][nj], al[mi], &bh[ni][p]);   // lo*B
                }
        }
    }

    const int rbase = row0 + wm * 64, cbase = col0 + wn * 32;
    const int lr = lane >> 2, lc = (lane & 3) * 2;
#pragma unroll
    for (int mi = 0; mi < 4; mi++)
#pragma unroll
        for (int nj = 0; nj < 4; nj++) {
            int rr = rbase + mi * 16 + lr;
            int cc = cbase + nj * 8 + lc;
            *(float2*)&C[(size_t)rr * 1024 + cc] =
                make_float2(acc[mi][nj][0], acc[mi][nj][1]);
            *(float2*)&C[(size_t)(rr + 8) * 1024 + cc] =
                make_float2(acc[mi][nj][2], acc[mi][nj][3]);
        }
}

// ---------------- score / softmax / pool / linears / GRU (proven) -------------
__global__ __launch_bounds__(256) void score_k(const float* __restrict__ C,
                                               const float* __restrict__ qterm,
                                               const float* __restrict__ wv,
                                               const float* __restrict__ mask,
                                               float* __restrict__ outs, int per_row) {
    const int r = blockIdx.x, tid = threadIdx.x;
    __shared__ float red[8];
    const float* crow = C + (size_t)r * 1024;
    const float* q = per_row ? (qterm + (size_t)(r >> 10) * 1024) : qterm;
    float acc = 0.f;
    for (int c = tid; c < 1024; c += 256)
        acc += wv[c] * fast_tanh(crow[c] + q[c]);
    for (int o = 16; o; o >>= 1) acc += __shfl_xor_sync(0xffffffffu, acc, o);
    if ((tid & 31) == 0) red[tid >> 5] = acc;
    __syncthreads();
    if (tid == 0) {
        float s = 0.f;
#pragma unroll
        for (int w = 0; w < 8; w++) s += red[w];
        outs[r] = (mask[r] > 0.f) ? s : -1e30f;
    }
}

__global__ __launch_bounds__(256) void softmax_k(const float* __restrict__ s,
                                                 float* __restrict__ alpha, int T) {
    const int b = blockIdx.x, tid = threadIdx.x;
    __shared__ float red[8];
    __shared__ float sh;
    const float* sb = s + (size_t)b * T;
    float mx = -3.0e38f;
    for (int t = tid; t < T; t += 256) mx = fmaxf(mx, sb[t]);
    for (int o = 16; o; o >>= 1) mx = fmaxf(mx, __shfl_xor_sync(0xffffffffu, mx, o));
    if ((tid & 31) == 0) red[tid >> 5] = mx;
    __syncthreads();
    if (tid == 0) {
        float v = red[0];
#pragma unroll
        for (int w = 1; w < 8; w++) v = fmaxf(v, red[w]);
        sh = v;
    }
    __syncthreads();
    mx = sh;
    float sum = 0.f;
    for (int t = tid; t < T; t += 256) {
        float e = expf(sb[t] - mx);
        alpha[(size_t)b * T + t] = e;
        sum += e;
    }
    for (int o = 16; o; o >>= 1) sum += __shfl_xor_sync(0xffffffffu, sum, o);
    __syncthreads();
    if ((tid & 31) == 0) red[tid >> 5] = sum;
    __syncthreads();
    if (tid == 0) {
        float v = 0.f;
#pragma unroll
        for (int w = 0; w < 8; w++) v += red[w];
        sh = 1.f / v;
    }
    __syncthreads();
    float inv = sh;
    for (int t = tid; t < T; t += 256) alpha[(size_t)b * T + t] *= inv;
}

__global__ __launch_bounds__(256) void pool_k(const float* __restrict__ key,
                                              const float* __restrict__ alpha,
                                              float* __restrict__ out, int T) {
    const int b = blockIdx.x;
    const int h = blockIdx.y * 256 + threadIdx.x;
    const float* kb = key + (size_t)b * T * 1024 + h;
    const float* ab = alpha + (size_t)b * T;
    float a0 = 0.f, a1 = 0.f, a2 = 0.f, a3 = 0.f;
    for (int t = 0; t < T; t += 4) {
        a0 += ab[t + 0] * kb[(size_t)(t + 0) * 1024];
        a1 += ab[t + 1] * kb[(size_t)(t + 1) * 1024];
        a2 += ab[t + 2] * kb[(size_t)(t + 2) * 1024];
        a3 += ab[t + 3] * kb[(size_t)(t + 3) * 1024];
    }
    out[(size_t)b * 1024 + h] = (a0 + a1) + (a2 + a3);
}

__global__ __launch_bounds__(256) void xw_k(const float* __restrict__ x,
                                            const float* __restrict__ W,
                                            float* __restrict__ out) {
    const int b = blockIdx.y;
    const int j = blockIdx.x * 256 + threadIdx.x;
    __shared__ float xs[1024];
    for (int i = threadIdx.x; i < 1024; i += 256) xs[i] = x[(size_t)b * 1024 + i];
    __syncthreads();
    const float* Wc = W + j;
    float a0 = 0.f, a1 = 0.f, a2 = 0.f, a3 = 0.f;
    for (int h = 0; h < 1024; h += 4) {
        a0 += xs[h + 0] * Wc[(size_t)(h + 0) * 1024];
        a1 += xs[h + 1] * Wc[(size_t)(h + 1) * 1024];
        a2 += xs[h + 2] * Wc[(size_t)(h + 2) * 1024];
        a3 += xs[h + 3] * Wc[(size_t)(h + 3) * 1024];
    }
    out[(size_t)b * 1024 + j] = (a0 + a1) + (a2 + a3);
}

__global__ __launch_bounds__(256) void rowdot_k(const float* __restrict__ x,
                                                const float* __restrict__ W,
                                                const float* __restrict__ bias,
                                                float* __restrict__ out, int N) {
    const int b = blockIdx.y;
    const int w = threadIdx.x >> 5, lane = threadIdx.x & 31;
    const int j = blockIdx.x * 8 + w;
    const float* xr = x + (size_t)b * 1024;
    const float* wr = W + (size_t)j * 1024;
    float a0 = 0.f, a1 = 0.f;
    for (int h = lane; h < 1024; h += 64) {
        a0 += xr[h] * wr[h];
        a1 += xr[h + 32] * wr[h + 32];
    }
    float acc = a0 + a1;
    for (int o = 16; o; o >>= 1) acc += __shfl_xor_sync(0xffffffffu, acc, o);
    if (!lane) out[(size_t)b * N + j] = acc + bias[j];
}

__global__ __launch_bounds__(256) void gru_k() {
    const int i = blockIdx.x * 256 + threadIdx.x;
    const int b = i >> 10, h = i & 1023;
    const float* gi = g_gi + (size_t)b * 3072;
    const float* gh = g_gh + (size_t)b * 3072;
    float r = 1.f / (1.f + expf(-(gi[h] + gh[h])));
    float z = 1.f / (1.f + expf(-(gi[1024 + h] + gh[1024 + h])));
    float n = tanhf(gi[2048 + h] + r * gh[2048 + h]);
    g_gout[i] = (1.f - z) * n + z * g_hidden[i];
}

// ---------------- launch ------------------------------------------------------
extern "C" void kernel_launch(void* const* d_in, const int* in_sizes, int n_in,
                              void* d_out, int out_size) {
    const float* question = (const float*)d_in[0];
    const float* qmask    = (const float*)d_in[1];
    const float* passage  = (const float*)d_in[2];
    const float* pmask    = (const float*)d_in[3];
    const float* Vq       = (const float*)d_in[4];
    const float* Wk_q     = (const float*)d_in[5];
    const float* Wq_q     = (const float*)d_in[6];
    const float* w_q      = (const float*)d_in[7];
    const float* Wk_p     = (const float*)d_in[8];
    const float* Wq_p     = (const float*)d_in[9];
    const float* w_p      = (const float*)d_in[10];
    const float* W_ih     = (const float*)d_in[11];
    const float* W_hh     = (const float*)d_in[12];
    const float* b_ih     = (const float*)d_in[13];
    const float* b_hh     = (const float*)d_in[14];
    float* out = (float*)d_out;

    float *pPK, *psq, *palpha, *phid, *pinp, *pgout, *pQ1, *pQ2, *pcq, *pgi, *pgh;
    __half *pAh, *pAl, *pQh, *pQl, *pBqh, *pBph;
    cudaGetSymbolAddress((void**)&pPK,   g_PK);
    cudaGetSymbolAddress((void**)&psq,   g_sq);
    cudaGetSymbolAddress((void**)&palpha,g_alpha);
    cudaGetSymbolAddress((void**)&phid,  g_hidden);
    cudaGetSymbolAddress((void**)&pinp,  g_inputs);
    cudaGetSymbolAddress((void**)&pgout, g_gout);
    cudaGetSymbolAddress((void**)&pQ1,   g_Q1);
    cudaGetSymbolAddress((void**)&pQ2,   g_Q2);
    cudaGetSymbolAddress((void**)&pcq,   g_cq);
    cudaGetSymbolAddress((void**)&pgi,   g_gi);
    cudaGetSymbolAddress((void**)&pgh,   g_gh);
    cudaGetSymbolAddress((void**)&pAh,   g_Ah);
    cudaGetSymbolAddress((void**)&pAl,   g_Al);
    cudaGetSymbolAddress((void**)&pQh,   g_Qh);
    cudaGetSymbolAddress((void**)&pQl,   g_Ql);
    cudaGetSymbolAddress((void**)&pBqh,  g_Bqh);
    cudaGetSymbolAddress((void**)&pBph,  g_Bph);

    cudaFuncSetAttribute(mma2_k, cudaFuncAttributeMaxDynamicSharedMemorySize, 3 * STG + 1024);

    // conversions (Wk_* already [k][n]; no transpose needed)
    cvtB_k<<<1024, 256>>>(Wk_q, pBqh);
    cvtB_k<<<1024, 256>>>(Wk_p, pBph);
    splitA_k<<<4096, 256>>>(question, pQh, pQl);
    splitA_k<<<65536, 256>>>(passage, pAh, pAl);

    // question branch
    xw_k<<<dim3(4, 1), 256>>>(Vq, Wq_q, pcq);
    mma2_k<<<dim3(8, 32), 256, 3 * STG + 1024>>>(pQh, pQl, pBqh, pPK);
    score_k<<<4096, 256>>>(pPK, pcq, w_q, qmask, psq, 0);
    softmax_k<<<64, 256>>>(psq, palpha, 64);
    pool_k<<<dim3(64, 4), 256>>>(question, palpha, phid, 64);
    xw_k<<<dim3(4, 64), 256>>>(phid, Wq_p, pQ1);

    // passage branch (dominant GEMM, computed once)
    mma2_k<<<dim3(8, 512), 256, 3 * STG + 1024>>>(pAh, pAl, pBph, pPK);
    score_k<<<65536, 256>>>(pPK, pQ1, w_p, pmask, out, 1);
    softmax_k<<<64, 256>>>(out, palpha, 1024);
    pool_k<<<dim3(64, 4), 256>>>(passage, palpha, pinp, 1024);

    // GRU + end logits
    rowdot_k<<<dim3(384, 64), 256>>>(pinp, W_ih, b_ih, pgi, 3072);
    rowdot_k<<<dim3(384, 64), 256>>>(phid, W_hh, b_hh, pgh, 3072);
    gru_k<<<256, 256>>>();
    xw_k<<<dim3(4, 64), 256>>>(pgout, Wq_p, pQ2);
    score_k<<<65536, 256>>>(pPK, pQ2, w_p, pmask, out + 65536, 1);
}

// round 6
// speedup vs baseline: 1.2867x; 1.0817x over previous
#include <cuda_runtime.h>
#include <cuda_fp16.h>
#include <math.h>
#include <stdint.h>

// Shapes (fixed): B=64, TQ=64, TP=1024, H=A=1024
#define NB  64
#define Hn  1024

// ---------------- scratch (__device__ globals) --------------------------------
__device__ float g_PK[67108864];                 // 256MB logits-GEMM output
__device__ __half g_Ah[67108864];                // passage hi (fp16)
__device__ __half g_Al[67108864];                // passage lo (fp16)
__device__ __half g_Qh[4194304];                 // question hi
__device__ __half g_Ql[4194304];                 // question lo
__device__ __half g_Bqh[1048576];                // Wk_q fp16 [k][n]
__device__ __half g_Bph[1048576];                // Wk_p fp16 [k][n]
__device__ float g_sp[65536];                    // fused begin-score partials
__device__ float g_sq[NB * 64];
__device__ float g_alpha[NB * 1024];
__device__ float g_hidden[NB * Hn];
__device__ float g_inputs[NB * Hn];
__device__ float g_gout[NB * Hn];
__device__ float g_Q1[NB * Hn];
__device__ float g_Q2[NB * Hn];
__device__ float g_cq[Hn];
__device__ float g_gi[NB * 3 * Hn];
__device__ float g_gh[NB * 3 * Hn];

// ---------------- helpers -----------------------------------------------------
__device__ __forceinline__ float tanh_apx(float x) {
    float y;
    asm("tanh.approx.f32 %0, %1;" : "=f"(y) : "f"(x));
    return y;
}
__device__ __forceinline__ uint32_t smem_u32(const void* p) {
    uint32_t a;
    asm("{ .reg .u64 t; cvta.to.shared.u64 t, %1; cvt.u32.u64 %0, t; }" : "=r"(a) : "l"(p));
    return a;
}
__device__ __forceinline__ void cpa16(uint32_t s, const void* g) {
    asm volatile("cp.async.cg.shared.global [%0], [%1], 16;" :: "r"(s), "l"(g));
}
__device__ __forceinline__ void ldsm_x4u(uint32_t* r, uint32_t a) {
    asm volatile("ldmatrix.sync.aligned.m8n8.x4.shared.b16 {%0,%1,%2,%3}, [%4];"
                 : "=r"(r[0]), "=r"(r[1]), "=r"(r[2]), "=r"(r[3]) : "r"(a));
}
__device__ __forceinline__ void ldsm_x4t_u(uint32_t* r, uint32_t a) {
    asm volatile("ldmatrix.sync.aligned.m8n8.x4.trans.shared.b16 {%0,%1,%2,%3}, [%4];"
                 : "=r"(r[0]), "=r"(r[1]), "=r"(r[2]), "=r"(r[3]) : "r"(a));
}
__device__ __forceinline__ void mma_f16(float* d, const uint32_t* a, const uint32_t* b) {
    asm volatile(
        "mma.sync.aligned.m16n8k16.row.col.f32.f16.f16.f32 "
        "{%0,%1,%2,%3}, {%4,%5,%6,%7}, {%8,%9}, {%0,%1,%2,%3};"
        : "+f"(d[0]), "+f"(d[1]), "+f"(d[2]), "+f"(d[3])
        : "r"(a[0]), "r"(a[1]), "r"(a[2]), "r"(a[3]), "r"(b[0]), "r"(b[1]));
}

// ---------------- conversions --------------------------------------------------
__global__ __launch_bounds__(256) void splitA_k(const float* __restrict__ src,
                                                __half* __restrict__ hi,
                                                __half* __restrict__ lo) {
    int i = blockIdx.x * 256 + threadIdx.x;
    float4 v = ((const float4*)src)[i];
    __half h0 = __float2half(v.x), h1 = __float2half(v.y);
    __half h2 = __float2half(v.z), h3 = __float2half(v.w);
    __half2* hp = (__half2*)hi;
    __half2* lp = (__half2*)lo;
    hp[2 * i]     = __halves2half2(h0, h1);
    hp[2 * i + 1] = __halves2half2(h2, h3);
    lp[2 * i]     = __halves2half2(__float2half(v.x - __half2float(h0)),
                                   __float2half(v.y - __half2float(h1)));
    lp[2 * i + 1] = __halves2half2(__float2half(v.z - __half2float(h2)),
                                   __float2half(v.w - __half2float(h3)));
}
__global__ __launch_bounds__(256) void cvtB_k(const float* __restrict__ src,
                                              __half* __restrict__ hi) {
    int i = blockIdx.x * 256 + threadIdx.x;
    float4 v = ((const float4*)src)[i];
    __half2* hp = (__half2*)hi;
    hp[2 * i]     = __halves2half2(__float2half(v.x), __float2half(v.y));
    hp[2 * i + 1] = __halves2half2(__float2half(v.z), __float2half(v.w));
}
__global__ __launch_bounds__(256) void zero_k(float* __restrict__ p) {
    p[blockIdx.x * 256 + threadIdx.x] = 0.f;
}
__global__ __launch_bounds__(256) void fixup_k(const float* __restrict__ sp,
                                               const float* __restrict__ mask,
                                               float* __restrict__ out) {
    int i = blockIdx.x * 256 + threadIdx.x;
    out[i] = (mask[i] > 0.f) ? sp[i] : -1e30f;
}

// ---------------- pipelined 2-pass fp16 mma.sync GEMM + fused score -----------
// C[M,1024] = (Ah+Al)[M,1024] @ Bh[1024,1024]; optional fused score partials:
//   SP[r] += sum_{c in CTA cols} wv[c] * tanh(C[r,c] + Qv[r>>10, c])
// CTA 128x128, K-chunk 64, 3-stage cp.async pipeline, 8 warps (2x4), 2 passes.
#define STG 54272
__device__ __forceinline__ void load_chunk(uint32_t st,
                                           const __half* Ah, const __half* Al,
                                           const __half* Bh,
                                           int row0, int col0, int k0, int tid) {
#pragma unroll
    for (int j = 0; j < 4; j++) {          // A: 128 rows x 64 halves (hi+lo)
        int s = tid + j * 256;
        int r = s >> 3, c8 = s & 7;
        uint32_t so = (uint32_t)(r * 144 + c8 * 16);
        size_t go = (size_t)(row0 + r) * 1024 + k0 + c8 * 8;
        cpa16(st + so,         Ah + go);
        cpa16(st + 18432 + so, Al + go);
    }
#pragma unroll
    for (int j = 0; j < 4; j++) {          // B: 64 k-rows x 128 halves
        int s = tid + j * 256;
        int r = s >> 4, c8 = s & 15;
        uint32_t so = (uint32_t)(r * 272 + c8 * 16);
        size_t go = (size_t)(k0 + r) * 1024 + col0 + c8 * 8;
        cpa16(st + 36864 + so, Bh + go);
    }
    asm volatile("cp.async.commit_group;" ::: "memory");
}

__global__ __launch_bounds__(256, 1) void mma2_k(const __half* __restrict__ Ah,
                                                 const __half* __restrict__ Al,
                                                 const __half* __restrict__ Bh,
                                                 float* __restrict__ C,
                                                 const float* __restrict__ wv,
                                                 const float* __restrict__ Qv,
                                                 float* __restrict__ SP,
                                                 int fuse) {
    extern __shared__ char dsm[];
    __shared__ float part[128];
    uint32_t sb  = smem_u32(dsm);
    uint32_t sba = (sb + 1023u) & ~1023u;
    const int tid = threadIdx.x;
    const int warp = tid >> 5, lane = tid & 31;
    const int wm = warp >> 2, wn = warp & 3;
    const int row0 = blockIdx.y * 128, col0 = blockIdx.x * 128;

    if (tid < 128) part[tid] = 0.f;

    float acc[4][4][4];
#pragma unroll
    for (int i = 0; i < 4; i++)
#pragma unroll
        for (int j = 0; j < 4; j++)
#pragma unroll
            for (int v = 0; v < 4; v++) acc[i][j][v] = 0.f;

    load_chunk(sba,       Ah, Al, Bh, row0, col0, 0,  tid);
    load_chunk(sba + STG, Ah, Al, Bh, row0, col0, 64, tid);

    for (int c = 0; c < 16; c++) {
        if (c < 14) asm volatile("cp.async.wait_group 1;" ::: "memory");
        else        asm volatile("cp.async.wait_group 0;" ::: "memory");
        __syncthreads();
        if (c + 2 < 16)
            load_chunk(sba + ((c + 2) % 3) * STG, Ah, Al, Bh, row0, col0, (c + 2) * 64, tid);

        const uint32_t st  = sba + (c % 3) * STG;
        const uint32_t aB  = st;
        const uint32_t alB = st + 18432;
        const uint32_t bB  = st + 36864;
        const int arow = lane & 15, acol = (lane >> 4) << 3;
        const int bkrl = lane & 15, bcb = wn * 32 + ((lane >> 4) << 3);
#pragma unroll
        for (int kk = 0; kk < 64; kk += 16) {
            uint32_t ah[4][4], al[4][4], bh[2][4];
#pragma unroll
            for (int mi = 0; mi < 4; mi++) {
                uint32_t off = (uint32_t)((wm * 64 + mi * 16 + arow) * 144 + (kk + acol) * 2);
                ldsm_x4u(ah[mi], aB + off);
                ldsm_x4u(al[mi], alB + off);
            }
#pragma unroll
            for (int ni = 0; ni < 2; ni++) {
                uint32_t off = (uint32_t)((kk + bkrl) * 272 + (bcb + ni * 16) * 2);
                ldsm_x4t_u(bh[ni], bB + off);
            }
#pragma unroll
            for (int mi = 0; mi < 4; mi++)
#pragma unroll
                for (int nj = 0; nj < 4; nj++) {
                    int ni = nj >> 1, p = (nj & 1) * 2;
                    mma_f16(acc[mi][nj], ah[mi], &bh[ni][p]);   // hi*B
                    mma_f16(acc[mi][nj], al[mi], &bh[ni][p]);   // lo*B
                }
        }
    }

    // ---- epilogue: store fp32 C (+ optional fused score partials) ----
    const int rbase = row0 + wm * 64, cbase = col0 + wn * 32;
    const int lr = lane >> 2, lc = (lane & 3) * 2;
#pragma unroll
    for (int mi = 0; mi < 4; mi++)
#pragma unroll
        for (int nj = 0; nj < 4; nj++) {
            int rr = rbase + mi * 16 + lr;
            int cc = cbase + nj * 8 + lc;
            *(float2*)&C[(size_t)rr * 1024 + cc] =
                make_float2(acc[mi][nj][0], acc[mi][nj][1]);
            *(float2*)&C[(size_t)(rr + 8) * 1024 + cc] =
                make_float2(acc[mi][nj][2], acc[mi][nj][3]);
        }

    if (fuse) {
        const float* q = Qv + ((size_t)(row0 >> 10) << 10);
        __syncthreads();  // part[] zero + all warps in epilogue
#pragma unroll
        for (int mi = 0; mi < 4; mi++) {
            float sA = 0.f, sB = 0.f;
#pragma unroll
            for (int nj = 0; nj < 4; nj++) {
                int cc = cbase + nj * 8 + lc;
                float w0 = wv[cc], w1 = wv[cc + 1];
                float q0 = q[cc],  q1v = q[cc + 1];
                sA += w0 * tanh_apx(acc[mi][nj][0] + q0) + w1 * tanh_apx(acc[mi][nj][1] + q1v);
                sB += w0 * tanh_apx(acc[mi][nj][2] + q0) + w1 * tanh_apx(acc[mi][nj][3] + q1v);
            }
            sA += __shfl_xor_sync(0xffffffffu, sA, 1);
            sA += __shfl_xor_sync(0xffffffffu, sA, 2);
            sB += __shfl_xor_sync(0xffffffffu, sB, 1);
            sB += __shfl_xor_sync(0xffffffffu, sB, 2);
            if ((lane & 3) == 0) {
                atomicAdd(&part[wm * 64 + mi * 16 + lr], sA);
                atomicAdd(&part[wm * 64 + mi * 16 + lr + 8], sB);
            }
        }
        __syncthreads();
        if (tid < 128) atomicAdd(&SP[row0 + tid], part[tid]);
    }
}

// ---------------- score (question + end) --------------------------------------
__global__ __launch_bounds__(256) void score_k(const float* __restrict__ C,
                                               const float* __restrict__ qterm,
                                               const float* __restrict__ wv,
                                               const float* __restrict__ mask,
                                               float* __restrict__ outs, int per_row) {
    const int r = blockIdx.x, tid = threadIdx.x;
    __shared__ float red[8];
    const float* crow = C + (size_t)r * 1024;
    const float* q = per_row ? (qterm + (size_t)(r >> 10) * 1024) : qterm;
    float acc = 0.f;
    for (int c = tid; c < 1024; c += 256)
        acc += wv[c] * tanh_apx(crow[c] + q[c]);
    for (int o = 16; o; o >>= 1) acc += __shfl_xor_sync(0xffffffffu, acc, o);
    if ((tid & 31) == 0) red[tid >> 5] = acc;
    __syncthreads();
    if (tid == 0) {
        float s = 0.f;
#pragma unroll
        for (int w = 0; w < 8; w++) s += red[w];
        outs[r] = (mask[r] > 0.f) ? s : -1e30f;
    }
}

__global__ __launch_bounds__(256) void softmax_k(const float* __restrict__ s,
                                                 float* __restrict__ alpha, int T) {
    const int b = blockIdx.x, tid = threadIdx.x;
    __shared__ float red[8];
    __shared__ float sh;
    const float* sb = s + (size_t)b * T;
    float mx = -3.0e38f;
    for (int t = tid; t < T; t += 256) mx = fmaxf(mx, sb[t]);
    for (int o = 16; o; o >>= 1) mx = fmaxf(mx, __shfl_xor_sync(0xffffffffu, mx, o));
    if ((tid & 31) == 0) red[tid >> 5] = mx;
    __syncthreads();
    if (tid == 0) {
        float v = red[0];
#pragma unroll
        for (int w = 1; w < 8; w++) v = fmaxf(v, red[w]);
        sh = v;
    }
    __syncthreads();
    mx = sh;
    float sum = 0.f;
    for (int t = tid; t < T; t += 256) {
        float e = expf(sb[t] - mx);
        alpha[(size_t)b * T + t] = e;
        sum += e;
    }
    for (int o = 16; o; o >>= 1) sum += __shfl_xor_sync(0xffffffffu, sum, o);
    __syncthreads();
    if ((tid & 31) == 0) red[tid >> 5] = sum;
    __syncthreads();
    if (tid == 0) {
        float v = 0.f;
#pragma unroll
        for (int w = 0; w < 8; w++) v += red[w];
        sh = 1.f / v;
    }
    __syncthreads();
    float inv = sh;
    for (int t = tid; t < T; t += 256) alpha[(size_t)b * T + t] *= inv;
}

__global__ __launch_bounds__(256) void pool_k(const float* __restrict__ key,
                                              const float* __restrict__ alpha,
                                              float* __restrict__ out, int T) {
    const int b = blockIdx.x;
    const int h = blockIdx.y * 256 + threadIdx.x;
    const float* kb = key + (size_t)b * T * 1024 + h;
    const float* ab = alpha + (size_t)b * T;
    float a0 = 0.f, a1 = 0.f, a2 = 0.f, a3 = 0.f;
    for (int t = 0; t < T; t += 4) {
        a0 += ab[t + 0] * kb[(size_t)(t + 0) * 1024];
        a1 += ab[t + 1] * kb[(size_t)(t + 1) * 1024];
        a2 += ab[t + 2] * kb[(size_t)(t + 2) * 1024];
        a3 += ab[t + 3] * kb[(size_t)(t + 3) * 1024];
    }
    out[(size_t)b * 1024 + h] = (a0 + a1) + (a2 + a3);
}

__global__ __launch_bounds__(256) void xw_k(const float* __restrict__ x,
                                            const float* __restrict__ W,
                                            float* __restrict__ out) {
    const int b = blockIdx.y;
    const int j = blockIdx.x * 256 + threadIdx.x;
    __shared__ float xs[1024];
    for (int i = threadIdx.x; i < 1024; i += 256) xs[i] = x[(size_t)b * 1024 + i];
    __syncthreads();
    const float* Wc = W + j;
    float a0 = 0.f, a1 = 0.f, a2 = 0.f, a3 = 0.f;
    for (int h = 0; h < 1024; h += 4) {
        a0 += xs[h + 0] * Wc[(size_t)(h + 0) * 1024];
        a1 += xs[h + 1] * Wc[(size_t)(h + 1) * 1024];
        a2 += xs[h + 2] * Wc[(size_t)(h + 2) * 1024];
        a3 += xs[h + 3] * Wc[(size_t)(h + 3) * 1024];
    }
    out[(size_t)b * 1024 + j] = (a0 + a1) + (a2 + a3);
}

__global__ __launch_bounds__(256) void rowdot_k(const float* __restrict__ x,
                                                const float* __restrict__ W,
                                                const float* __restrict__ bias,
                                                float* __restrict__ out, int N) {
    const int b = blockIdx.y;
    const int w = threadIdx.x >> 5, lane = threadIdx.x & 31;
    const int j = blockIdx.x * 8 + w;
    const float* xr = x + (size_t)b * 1024;
    const float* wr = W + (size_t)j * 1024;
    float a0 = 0.f, a1 = 0.f;
    for (int h = lane; h < 1024; h += 64) {
        a0 += xr[h] * wr[h];
        a1 += xr[h + 32] * wr[h + 32];
    }
    float acc = a0 + a1;
    for (int o = 16; o; o >>= 1) acc += __shfl_xor_sync(0xffffffffu, acc, o);
    if (!lane) out[(size_t)b * N + j] = acc + bias[j];
}

__global__ __launch_bounds__(256) void gru_k() {
    const int i = blockIdx.x * 256 + threadIdx.x;
    const int b = i >> 10, h = i & 1023;
    const float* gi = g_gi + (size_t)b * 3072;
    const float* gh = g_gh + (size_t)b * 3072;
    float r = 1.f / (1.f + expf(-(gi[h] + gh[h])));
    float z = 1.f / (1.f + expf(-(gi[1024 + h] + gh[1024 + h])));
    float n = tanhf(gi[2048 + h] + r * gh[2048 + h]);
    g_gout[i] = (1.f - z) * n + z * g_hidden[i];
}

// ---------------- launch ------------------------------------------------------
extern "C" void kernel_launch(void* const* d_in, const int* in_sizes, int n_in,
                              void* d_out, int out_size) {
    const float* question = (const float*)d_in[0];
    const float* qmask    = (const float*)d_in[1];
    const float* passage  = (const float*)d_in[2];
    const float* pmask    = (const float*)d_in[3];
    const float* Vq       = (const float*)d_in[4];
    const float* Wk_q     = (const float*)d_in[5];
    const float* Wq_q     = (const float*)d_in[6];
    const float* w_q      = (const float*)d_in[7];
    const float* Wk_p     = (const float*)d_in[8];
    const float* Wq_p     = (const float*)d_in[9];
    const float* w_p      = (const float*)d_in[10];
    const float* W_ih     = (const float*)d_in[11];
    const float* W_hh     = (const float*)d_in[12];
    const float* b_ih     = (const float*)d_in[13];
    const float* b_hh     = (const float*)d_in[14];
    float* out = (float*)d_out;

    float *pPK, *psp, *psq, *palpha, *phid, *pinp, *pgout, *pQ1, *pQ2, *pcq, *pgi, *pgh;
    __half *pAh, *pAl, *pQh, *pQl, *pBqh, *pBph;
    cudaGetSymbolAddress((void**)&pPK,   g_PK);
    cudaGetSymbolAddress((void**)&psp,   g_sp);
    cudaGetSymbolAddress((void**)&psq,   g_sq);
    cudaGetSymbolAddress((void**)&palpha,g_alpha);
    cudaGetSymbolAddress((void**)&phid,  g_hidden);
    cudaGetSymbolAddress((void**)&pinp,  g_inputs);
    cudaGetSymbolAddress((void**)&pgout, g_gout);
    cudaGetSymbolAddress((void**)&pQ1,   g_Q1);
    cudaGetSymbolAddress((void**)&pQ2,   g_Q2);
    cudaGetSymbolAddress((void**)&pcq,   g_cq);
    cudaGetSymbolAddress((void**)&pgi,   g_gi);
    cudaGetSymbolAddress((void**)&pgh,   g_gh);
    cudaGetSymbolAddress((void**)&pAh,   g_Ah);
    cudaGetSymbolAddress((void**)&pAl,   g_Al);
    cudaGetSymbolAddress((void**)&pQh,   g_Qh);
    cudaGetSymbolAddress((void**)&pQl,   g_Ql);
    cudaGetSymbolAddress((void**)&pBqh,  g_Bqh);
    cudaGetSymbolAddress((void**)&pBph,  g_Bph);

    cudaFuncSetAttribute(mma2_k, cudaFuncAttributeMaxDynamicSharedMemorySize, 3 * STG + 1024);

    // conversions
    cvtB_k<<<1024, 256>>>(Wk_q, pBqh);
    cvtB_k<<<1024, 256>>>(Wk_p, pBph);
    splitA_k<<<4096, 256>>>(question, pQh, pQl);
    splitA_k<<<65536, 256>>>(passage, pAh, pAl);

    // question branch
    xw_k<<<dim3(4, 1), 256>>>(Vq, Wq_q, pcq);
    mma2_k<<<dim3(8, 32), 256, 3 * STG + 1024>>>(pQh, pQl, pBqh, pPK,
                                                 w_q, pcq, psp, 0);
    score_k<<<4096, 256>>>(pPK, pcq, w_q, qmask, psq, 0);
    softmax_k<<<64, 256>>>(psq, palpha, 64);
    pool_k<<<dim3(64, 4), 256>>>(question, palpha, phid, 64);
    xw_k<<<dim3(4, 64), 256>>>(phid, Wq_p, pQ1);
    rowdot_k<<<dim3(384, 64), 256>>>(phid, W_hh, b_hh, pgh, 3072);  // hoisted (only needs hidden)

    // passage GEMM with fused begin-score (computed once)
    zero_k<<<256, 256>>>(psp);
    mma2_k<<<dim3(8, 512), 256, 3 * STG + 1024>>>(pAh, pAl, pBph, pPK,
                                                  w_p, pQ1, psp, 1);
    fixup_k<<<256, 256>>>(psp, pmask, out);

    // softmax + pool -> GRU input
    softmax_k<<<64, 256>>>(out, palpha, 1024);
    pool_k<<<dim3(64, 4), 256>>>(passage, palpha, pinp, 1024);

    // GRU + end logits
    rowdot_k<<<dim3(384, 64), 256>>>(pinp, W_ih, b_ih, pgi, 3072);
    gru_k<<<256, 256>>>();
    xw_k<<<dim3(4, 64), 256>>>(pgout, Wq_p, pQ2);
    score_k<<<65536, 256>>>(pPK, pQ2, w_p, pmask, out + 65536, 1);
}

// round 7
// speedup vs baseline: 1.6147x; 1.2549x over previous
#include <cuda_runtime.h>
#include <cuda_fp16.h>
#include <math.h>
#include <stdint.h>

// Shapes (fixed): B=64, TQ=64, TP=1024, H=A=1024
#define NB  64
#define Hn  1024

// ---------------- scratch (__device__ globals) --------------------------------
__device__ float g_PK[67108864];                 // 256MB logits-GEMM output
__device__ __half g_Ah[67108864];                // passage fp16
__device__ __half g_Qh[4194304];                 // question fp16
__device__ __half g_Bqh[1048576];                // Wk_q fp16 [k][n]
__device__ __half g_Bph[1048576];                // Wk_p fp16 [k][n]
__device__ float g_sp[65536];                    // fused begin-score partials
__device__ float g_sq[NB * 64];
__device__ float g_alpha[NB * 1024];
__device__ float g_hidden[NB * Hn];
__device__ float g_inputs[NB * Hn];
__device__ float g_gout[NB * Hn];
__device__ float g_Q1[NB * Hn];
__device__ float g_Q2[NB * Hn];
__device__ float g_cq[Hn];
__device__ float g_gi[NB * 3 * Hn];
__device__ float g_gh[NB * 3 * Hn];

// ---------------- helpers -----------------------------------------------------
__device__ __forceinline__ float tanh_apx(float x) {
    float y;
    asm("tanh.approx.f32 %0, %1;" : "=f"(y) : "f"(x));
    return y;
}
__device__ __forceinline__ uint32_t smem_u32(const void* p) {
    uint32_t a;
    asm("{ .reg .u64 t; cvta.to.shared.u64 t, %1; cvt.u32.u64 %0, t; }" : "=r"(a) : "l"(p));
    return a;
}
__device__ __forceinline__ void cpa16(uint32_t s, const void* g) {
    asm volatile("cp.async.cg.shared.global [%0], [%1], 16;" :: "r"(s), "l"(g));
}
__device__ __forceinline__ void ldsm_x4u(uint32_t* r, uint32_t a) {
    asm volatile("ldmatrix.sync.aligned.m8n8.x4.shared.b16 {%0,%1,%2,%3}, [%4];"
                 : "=r"(r[0]), "=r"(r[1]), "=r"(r[2]), "=r"(r[3]) : "r"(a));
}
__device__ __forceinline__ void ldsm_x4t_u(uint32_t* r, uint32_t a) {
    asm volatile("ldmatrix.sync.aligned.m8n8.x4.trans.shared.b16 {%0,%1,%2,%3}, [%4];"
                 : "=r"(r[0]), "=r"(r[1]), "=r"(r[2]), "=r"(r[3]) : "r"(a));
}
__device__ __forceinline__ void mma_f16(float* d, const uint32_t* a, const uint32_t* b) {
    asm volatile(
        "mma.sync.aligned.m16n8k16.row.col.f32.f16.f16.f32 "
        "{%0,%1,%2,%3}, {%4,%5,%6,%7}, {%8,%9}, {%0,%1,%2,%3};"
        : "+f"(d[0]), "+f"(d[1]), "+f"(d[2]), "+f"(d[3])
        : "r"(a[0]), "r"(a[1]), "r"(a[2]), "r"(a[3]), "r"(b[0]), "r"(b[1]));
}

// ---------------- conversions --------------------------------------------------
__global__ __launch_bounds__(256) void cvt_k(const float* __restrict__ src,
                                             __half* __restrict__ dst) {
    int i = blockIdx.x * 256 + threadIdx.x;
    float4 v = ((const float4*)src)[i];
    __half2* hp = (__half2*)dst;
    hp[2 * i]     = __halves2half2(__float2half(v.x), __float2half(v.y));
    hp[2 * i + 1] = __halves2half2(__float2half(v.z), __float2half(v.w));
}
__global__ __launch_bounds__(256) void zero_k(float* __restrict__ p) {
    p[blockIdx.x * 256 + threadIdx.x] = 0.f;
}
__global__ __launch_bounds__(256) void fixup_k(const float* __restrict__ sp,
                                               const float* __restrict__ mask,
                                               float* __restrict__ out) {
    int i = blockIdx.x * 256 + threadIdx.x;
    out[i] = (mask[i] > 0.f) ? sp[i] : -1e30f;
}

// ---------------- pipelined single-pass fp16 mma.sync GEMM + fused score ------
// C[M,1024] = A[M,1024] @ Bh[1024,1024] (both fp16, fp32 accumulate).
// Optional fused partials: SP[r] += sum_{c in CTA cols} wv[c]*tanh(C[r,c]+Qv[..,c])
// CTA 128x128, K-chunk 64, 3-stage cp.async pipeline, 8 warps (2x4).
// Stage: A 128x144B @0 (18432) | B 64x272B @18432 (17408) => 35840 B
#define STG 35840
__device__ __forceinline__ void load_chunk(uint32_t st,
                                           const __half* Ah, const __half* Bh,
                                           int row0, int col0, int k0, int tid) {
#pragma unroll
    for (int j = 0; j < 4; j++) {          // A: 128 rows x 64 halves
        int s = tid + j * 256;
        int r = s >> 3, c8 = s & 7;
        uint32_t so = (uint32_t)(r * 144 + c8 * 16);
        size_t go = (size_t)(row0 + r) * 1024 + k0 + c8 * 8;
        cpa16(st + so, Ah + go);
    }
#pragma unroll
    for (int j = 0; j < 4; j++) {          // B: 64 k-rows x 128 halves
        int s = tid + j * 256;
        int r = s >> 4, c8 = s & 15;
        uint32_t so = (uint32_t)(r * 272 + c8 * 16);
        size_t go = (size_t)(k0 + r) * 1024 + col0 + c8 * 8;
        cpa16(st + 18432 + so, Bh + go);
    }
    asm volatile("cp.async.commit_group;" ::: "memory");
}

__global__ __launch_bounds__(256, 1) void mma2_k(const __half* __restrict__ Ah,
                                                 const __half* __restrict__ Bh,
                                                 float* __restrict__ C,
                                                 const float* __restrict__ wv,
                                                 const float* __restrict__ Qv,
                                                 float* __restrict__ SP,
                                                 int fuse) {
    extern __shared__ char dsm[];
    __shared__ float part[128];
    uint32_t sb  = smem_u32(dsm);
    uint32_t sba = (sb + 1023u) & ~1023u;
    const int tid = threadIdx.x;
    const int warp = tid >> 5, lane = tid & 31;
    const int wm = warp >> 2, wn = warp & 3;
    const int row0 = blockIdx.y * 128, col0 = blockIdx.x * 128;

    if (tid < 128) part[tid] = 0.f;

    float acc[4][4][4];
#pragma unroll
    for (int i = 0; i < 4; i++)
#pragma unroll
        for (int j = 0; j < 4; j++)
#pragma unroll
            for (int v = 0; v < 4; v++) acc[i][j][v] = 0.f;

    load_chunk(sba,       Ah, Bh, row0, col0, 0,  tid);
    load_chunk(sba + STG, Ah, Bh, row0, col0, 64, tid);

    for (int c = 0; c < 16; c++) {
        if (c < 14) asm volatile("cp.async.wait_group 1;" ::: "memory");
        else        asm volatile("cp.async.wait_group 0;" ::: "memory");
        __syncthreads();
        if (c + 2 < 16)
            load_chunk(sba + ((c + 2) % 3) * STG, Ah, Bh, row0, col0, (c + 2) * 64, tid);

        const uint32_t st  = sba + (c % 3) * STG;
        const uint32_t aB  = st;
        const uint32_t bB  = st + 18432;
        const int arow = lane & 15, acol = (lane >> 4) << 3;
        const int bkrl = lane & 15, bcb = wn * 32 + ((lane >> 4) << 3);
#pragma unroll
        for (int kk = 0; kk < 64; kk += 16) {
            uint32_t ah[4][4], bh[2][4];
#pragma unroll
            for (int mi = 0; mi < 4; mi++) {
                uint32_t off = (uint32_t)((wm * 64 + mi * 16 + arow) * 144 + (kk + acol) * 2);
                ldsm_x4u(ah[mi], aB + off);
            }
#pragma unroll
            for (int ni = 0; ni < 2; ni++) {
                uint32_t off = (uint32_t)((kk + bkrl) * 272 + (bcb + ni * 16) * 2);
                ldsm_x4t_u(bh[ni], bB + off);
            }
#pragma unroll
            for (int mi = 0; mi < 4; mi++)
#pragma unroll
                for (int nj = 0; nj < 4; nj++) {
                    int ni = nj >> 1, p = (nj & 1) * 2;
                    mma_f16(acc[mi][nj], ah[mi], &bh[ni][p]);
                }
        }
    }

    // ---- epilogue: store fp32 C (+ optional fused score partials) ----
    const int rbase = row0 + wm * 64, cbase = col0 + wn * 32;
    const int lr = lane >> 2, lc = (lane & 3) * 2;
#pragma unroll
    for (int mi = 0; mi < 4; mi++)
#pragma unroll
        for (int nj = 0; nj < 4; nj++) {
            int rr = rbase + mi * 16 + lr;
            int cc = cbase + nj * 8 + lc;
            *(float2*)&C[(size_t)rr * 1024 + cc] =
                make_float2(acc[mi][nj][0], acc[mi][nj][1]);
            *(float2*)&C[(size_t)(rr + 8) * 1024 + cc] =
                make_float2(acc[mi][nj][2], acc[mi][nj][3]);
        }

    if (fuse) {
        const float* q = Qv + ((size_t)(row0 >> 10) << 10);
        __syncthreads();  // part[] zero + all warps in epilogue
#pragma unroll
        for (int mi = 0; mi < 4; mi++) {
            float sA = 0.f, sB = 0.f;
#pragma unroll
            for (int nj = 0; nj < 4; nj++) {
                int cc = cbase + nj * 8 + lc;
                float w0 = wv[cc], w1 = wv[cc + 1];
                float q0 = q[cc],  q1v = q[cc + 1];
                sA += w0 * tanh_apx(acc[mi][nj][0] + q0) + w1 * tanh_apx(acc[mi][nj][1] + q1v);
                sB += w0 * tanh_apx(acc[mi][nj][2] + q0) + w1 * tanh_apx(acc[mi][nj][3] + q1v);
            }
            sA += __shfl_xor_sync(0xffffffffu, sA, 1);
            sA += __shfl_xor_sync(0xffffffffu, sA, 2);
            sB += __shfl_xor_sync(0xffffffffu, sB, 1);
            sB += __shfl_xor_sync(0xffffffffu, sB, 2);
            if ((lane & 3) == 0) {
                atomicAdd(&part[wm * 64 + mi * 16 + lr], sA);
                atomicAdd(&part[wm * 64 + mi * 16 + lr + 8], sB);
            }
        }
        __syncthreads();
        if (tid < 128) atomicAdd(&SP[row0 + tid], part[tid]);
    }
}

// ---------------- score (question + end) --------------------------------------
__global__ __launch_bounds__(256) void score_k(const float* __restrict__ C,
                                               const float* __restrict__ qterm,
                                               const float* __restrict__ wv,
                                               const float* __restrict__ mask,
                                               float* __restrict__ outs, int per_row) {
    const int r = blockIdx.x, tid = threadIdx.x;
    __shared__ float red[8];
    const float* crow = C + (size_t)r * 1024;
    const float* q = per_row ? (qterm + (size_t)(r >> 10) * 1024) : qterm;
    float acc = 0.f;
    for (int c = tid; c < 1024; c += 256)
        acc += wv[c] * tanh_apx(crow[c] + q[c]);
    for (int o = 16; o; o >>= 1) acc += __shfl_xor_sync(0xffffffffu, acc, o);
    if ((tid & 31) == 0) red[tid >> 5] = acc;
    __syncthreads();
    if (tid == 0) {
        float s = 0.f;
#pragma unroll
        for (int w = 0; w < 8; w++) s += red[w];
        outs[r] = (mask[r] > 0.f) ? s : -1e30f;
    }
}

__global__ __launch_bounds__(256) void softmax_k(const float* __restrict__ s,
                                                 float* __restrict__ alpha, int T) {
    const int b = blockIdx.x, tid = threadIdx.x;
    __shared__ float red[8];
    __shared__ float sh;
    const float* sb = s + (size_t)b * T;
    float mx = -3.0e38f;
    for (int t = tid; t < T; t += 256) mx = fmaxf(mx, sb[t]);
    for (int o = 16; o; o >>= 1) mx = fmaxf(mx, __shfl_xor_sync(0xffffffffu, mx, o));
    if ((tid & 31) == 0) red[tid >> 5] = mx;
    __syncthreads();
    if (tid == 0) {
        float v = red[0];
#pragma unroll
        for (int w = 1; w < 8; w++) v = fmaxf(v, red[w]);
        sh = v;
    }
    __syncthreads();
    mx = sh;
    float sum = 0.f;
    for (int t = tid; t < T; t += 256) {
        float e = expf(sb[t] - mx);
        alpha[(size_t)b * T + t] = e;
        sum += e;
    }
    for (int o = 16; o; o >>= 1) sum += __shfl_xor_sync(0xffffffffu, sum, o);
    __syncthreads();
    if ((tid & 31) == 0) red[tid >> 5] = sum;
    __syncthreads();
    if (tid == 0) {
        float v = 0.f;
#pragma unroll
        for (int w = 0; w < 8; w++) v += red[w];
        sh = 1.f / v;
    }
    __syncthreads();
    float inv = sh;
    for (int t = tid; t < T; t += 256) alpha[(size_t)b * T + t] *= inv;
}

__global__ __launch_bounds__(256) void pool_k(const float* __restrict__ key,
                                              const float* __restrict__ alpha,
                                              float* __restrict__ out, int T) {
    const int b = blockIdx.x;
    const int h = blockIdx.y * 256 + threadIdx.x;
    const float* kb = key + (size_t)b * T * 1024 + h;
    const float* ab = alpha + (size_t)b * T;
    float a0 = 0.f, a1 = 0.f, a2 = 0.f, a3 = 0.f;
    for (int t = 0; t < T; t += 4) {
        a0 += ab[t + 0] * kb[(size_t)(t + 0) * 1024];
        a1 += ab[t + 1] * kb[(size_t)(t + 1) * 1024];
        a2 += ab[t + 2] * kb[(size_t)(t + 2) * 1024];
        a3 += ab[t + 3] * kb[(size_t)(t + 3) * 1024];
    }
    out[(size_t)b * 1024 + h] = (a0 + a1) + (a2 + a3);
}

__global__ __launch_bounds__(256) void xw_k(const float* __restrict__ x,
                                            const float* __restrict__ W,
                                            float* __restrict__ out) {
    const int b = blockIdx.y;
    const int j = blockIdx.x * 256 + threadIdx.x;
    __shared__ float xs[1024];
    for (int i = threadIdx.x; i < 1024; i += 256) xs[i] = x[(size_t)b * 1024 + i];
    __syncthreads();
    const float* Wc = W + j;
    float a0 = 0.f, a1 = 0.f, a2 = 0.f, a3 = 0.f;
    for (int h = 0; h < 1024; h += 4) {
        a0 += xs[h + 0] * Wc[(size_t)(h + 0) * 1024];
        a1 += xs[h + 1] * Wc[(size_t)(h + 1) * 1024];
        a2 += xs[h + 2] * Wc[(size_t)(h + 2) * 1024];
        a3 += xs[h + 3] * Wc[(size_t)(h + 3) * 1024];
    }
    out[(size_t)b * 1024 + j] = (a0 + a1) + (a2 + a3);
}

__global__ __launch_bounds__(256) void rowdot_k(const float* __restrict__ x,
                                                const float* __restrict__ W,
                                                const float* __restrict__ bias,
                                                float* __restrict__ out, int N) {
    const int b = blockIdx.y;
    const int w = threadIdx.x >> 5, lane = threadIdx.x & 31;
    const int j = blockIdx.x * 8 + w;
    const float* xr = x + (size_t)b * 1024;
    const float* wr = W + (size_t)j * 1024;
    float a0 = 0.f, a1 = 0.f;
    for (int h = lane; h < 1024; h += 64) {
        a0 += xr[h] * wr[h];
        a1 += xr[h + 32] * wr[h + 32];
    }
    float acc = a0 + a1;
    for (int o = 16; o; o >>= 1) acc += __shfl_xor_sync(0xffffffffu, acc, o);
    if (!lane) out[(size_t)b * N + j] = acc + bias[j];
}

__global__ __launch_bounds__(256) void gru_k() {
    const int i = blockIdx.x * 256 + threadIdx.x;
    const int b = i >> 10, h = i & 1023;
    const float* gi = g_gi + (size_t)b * 3072;
    const float* gh = g_gh + (size_t)b * 3072;
    float r = 1.f / (1.f + expf(-(gi[h] + gh[h])));
    float z = 1.f / (1.f + expf(-(gi[1024 + h] + gh[1024 + h])));
    float n = tanhf(gi[2048 + h] + r * gh[2048 + h]);
    g_gout[i] = (1.f - z) * n + z * g_hidden[i];
}

// ---------------- launch ------------------------------------------------------
extern "C" void kernel_launch(void* const* d_in, const int* in_sizes, int n_in,
                              void* d_out, int out_size) {
    const float* question = (const float*)d_in[0];
    const float* qmask    = (const float*)d_in[1];
    const float* passage  = (const float*)d_in[2];
    const float* pmask    = (const float*)d_in[3];
    const float* Vq       = (const float*)d_in[4];
    const float* Wk_q     = (const float*)d_in[5];
    const float* Wq_q     = (const float*)d_in[6];
    const float* w_q      = (const float*)d_in[7];
    const float* Wk_p     = (const float*)d_in[8];
    const float* Wq_p     = (const float*)d_in[9];
    const float* w_p      = (const float*)d_in[10];
    const float* W_ih     = (const float*)d_in[11];
    const float* W_hh     = (const float*)d_in[12];
    const float* b_ih     = (const float*)d_in[13];
    const float* b_hh     = (const float*)d_in[14];
    float* out = (float*)d_out;

    float *pPK, *psp, *psq, *palpha, *phid, *pinp, *pgout, *pQ1, *pQ2, *pcq, *pgi, *pgh;
    __half *pAh, *pQh, *pBqh, *pBph;
    cudaGetSymbolAddress((void**)&pPK,   g_PK);
    cudaGetSymbolAddress((void**)&psp,   g_sp);
    cudaGetSymbolAddress((void**)&psq,   g_sq);
    cudaGetSymbolAddress((void**)&palpha,g_alpha);
    cudaGetSymbolAddress((void**)&phid,  g_hidden);
    cudaGetSymbolAddress((void**)&pinp,  g_inputs);
    cudaGetSymbolAddress((void**)&pgout, g_gout);
    cudaGetSymbolAddress((void**)&pQ1,   g_Q1);
    cudaGetSymbolAddress((void**)&pQ2,   g_Q2);
    cudaGetSymbolAddress((void**)&pcq,   g_cq);
    cudaGetSymbolAddress((void**)&pgi,   g_gi);
    cudaGetSymbolAddress((void**)&pgh,   g_gh);
    cudaGetSymbolAddress((void**)&pAh,   g_Ah);
    cudaGetSymbolAddress((void**)&pQh,   g_Qh);
    cudaGetSymbolAddress((void**)&pBqh,  g_Bqh);
    cudaGetSymbolAddress((void**)&pBph,  g_Bph);

    cudaFuncSetAttribute(mma2_k, cudaFuncAttributeMaxDynamicSharedMemorySize, 3 * STG + 1024);

    // conversions (all plain fp32 -> fp16)
    cvt_k<<<1024, 256>>>(Wk_q, pBqh);
    cvt_k<<<1024, 256>>>(Wk_p, pBph);
    cvt_k<<<4096, 256>>>(question, pQh);
    cvt_k<<<65536, 256>>>(passage, pAh);

    // question branch
    xw_k<<<dim3(4, 1), 256>>>(Vq, Wq_q, pcq);
    mma2_k<<<dim3(8, 32), 256, 3 * STG + 1024>>>(pQh, pBqh, pPK, w_q, pcq, psp, 0);
    score_k<<<4096, 256>>>(pPK, pcq, w_q, qmask, psq, 0);
    softmax_k<<<64, 256>>>(psq, palpha, 64);
    pool_k<<<dim3(64, 4), 256>>>(question, palpha, phid, 64);
    xw_k<<<dim3(4, 64), 256>>>(phid, Wq_p, pQ1);
    rowdot_k<<<dim3(384, 64), 256>>>(phid, W_hh, b_hh, pgh, 3072);  // only needs hidden

    // passage GEMM with fused begin-score (computed once)
    zero_k<<<256, 256>>>(psp);
    mma2_k<<<dim3(8, 512), 256, 3 * STG + 1024>>>(pAh, pBph, pPK, w_p, pQ1, psp, 1);
    fixup_k<<<256, 256>>>(psp, pmask, out);

    // softmax + pool -> GRU input
    softmax_k<<<64, 256>>>(out, palpha, 1024);
    pool_k<<<dim3(64, 4), 256>>>(passage, palpha, pinp, 1024);

    // GRU + end logits
    rowdot_k<<<dim3(384, 64), 256>>>(pinp, W_ih, b_ih, pgi, 3072);
    gru_k<<<256, 256>>>();
    xw_k<<<dim3(4, 64), 256>>>(pgout, Wq_p, pQ2);
    score_k<<<65536, 256>>>(pPK, pQ2, w_p, pmask, out + 65536, 1);
}

// round 8
// speedup vs baseline: 1.8708x; 1.1586x over previous
#include <cuda_runtime.h>
#include <cuda_fp16.h>
#include <math.h>
#include <stdint.h>

// Shapes (fixed): B=64, TQ=64, TP=1024, H=A=1024
#define NB  64
#define Hn  1024

// ---------------- scratch (__device__ globals) --------------------------------
__device__ float g_PK[67108864];                 // 256MB logits-GEMM output
__device__ __half g_Ah[67108864];                // passage fp16
__device__ __half g_Qh[4194304];                 // question fp16
__device__ __half g_Bqh[1048576];                // Wk_q fp16 [k][n]
__device__ __half g_Bph[1048576];                // Wk_p fp16 [k][n]
__device__ float g_sp[65536];                    // fused begin-score partials
__device__ float g_sq[NB * 64];
__device__ float g_alpha[NB * 1024];
__device__ float g_hidden[NB * Hn];
__device__ float g_inputs[NB * Hn];
__device__ float g_gout[NB * Hn];
__device__ float g_Q1[NB * Hn];
__device__ float g_Q2[NB * Hn];
__device__ float g_cq[Hn];
__device__ float g_gi[NB * 3 * Hn];
__device__ float g_gh[NB * 3 * Hn];

// ---------------- helpers -----------------------------------------------------
__device__ __forceinline__ float tanh_apx(float x) {
    float y;
    asm("tanh.approx.f32 %0, %1;" : "=f"(y) : "f"(x));
    return y;
}
__device__ __forceinline__ uint32_t smem_u32(const void* p) {
    uint32_t a;
    asm("{ .reg .u64 t; cvta.to.shared.u64 t, %1; cvt.u32.u64 %0, t; }" : "=r"(a) : "l"(p));
    return a;
}
__device__ __forceinline__ void cpa16(uint32_t s, const void* g) {
    asm volatile("cp.async.cg.shared.global [%0], [%1], 16;" :: "r"(s), "l"(g));
}
__device__ __forceinline__ void ldsm_x4u(uint32_t* r, uint32_t a) {
    asm volatile("ldmatrix.sync.aligned.m8n8.x4.shared.b16 {%0,%1,%2,%3}, [%4];"
                 : "=r"(r[0]), "=r"(r[1]), "=r"(r[2]), "=r"(r[3]) : "r"(a));
}
__device__ __forceinline__ void ldsm_x4t_u(uint32_t* r, uint32_t a) {
    asm volatile("ldmatrix.sync.aligned.m8n8.x4.trans.shared.b16 {%0,%1,%2,%3}, [%4];"
                 : "=r"(r[0]), "=r"(r[1]), "=r"(r[2]), "=r"(r[3]) : "r"(a));
}
__device__ __forceinline__ void mma_f16(float* d, const uint32_t* a, const uint32_t* b) {
    asm volatile(
        "mma.sync.aligned.m16n8k16.row.col.f32.f16.f16.f32 "
        "{%0,%1,%2,%3}, {%4,%5,%6,%7}, {%8,%9}, {%0,%1,%2,%3};"
        : "+f"(d[0]), "+f"(d[1]), "+f"(d[2]), "+f"(d[3])
        : "r"(a[0]), "r"(a[1]), "r"(a[2]), "r"(a[3]), "r"(b[0]), "r"(b[1]));
}

// ---------------- conversions --------------------------------------------------
__global__ __launch_bounds__(256) void cvt_k(const float* __restrict__ src,
                                             __half* __restrict__ dst) {
    int i = blockIdx.x * 256 + threadIdx.x;
    float4 v = ((const float4*)src)[i];
    __half2* hp = (__half2*)dst;
    hp[2 * i]     = __halves2half2(__float2half(v.x), __float2half(v.y));
    hp[2 * i + 1] = __halves2half2(__float2half(v.z), __float2half(v.w));
}
__global__ __launch_bounds__(256) void zero_k(float* __restrict__ p) {
    p[blockIdx.x * 256 + threadIdx.x] = 0.f;
}
__global__ __launch_bounds__(256) void fixup_k(const float* __restrict__ sp,
                                               const float* __restrict__ mask,
                                               float* __restrict__ out) {
    int i = blockIdx.x * 256 + threadIdx.x;
    out[i] = (mask[i] > 0.f) ? sp[i] : -1e30f;
}

// ---------------- double-buffered single-pass fp16 GEMM + fused score ---------
// C[M,1024] = A[M,1024] @ Bh[1024,1024] (fp16 in, fp32 accumulate).
// Optional fused partials: SP[r] += sum_{c in CTA cols} wv[c]*tanh(C[r,c]+Qv[..,c])
// CTA 128x128, K-chunk 64, 2-stage cp.async, 8 warps (2x4), 2 CTAs/SM.
// Stage: A 128x144B @0 (18432) | B 64x272B @18432 (17408) => 35840 B
#define STG 35840
__device__ __forceinline__ void load_chunk(uint32_t st,
                                           const __half* Ah, const __half* Bh,
                                           int row0, int col0, int k0, int tid) {
#pragma unroll
    for (int j = 0; j < 4; j++) {          // A: 128 rows x 64 halves
        int s = tid + j * 256;
        int r = s >> 3, c8 = s & 7;
        uint32_t so = (uint32_t)(r * 144 + c8 * 16);
        size_t go = (size_t)(row0 + r) * 1024 + k0 + c8 * 8;
        cpa16(st + so, Ah + go);
    }
#pragma unroll
    for (int j = 0; j < 4; j++) {          // B: 64 k-rows x 128 halves
        int s = tid + j * 256;
        int r = s >> 4, c8 = s & 15;
        uint32_t so = (uint32_t)(r * 272 + c8 * 16);
        size_t go = (size_t)(k0 + r) * 1024 + col0 + c8 * 8;
        cpa16(st + 18432 + so, Bh + go);
    }
    asm volatile("cp.async.commit_group;" ::: "memory");
}

__global__ __launch_bounds__(256, 2) void mma2_k(const __half* __restrict__ Ah,
                                                 const __half* __restrict__ Bh,
                                                 float* __restrict__ C,
                                                 const float* __restrict__ wv,
                                                 const float* __restrict__ Qv,
                                                 float* __restrict__ SP,
                                                 int fuse) {
    extern __shared__ char dsm[];
    __shared__ float part[128];
    uint32_t sb  = smem_u32(dsm);
    uint32_t sba = (sb + 1023u) & ~1023u;
    const int tid = threadIdx.x;
    const int warp = tid >> 5, lane = tid & 31;
    const int wm = warp >> 2, wn = warp & 3;
    const int row0 = blockIdx.y * 128, col0 = blockIdx.x * 128;

    if (tid < 128) part[tid] = 0.f;

    float acc[4][4][4];
#pragma unroll
    for (int i = 0; i < 4; i++)
#pragma unroll
        for (int j = 0; j < 4; j++)
#pragma unroll
            for (int v = 0; v < 4; v++) acc[i][j][v] = 0.f;

    load_chunk(sba, Ah, Bh, row0, col0, 0, tid);

    for (int c = 0; c < 16; c++) {
        if (c + 1 < 16)
            load_chunk(sba + ((c + 1) & 1) * STG, Ah, Bh, row0, col0, (c + 1) * 64, tid);
        if (c + 1 < 16) asm volatile("cp.async.wait_group 1;" ::: "memory");
        else            asm volatile("cp.async.wait_group 0;" ::: "memory");
        __syncthreads();

        const uint32_t st  = sba + (c & 1) * STG;
        const uint32_t aB  = st;
        const uint32_t bB  = st + 18432;
        const int arow = lane & 15, acol = (lane >> 4) << 3;
        const int bkrl = lane & 15, bcb = wn * 32 + ((lane >> 4) << 3);
#pragma unroll
        for (int kk = 0; kk < 64; kk += 16) {
            uint32_t ah[4][4], bh[2][4];
#pragma unroll
            for (int mi = 0; mi < 4; mi++) {
                uint32_t off = (uint32_t)((wm * 64 + mi * 16 + arow) * 144 + (kk + acol) * 2);
                ldsm_x4u(ah[mi], aB + off);
            }
#pragma unroll
            for (int ni = 0; ni < 2; ni++) {
                uint32_t off = (uint32_t)((kk + bkrl) * 272 + (bcb + ni * 16) * 2);
                ldsm_x4t_u(bh[ni], bB + off);
            }
#pragma unroll
            for (int mi = 0; mi < 4; mi++)
#pragma unroll
                for (int nj = 0; nj < 4; nj++) {
                    int ni = nj >> 1, p = (nj & 1) * 2;
                    mma_f16(acc[mi][nj], ah[mi], &bh[ni][p]);
                }
        }
        if (c + 1 < 16) __syncthreads();   // buffer (c&1) reused by load(c+2)
    }

    // ---- epilogue: store fp32 C (+ optional fused score partials) ----
    const int rbase = row0 + wm * 64, cbase = col0 + wn * 32;
    const int lr = lane >> 2, lc = (lane & 3) * 2;
#pragma unroll
    for (int mi = 0; mi < 4; mi++)
#pragma unroll
        for (int nj = 0; nj < 4; nj++) {
            int rr = rbase + mi * 16 + lr;
            int cc = cbase + nj * 8 + lc;
            *(float2*)&C[(size_t)rr * 1024 + cc] =
                make_float2(acc[mi][nj][0], acc[mi][nj][1]);
            *(float2*)&C[(size_t)(rr + 8) * 1024 + cc] =
                make_float2(acc[mi][nj][2], acc[mi][nj][3]);
        }

    if (fuse) {
        const float* q = Qv + ((size_t)(row0 >> 10) << 10);
        __syncthreads();
#pragma unroll
        for (int mi = 0; mi < 4; mi++) {
            float sA = 0.f, sB = 0.f;
#pragma unroll
            for (int nj = 0; nj < 4; nj++) {
                int cc = cbase + nj * 8 + lc;
                float w0 = wv[cc], w1 = wv[cc + 1];
                float q0 = q[cc],  q1v = q[cc + 1];
                sA += w0 * tanh_apx(acc[mi][nj][0] + q0) + w1 * tanh_apx(acc[mi][nj][1] + q1v);
                sB += w0 * tanh_apx(acc[mi][nj][2] + q0) + w1 * tanh_apx(acc[mi][nj][3] + q1v);
            }
            sA += __shfl_xor_sync(0xffffffffu, sA, 1);
            sA += __shfl_xor_sync(0xffffffffu, sA, 2);
            sB += __shfl_xor_sync(0xffffffffu, sB, 1);
            sB += __shfl_xor_sync(0xffffffffu, sB, 2);
            if ((lane & 3) == 0) {
                atomicAdd(&part[wm * 64 + mi * 16 + lr], sA);
                atomicAdd(&part[wm * 64 + mi * 16 + lr + 8], sB);
            }
        }
        __syncthreads();
        if (tid < 128) atomicAdd(&SP[row0 + tid], part[tid]);
    }
}

// ---------------- score (question + end) --------------------------------------
__global__ __launch_bounds__(256) void score_k(const float* __restrict__ C,
                                               const float* __restrict__ qterm,
                                               const float* __restrict__ wv,
                                               const float* __restrict__ mask,
                                               float* __restrict__ outs, int per_row) {
    const int r = blockIdx.x, tid = threadIdx.x;
    __shared__ float red[8];
    const float* crow = C + (size_t)r * 1024;
    const float* q = per_row ? (qterm + (size_t)(r >> 10) * 1024) : qterm;
    float acc = 0.f;
    for (int c = tid; c < 1024; c += 256)
        acc += wv[c] * tanh_apx(crow[c] + q[c]);
    for (int o = 16; o; o >>= 1) acc += __shfl_xor_sync(0xffffffffu, acc, o);
    if ((tid & 31) == 0) red[tid >> 5] = acc;
    __syncthreads();
    if (tid == 0) {
        float s = 0.f;
#pragma unroll
        for (int w = 0; w < 8; w++) s += red[w];
        outs[r] = (mask[r] > 0.f) ? s : -1e30f;
    }
}

__global__ __launch_bounds__(256) void softmax_k(const float* __restrict__ s,
                                                 float* __restrict__ alpha, int T) {
    const int b = blockIdx.x, tid = threadIdx.x;
    __shared__ float red[8];
    __shared__ float sh;
    const float* sb = s + (size_t)b * T;
    float mx = -3.0e38f;
    for (int t = tid; t < T; t += 256) mx = fmaxf(mx, sb[t]);
    for (int o = 16; o; o >>= 1) mx = fmaxf(mx, __shfl_xor_sync(0xffffffffu, mx, o));
    if ((tid & 31) == 0) red[tid >> 5] = mx;
    __syncthreads();
    if (tid == 0) {
        float v = red[0];
#pragma unroll
        for (int w = 1; w < 8; w++) v = fmaxf(v, red[w]);
        sh = v;
    }
    __syncthreads();
    mx = sh;
    float sum = 0.f;
    for (int t = tid; t < T; t += 256) {
        float e = expf(sb[t] - mx);
        alpha[(size_t)b * T + t] = e;
        sum += e;
    }
    for (int o = 16; o; o >>= 1) sum += __shfl_xor_sync(0xffffffffu, sum, o);
    __syncthreads();
    if ((tid & 31) == 0) red[tid >> 5] = sum;
    __syncthreads();
    if (tid == 0) {
        float v = 0.f;
#pragma unroll
        for (int w = 0; w < 8; w++) v += red[w];
        sh = 1.f / v;
    }
    __syncthreads();
    float inv = sh;
    for (int t = tid; t < T; t += 256) alpha[(size_t)b * T + t] *= inv;
}

__global__ __launch_bounds__(256) void pool_k(const float* __restrict__ key,
                                              const float* __restrict__ alpha,
                                              float* __restrict__ out, int T) {
    const int b = blockIdx.x;
    const int h = blockIdx.y * 256 + threadIdx.x;
    const float* kb = key + (size_t)b * T * 1024 + h;
    const float* ab = alpha + (size_t)b * T;
    float a0 = 0.f, a1 = 0.f, a2 = 0.f, a3 = 0.f;
    for (int t = 0; t < T; t += 4) {
        a0 += ab[t + 0] * kb[(size_t)(t + 0) * 1024];
        a1 += ab[t + 1] * kb[(size_t)(t + 1) * 1024];
        a2 += ab[t + 2] * kb[(size_t)(t + 2) * 1024];
        a3 += ab[t + 3] * kb[(size_t)(t + 3) * 1024];
    }
    out[(size_t)b * 1024 + h] = (a0 + a1) + (a2 + a3);
}

__global__ __launch_bounds__(256) void xw_k(const float* __restrict__ x,
                                            const float* __restrict__ W,
                                            float* __restrict__ out) {
    const int b = blockIdx.y;
    const int j = blockIdx.x * 256 + threadIdx.x;
    __shared__ float xs[1024];
    for (int i = threadIdx.x; i < 1024; i += 256) xs[i] = x[(size_t)b * 1024 + i];
    __syncthreads();
    const float* Wc = W + j;
    float a0 = 0.f, a1 = 0.f, a2 = 0.f, a3 = 0.f;
    for (int h = 0; h < 1024; h += 4) {
        a0 += xs[h + 0] * Wc[(size_t)(h + 0) * 1024];
        a1 += xs[h + 1] * Wc[(size_t)(h + 1) * 1024];
        a2 += xs[h + 2] * Wc[(size_t)(h + 2) * 1024];
        a3 += xs[h + 3] * Wc[(size_t)(h + 3) * 1024];
    }
    out[(size_t)b * 1024 + j] = (a0 + a1) + (a2 + a3);
}

__global__ __launch_bounds__(256) void rowdot_k(const float* __restrict__ x,
                                                const float* __restrict__ W,
                                                const float* __restrict__ bias,
                                                float* __restrict__ out, int N) {
    const int b = blockIdx.y;
    const int w = threadIdx.x >> 5, lane = threadIdx.x & 31;
    const int j = blockIdx.x * 8 + w;
    const float* xr = x + (size_t)b * 1024;
    const float* wr = W + (size_t)j * 1024;
    float a0 = 0.f, a1 = 0.f;
    for (int h = lane; h < 1024; h += 64) {
        a0 += xr[h] * wr[h];
        a1 += xr[h + 32] * wr[h + 32];
    }
    float acc = a0 + a1;
    for (int o = 16; o; o >>= 1) acc += __shfl_xor_sync(0xffffffffu, acc, o);
    if (!lane) out[(size_t)b * N + j] = acc + bias[j];
}

__global__ __launch_bounds__(256) void gru_k() {
    const int i = blockIdx.x * 256 + threadIdx.x;
    const int b = i >> 10, h = i & 1023;
    const float* gi = g_gi + (size_t)b * 3072;
    const float* gh = g_gh + (size_t)b * 3072;
    float r = 1.f / (1.f + expf(-(gi[h] + gh[h])));
    float z = 1.f / (1.f + expf(-(gi[1024 + h] + gh[1024 + h])));
    float n = tanhf(gi[2048 + h] + r * gh[2048 + h]);
    g_gout[i] = (1.f - z) * n + z * g_hidden[i];
}

// ---------------- launch ------------------------------------------------------
extern "C" void kernel_launch(void* const* d_in, const int* in_sizes, int n_in,
                              void* d_out, int out_size) {
    const float* question = (const float*)d_in[0];
    const float* qmask    = (const float*)d_in[1];
    const float* passage  = (const float*)d_in[2];
    const float* pmask    = (const float*)d_in[3];
    const float* Vq       = (const float*)d_in[4];
    const float* Wk_q     = (const float*)d_in[5];
    const float* Wq_q     = (const float*)d_in[6];
    const float* w_q      = (const float*)d_in[7];
    const float* Wk_p     = (const float*)d_in[8];
    const float* Wq_p     = (const float*)d_in[9];
    const float* w_p      = (const float*)d_in[10];
    const float* W_ih     = (const float*)d_in[11];
    const float* W_hh     = (const float*)d_in[12];
    const float* b_ih     = (const float*)d_in[13];
    const float* b_hh     = (const float*)d_in[14];
    float* out = (float*)d_out;

    float *pPK, *psp, *psq, *palpha, *phid, *pinp, *pgout, *pQ1, *pQ2, *pcq, *pgi, *pgh;
    __half *pAh, *pQh, *pBqh, *pBph;
    cudaGetSymbolAddress((void**)&pPK,   g_PK);
    cudaGetSymbolAddress((void**)&psp,   g_sp);
    cudaGetSymbolAddress((void**)&psq,   g_sq);
    cudaGetSymbolAddress((void**)&palpha,g_alpha);
    cudaGetSymbolAddress((void**)&phid,  g_hidden);
    cudaGetSymbolAddress((void**)&pinp,  g_inputs);
    cudaGetSymbolAddress((void**)&pgout, g_gout);
    cudaGetSymbolAddress((void**)&pQ1,   g_Q1);
    cudaGetSymbolAddress((void**)&pQ2,   g_Q2);
    cudaGetSymbolAddress((void**)&pcq,   g_cq);
    cudaGetSymbolAddress((void**)&pgi,   g_gi);
    cudaGetSymbolAddress((void**)&pgh,   g_gh);
    cudaGetSymbolAddress((void**)&pAh,   g_Ah);
    cudaGetSymbolAddress((void**)&pQh,   g_Qh);
    cudaGetSymbolAddress((void**)&pBqh,  g_Bqh);
    cudaGetSymbolAddress((void**)&pBph,  g_Bph);

    cudaFuncSetAttribute(mma2_k, cudaFuncAttributeMaxDynamicSharedMemorySize, 2 * STG + 1024);

    // conversions (all plain fp32 -> fp16)
    cvt_k<<<1024, 256>>>(Wk_q, pBqh);
    cvt_k<<<1024, 256>>>(Wk_p, pBph);
    cvt_k<<<4096, 256>>>(question, pQh);
    cvt_k<<<65536, 256>>>(passage, pAh);

    // question branch
    xw_k<<<dim3(4, 1), 256>>>(Vq, Wq_q, pcq);
    mma2_k<<<dim3(8, 32), 256, 2 * STG + 1024>>>(pQh, pBqh, pPK, w_q, pcq, psp, 0);
    score_k<<<4096, 256>>>(pPK, pcq, w_q, qmask, psq, 0);
    softmax_k<<<64, 256>>>(psq, palpha, 64);
    pool_k<<<dim3(64, 4), 256>>>(question, palpha, phid, 64);
    xw_k<<<dim3(4, 64), 256>>>(phid, Wq_p, pQ1);
    rowdot_k<<<dim3(384, 64), 256>>>(phid, W_hh, b_hh, pgh, 3072);  // only needs hidden

    // passage GEMM with fused begin-score (computed once)
    zero_k<<<256, 256>>>(psp);
    mma2_k<<<dim3(8, 512), 256, 2 * STG + 1024>>>(pAh, pBph, pPK, w_p, pQ1, psp, 1);
    fixup_k<<<256, 256>>>(psp, pmask, out);

    // softmax + pool -> GRU input
    softmax_k<<<64, 256>>>(out, palpha, 1024);
    pool_k<<<dim3(64, 4), 256>>>(passage, palpha, pinp, 1024);

    // GRU + end logits
    rowdot_k<<<dim3(384, 64), 256>>>(pinp, W_ih, b_ih, pgi, 3072);
    gru_k<<<256, 256>>>();
    xw_k<<<dim3(4, 64), 256>>>(pgout, Wq_p, pQ2);
    score_k<<<65536, 256>>>(pPK, pQ2, w_p, pmask, out + 65536, 1);
}

// round 9
// speedup vs baseline: 1.8996x; 1.0154x over previous
#include <cuda_runtime.h>
#include <cuda_fp16.h>
#include <math.h>
#include <stdint.h>

// Shapes (fixed): B=64, TQ=64, TP=1024, H=A=1024
#define NB  64
#define Hn  1024

// ---------------- scratch (__device__ globals) --------------------------------
__device__ __half g_PKh[67108864];               // 128MB logits-GEMM output (fp16)
__device__ __half g_Ah[67108864];                // passage fp16
__device__ __half g_Qh[4194304];                 // question fp16
__device__ __half g_Bqh[1048576];                // Wk_q fp16 [k][n]
__device__ __half g_Bph[1048576];                // Wk_p fp16 [k][n]
__device__ float g_sp[65536];                    // fused begin-score partials
__device__ float g_sq[NB * 64];
__device__ float g_alpha[NB * 1024];
__device__ float g_hidden[NB * Hn];
__device__ float g_inputs[NB * Hn];
__device__ float g_gout[NB * Hn];
__device__ float g_Q1[NB * Hn];
__device__ float g_Q2[NB * Hn];
__device__ float g_cq[Hn];
__device__ float g_gi[NB * 3 * Hn];
__device__ float g_gh[NB * 3 * Hn];

// ---------------- helpers -----------------------------------------------------
__device__ __forceinline__ float tanh_apx(float x) {
    float y;
    asm("tanh.approx.f32 %0, %1;" : "=f"(y) : "f"(x));
    return y;
}
__device__ __forceinline__ uint32_t smem_u32(const void* p) {
    uint32_t a;
    asm("{ .reg .u64 t; cvta.to.shared.u64 t, %1; cvt.u32.u64 %0, t; }" : "=r"(a) : "l"(p));
    return a;
}
__device__ __forceinline__ void cpa16(uint32_t s, const void* g) {
    asm volatile("cp.async.cg.shared.global [%0], [%1], 16;" :: "r"(s), "l"(g));
}
__device__ __forceinline__ void ldsm_x4u(uint32_t* r, uint32_t a) {
    asm volatile("ldmatrix.sync.aligned.m8n8.x4.shared.b16 {%0,%1,%2,%3}, [%4];"
                 : "=r"(r[0]), "=r"(r[1]), "=r"(r[2]), "=r"(r[3]) : "r"(a));
}
__device__ __forceinline__ void ldsm_x4t_u(uint32_t* r, uint32_t a) {
    asm volatile("ldmatrix.sync.aligned.m8n8.x4.trans.shared.b16 {%0,%1,%2,%3}, [%4];"
                 : "=r"(r[0]), "=r"(r[1]), "=r"(r[2]), "=r"(r[3]) : "r"(a));
}
__device__ __forceinline__ void mma_f16(float* d, const uint32_t* a, const uint32_t* b) {
    asm volatile(
        "mma.sync.aligned.m16n8k16.row.col.f32.f16.f16.f32 "
        "{%0,%1,%2,%3}, {%4,%5,%6,%7}, {%8,%9}, {%0,%1,%2,%3};"
        : "+f"(d[0]), "+f"(d[1]), "+f"(d[2]), "+f"(d[3])
        : "r"(a[0]), "r"(a[1]), "r"(a[2]), "r"(a[3]), "r"(b[0]), "r"(b[1]));
}

// ---------------- conversions --------------------------------------------------
__global__ __launch_bounds__(256) void cvt_k(const float* __restrict__ src,
                                             __half* __restrict__ dst) {
    int i = blockIdx.x * 256 + threadIdx.x;
    float4 v = ((const float4*)src)[i];
    __half2* hp = (__half2*)dst;
    hp[2 * i]     = __halves2half2(__float2half(v.x), __float2half(v.y));
    hp[2 * i + 1] = __halves2half2(__float2half(v.z), __float2half(v.w));
}
__global__ __launch_bounds__(256) void zero_k(float* __restrict__ p) {
    p[blockIdx.x * 256 + threadIdx.x] = 0.f;
}
__global__ __launch_bounds__(256) void fixup_k(const float* __restrict__ sp,
                                               const float* __restrict__ mask,
                                               float* __restrict__ out) {
    int i = blockIdx.x * 256 + threadIdx.x;
    out[i] = (mask[i] > 0.f) ? sp[i] : -1e30f;
}

// ---------------- double-buffered single-pass fp16 GEMM + fused score ---------
// C(half)[M,1024] = A[M,1024] @ Bh[1024,1024] (fp16 in, fp32 accumulate).
// Optional fused partials: SP[r] += sum_{c in CTA cols} wv[c]*tanh(acc + Qv[..,c])
// CTA 128x128, K-chunk 64, 2-stage cp.async, 8 warps (2x4), 2 CTAs/SM.
// Stage: A 128x144B @0 (18432) | B 64x272B @18432 (17408) => 35840 B
#define STG 35840
__device__ __forceinline__ void load_chunk(uint32_t st,
                                           const __half* Ah, const __half* Bh,
                                           int row0, int col0, int k0, int tid) {
#pragma unroll
    for (int j = 0; j < 4; j++) {          // A: 128 rows x 64 halves
        int s = tid + j * 256;
        int r = s >> 3, c8 = s & 7;
        uint32_t so = (uint32_t)(r * 144 + c8 * 16);
        size_t go = (size_t)(row0 + r) * 1024 + k0 + c8 * 8;
        cpa16(st + so, Ah + go);
    }
#pragma unroll
    for (int j = 0; j < 4; j++) {          // B: 64 k-rows x 128 halves
        int s = tid + j * 256;
        int r = s >> 4, c8 = s & 15;
        uint32_t so = (uint32_t)(r * 272 + c8 * 16);
        size_t go = (size_t)(k0 + r) * 1024 + col0 + c8 * 8;
        cpa16(st + 18432 + so, Bh + go);
    }
    asm volatile("cp.async.commit_group;" ::: "memory");
}

__global__ __launch_bounds__(256, 2) void mma2_k(const __half* __restrict__ Ah,
                                                 const __half* __restrict__ Bh,
                                                 __half* __restrict__ C,
                                                 const float* __restrict__ wv,
                                                 const float* __restrict__ Qv,
                                                 float* __restrict__ SP,
                                                 int fuse) {
    extern __shared__ char dsm[];
    __shared__ float part[128];
    uint32_t sb  = smem_u32(dsm);
    uint32_t sba = (sb + 1023u) & ~1023u;
    const int tid = threadIdx.x;
    const int warp = tid >> 5, lane = tid & 31;
    const int wm = warp >> 2, wn = warp & 3;
    const int row0 = blockIdx.y * 128, col0 = blockIdx.x * 128;

    if (tid < 128) part[tid] = 0.f;

    float acc[4][4][4];
#pragma unroll
    for (int i = 0; i < 4; i++)
#pragma unroll
        for (int j = 0; j < 4; j++)
#pragma unroll
            for (int v = 0; v < 4; v++) acc[i][j][v] = 0.f;

    load_chunk(sba, Ah, Bh, row0, col0, 0, tid);

    for (int c = 0; c < 16; c++) {
        if (c + 1 < 16)
            load_chunk(sba + ((c + 1) & 1) * STG, Ah, Bh, row0, col0, (c + 1) * 64, tid);
        if (c + 1 < 16) asm volatile("cp.async.wait_group 1;" ::: "memory");
        else            asm volatile("cp.async.wait_group 0;" ::: "memory");
        __syncthreads();

        const uint32_t st  = sba + (c & 1) * STG;
        const uint32_t aB  = st;
        const uint32_t bB  = st + 18432;
        const int arow = lane & 15, acol = (lane >> 4) << 3;
        const int bkrl = lane & 15, bcb = wn * 32 + ((lane >> 4) << 3);
#pragma unroll
        for (int kk = 0; kk < 64; kk += 16) {
            uint32_t ah[4][4], bh[2][4];
#pragma unroll
            for (int mi = 0; mi < 4; mi++) {
                uint32_t off = (uint32_t)((wm * 64 + mi * 16 + arow) * 144 + (kk + acol) * 2);
                ldsm_x4u(ah[mi], aB + off);
            }
#pragma unroll
            for (int ni = 0; ni < 2; ni++) {
                uint32_t off = (uint32_t)((kk + bkrl) * 272 + (bcb + ni * 16) * 2);
                ldsm_x4t_u(bh[ni], bB + off);
            }
#pragma unroll
            for (int mi = 0; mi < 4; mi++)
#pragma unroll
                for (int nj = 0; nj < 4; nj++) {
                    int ni = nj >> 1, p = (nj & 1) * 2;
                    mma_f16(acc[mi][nj], ah[mi], &bh[ni][p]);
                }
        }
        if (c + 1 < 16) __syncthreads();   // buffer (c&1) reused by load(c+2)
    }

    // ---- epilogue: store fp16 C (+ optional fused score partials) ----
    const int rbase = row0 + wm * 64, cbase = col0 + wn * 32;
    const int lr = lane >> 2, lc = (lane & 3) * 2;
#pragma unroll
    for (int mi = 0; mi < 4; mi++)
#pragma unroll
        for (int nj = 0; nj < 4; nj++) {
            int rr = rbase + mi * 16 + lr;
            int cc = cbase + nj * 8 + lc;
            *(__half2*)&C[(size_t)rr * 1024 + cc] =
                __floats2half2_rn(acc[mi][nj][0], acc[mi][nj][1]);
            *(__half2*)&C[(size_t)(rr + 8) * 1024 + cc] =
                __floats2half2_rn(acc[mi][nj][2], acc[mi][nj][3]);
        }

    if (fuse) {
        const float* q = Qv + ((size_t)(row0 >> 10) << 10);
        __syncthreads();
#pragma unroll
        for (int mi = 0; mi < 4; mi++) {
            float sA = 0.f, sB = 0.f;
#pragma unroll
            for (int nj = 0; nj < 4; nj++) {
                int cc = cbase + nj * 8 + lc;
                float w0 = wv[cc], w1 = wv[cc + 1];
                float q0 = q[cc],  q1v = q[cc + 1];
                sA += w0 * tanh_apx(acc[mi][nj][0] + q0) + w1 * tanh_apx(acc[mi][nj][1] + q1v);
                sB += w0 * tanh_apx(acc[mi][nj][2] + q0) + w1 * tanh_apx(acc[mi][nj][3] + q1v);
            }
            sA += __shfl_xor_sync(0xffffffffu, sA, 1);
            sA += __shfl_xor_sync(0xffffffffu, sA, 2);
            sB += __shfl_xor_sync(0xffffffffu, sB, 1);
            sB += __shfl_xor_sync(0xffffffffu, sB, 2);
            if ((lane & 3) == 0) {
                atomicAdd(&part[wm * 64 + mi * 16 + lr], sA);
                atomicAdd(&part[wm * 64 + mi * 16 + lr + 8], sB);
            }
        }
        __syncthreads();
        if (tid < 128) atomicAdd(&SP[row0 + tid], part[tid]);
    }
}

// ---------------- score over fp16 PK: warp-per-row -----------------------------
// s[r] = mask[r] ? sum_c wv[c]*tanh(C[r,c] + q[..,c]) : -1e30
__global__ __launch_bounds__(256) void score_h_k(const __half* __restrict__ C,
                                                 const float* __restrict__ qterm,
                                                 const float* __restrict__ wv,
                                                 const float* __restrict__ mask,
                                                 float* __restrict__ outs, int per_row) {
    const int warp = threadIdx.x >> 5, lane = threadIdx.x & 31;
    const int r = blockIdx.x * 8 + warp;
    const __half* crow = C + (size_t)r * 1024;
    const float* q = per_row ? (qterm + (size_t)(r >> 10) * 1024) : qterm;
    float acc = 0.f;
#pragma unroll
    for (int i = 0; i < 4; i++) {
        int c0 = (lane + i * 32) * 8;            // 8 halves (16B) per lane-chunk
        uint4 v = *(const uint4*)(crow + c0);
        const __half2* h = (const __half2*)&v;
#pragma unroll
        for (int j = 0; j < 4; j++) {
            float2 f = __half22float2(h[j]);
            int c = c0 + j * 2;
            acc += wv[c]     * tanh_apx(f.x + q[c]);
            acc += wv[c + 1] * tanh_apx(f.y + q[c + 1]);
        }
    }
#pragma unroll
    for (int o = 16; o; o >>= 1) acc += __shfl_xor_sync(0xffffffffu, acc, o);
    if (lane == 0) outs[r] = (mask[r] > 0.f) ? acc : -1e30f;
}

__global__ __launch_bounds__(256) void softmax_k(const float* __restrict__ s,
                                                 float* __restrict__ alpha, int T) {
    const int b = blockIdx.x, tid = threadIdx.x;
    __shared__ float red[8];
    __shared__ float sh;
    const float* sb = s + (size_t)b * T;
    float mx = -3.0e38f;
    for (int t = tid; t < T; t += 256) mx = fmaxf(mx, sb[t]);
    for (int o = 16; o; o >>= 1) mx = fmaxf(mx, __shfl_xor_sync(0xffffffffu, mx, o));
    if ((tid & 31) == 0) red[tid >> 5] = mx;
    __syncthreads();
    if (tid == 0) {
        float v = red[0];
#pragma unroll
        for (int w = 1; w < 8; w++) v = fmaxf(v, red[w]);
        sh = v;
    }
    __syncthreads();
    mx = sh;
    float sum = 0.f;
    for (int t = tid; t < T; t += 256) {
        float e = expf(sb[t] - mx);
        alpha[(size_t)b * T + t] = e;
        sum += e;
    }
    for (int o = 16; o; o >>= 1) sum += __shfl_xor_sync(0xffffffffu, sum, o);
    __syncthreads();
    if ((tid & 31) == 0) red[tid >> 5] = sum;
    __syncthreads();
    if (tid == 0) {
        float v = 0.f;
#pragma unroll
        for (int w = 0; w < 8; w++) v += red[w];
        sh = 1.f / v;
    }
    __syncthreads();
    float inv = sh;
    for (int t = tid; t < T; t += 256) alpha[(size_t)b * T + t] *= inv;
}

__global__ __launch_bounds__(256) void pool_k(const float* __restrict__ key,
                                              const float* __restrict__ alpha,
                                              float* __restrict__ out, int T) {
    const int b = blockIdx.x;
    const int h = blockIdx.y * 256 + threadIdx.x;
    const float* kb = key + (size_t)b * T * 1024 + h;
    const float* ab = alpha + (size_t)b * T;
    float a0 = 0.f, a1 = 0.f, a2 = 0.f, a3 = 0.f;
    for (int t = 0; t < T; t += 4) {
        a0 += ab[t + 0] * kb[(size_t)(t + 0) * 1024];
        a1 += ab[t + 1] * kb[(size_t)(t + 1) * 1024];
        a2 += ab[t + 2] * kb[(size_t)(t + 2) * 1024];
        a3 += ab[t + 3] * kb[(size_t)(t + 3) * 1024];
    }
    out[(size_t)b * 1024 + h] = (a0 + a1) + (a2 + a3);
}

__global__ __launch_bounds__(256) void xw_k(const float* __restrict__ x,
                                            const float* __restrict__ W,
                                            float* __restrict__ out) {
    const int b = blockIdx.y;
    const int j = blockIdx.x * 256 + threadIdx.x;
    __shared__ float xs[1024];
    for (int i = threadIdx.x; i < 1024; i += 256) xs[i] = x[(size_t)b * 1024 + i];
    __syncthreads();
    const float* Wc = W + j;
    float a0 = 0.f, a1 = 0.f, a2 = 0.f, a3 = 0.f;
    for (int h = 0; h < 1024; h += 4) {
        a0 += xs[h + 0] * Wc[(size_t)(h + 0) * 1024];
        a1 += xs[h + 1] * Wc[(size_t)(h + 1) * 1024];
        a2 += xs[h + 2] * Wc[(size_t)(h + 2) * 1024];
        a3 += xs[h + 3] * Wc[(size_t)(h + 3) * 1024];
    }
    out[(size_t)b * 1024 + j] = (a0 + a1) + (a2 + a3);
}

__global__ __launch_bounds__(256) void rowdot_k(const float* __restrict__ x,
                                                const float* __restrict__ W,
                                                const float* __restrict__ bias,
                                                float* __restrict__ out, int N) {
    const int b = blockIdx.y;
    const int w = threadIdx.x >> 5, lane = threadIdx.x & 31;
    const int j = blockIdx.x * 8 + w;
    const float* xr = x + (size_t)b * 1024;
    const float* wr = W + (size_t)j * 1024;
    float a0 = 0.f, a1 = 0.f;
    for (int h = lane; h < 1024; h += 64) {
        a0 += xr[h] * wr[h];
        a1 += xr[h + 32] * wr[h + 32];
    }
    float acc = a0 + a1;
    for (int o = 16; o; o >>= 1) acc += __shfl_xor_sync(0xffffffffu, acc, o);
    if (!lane) out[(size_t)b * N + j] = acc + bias[j];
}

__global__ __launch_bounds__(256) void gru_k() {
    const int i = blockIdx.x * 256 + threadIdx.x;
    const int b = i >> 10, h = i & 1023;
    const float* gi = g_gi + (size_t)b * 3072;
    const float* gh = g_gh + (size_t)b * 3072;
    float r = 1.f / (1.f + expf(-(gi[h] + gh[h])));
    float z = 1.f / (1.f + expf(-(gi[1024 + h] + gh[1024 + h])));
    float n = tanhf(gi[2048 + h] + r * gh[2048 + h]);
    g_gout[i] = (1.f - z) * n + z * g_hidden[i];
}

// ---------------- launch ------------------------------------------------------
extern "C" void kernel_launch(void* const* d_in, const int* in_sizes, int n_in,
                              void* d_out, int out_size) {
    const float* question = (const float*)d_in[0];
    const float* qmask    = (const float*)d_in[1];
    const float* passage  = (const float*)d_in[2];
    const float* pmask    = (const float*)d_in[3];
    const float* Vq       = (const float*)d_in[4];
    const float* Wk_q     = (const float*)d_in[5];
    const float* Wq_q     = (const float*)d_in[6];
    const float* w_q      = (const float*)d_in[7];
    const float* Wk_p     = (const float*)d_in[8];
    const float* Wq_p     = (const float*)d_in[9];
    const float* w_p      = (const float*)d_in[10];
    const float* W_ih     = (const float*)d_in[11];
    const float* W_hh     = (const float*)d_in[12];
    const float* b_ih     = (const float*)d_in[13];
    const float* b_hh     = (const float*)d_in[14];
    float* out = (float*)d_out;

    float *psp, *psq, *palpha, *phid, *pinp, *pgout, *pQ1, *pQ2, *pcq, *pgi, *pgh;
    __half *pPKh, *pAh, *pQh, *pBqh, *pBph;
    cudaGetSymbolAddress((void**)&pPKh,  g_PKh);
    cudaGetSymbolAddress((void**)&psp,   g_sp);
    cudaGetSymbolAddress((void**)&psq,   g_sq);
    cudaGetSymbolAddress((void**)&palpha,g_alpha);
    cudaGetSymbolAddress((void**)&phid,  g_hidden);
    cudaGetSymbolAddress((void**)&pinp,  g_inputs);
    cudaGetSymbolAddress((void**)&pgout, g_gout);
    cudaGetSymbolAddress((void**)&pQ1,   g_Q1);
    cudaGetSymbolAddress((void**)&pQ2,   g_Q2);
    cudaGetSymbolAddress((void**)&pcq,   g_cq);
    cudaGetSymbolAddress((void**)&pgi,   g_gi);
    cudaGetSymbolAddress((void**)&pgh,   g_gh);
    cudaGetSymbolAddress((void**)&pAh,   g_Ah);
    cudaGetSymbolAddress((void**)&pQh,   g_Qh);
    cudaGetSymbolAddress((void**)&pBqh,  g_Bqh);
    cudaGetSymbolAddress((void**)&pBph,  g_Bph);

    cudaFuncSetAttribute(mma2_k, cudaFuncAttributeMaxDynamicSharedMemorySize, 2 * STG + 1024);

    // conversions (all plain fp32 -> fp16)
    cvt_k<<<1024, 256>>>(Wk_q, pBqh);
    cvt_k<<<1024, 256>>>(Wk_p, pBph);
    cvt_k<<<4096, 256>>>(question, pQh);
    cvt_k<<<65536, 256>>>(passage, pAh);

    // question branch
    xw_k<<<dim3(4, 1), 256>>>(Vq, Wq_q, pcq);
    mma2_k<<<dim3(8, 32), 256, 2 * STG + 1024>>>(pQh, pBqh, pPKh, w_q, pcq, psp, 0);
    score_h_k<<<512, 256>>>(pPKh, pcq, w_q, qmask, psq, 0);
    softmax_k<<<64, 256>>>(psq, palpha, 64);
    pool_k<<<dim3(64, 4), 256>>>(question, palpha, phid, 64);
    xw_k<<<dim3(4, 64), 256>>>(phid, Wq_p, pQ1);
    rowdot_k<<<dim3(384, 64), 256>>>(phid, W_hh, b_hh, pgh, 3072);  // only needs hidden

    // passage GEMM with fused begin-score (computed once)
    zero_k<<<256, 256>>>(psp);
    mma2_k<<<dim3(8, 512), 256, 2 * STG + 1024>>>(pAh, pBph, pPKh, w_p, pQ1, psp, 1);
    fixup_k<<<256, 256>>>(psp, pmask, out);

    // softmax + pool -> GRU input
    softmax_k<<<64, 256>>>(out, palpha, 1024);
    pool_k<<<dim3(64, 4), 256>>>(passage, palpha, pinp, 1024);

    // GRU + end logits
    rowdot_k<<<dim3(384, 64), 256>>>(pinp, W_ih, b_ih, pgi, 3072);
    gru_k<<<256, 256>>>();
    xw_k<<<dim3(4, 64), 256>>>(pgout, Wq_p, pQ2);
    score_h_k<<<8192, 256>>>(pPKh, pQ2, w_p, pmask, out + 65536, 1);
}

// round 10
// speedup vs baseline: 1.9032x; 1.0019x over previous
#include <cuda_runtime.h>
#include <cuda_fp16.h>
#include <math.h>
#include <stdint.h>

// Shapes (fixed): B=64, TQ=64, TP=1024, H=A=1024
#define NB  64
#define Hn  1024

// ---------------- scratch (__device__ globals) --------------------------------
__device__ __half g_PKh[67108864];               // 128MB logits-GEMM output (fp16)
__device__ __half g_Ah[67108864];                // passage fp16
__device__ __half g_Qh[4194304];                 // question fp16
__device__ __half g_Bqh[1048576];                // Wk_q fp16 [k][n]
__device__ __half g_Bph[1048576];                // Wk_p fp16 [k][n]
__device__ float g_sp[65536];                    // fused begin-score partials
__device__ float g_sq[NB * 64];
__device__ float g_alpha[NB * 1024];
__device__ float g_hidden[NB * Hn];
__device__ float g_inputs[NB * Hn];
__device__ float g_gout[NB * Hn];
__device__ float g_Q1[NB * Hn];
__device__ float g_Q2[NB * Hn];
__device__ float g_cq[Hn];
__device__ float g_gi[NB * 3 * Hn];
__device__ float g_gh[NB * 3 * Hn];

// ---------------- helpers -----------------------------------------------------
__device__ __forceinline__ float tanh_apx(float x) {
    float y;
    asm("tanh.approx.f32 %0, %1;" : "=f"(y) : "f"(x));
    return y;
}
__device__ __forceinline__ uint32_t smem_u32(const void* p) {
    uint32_t a;
    asm("{ .reg .u64 t; cvta.to.shared.u64 t, %1; cvt.u32.u64 %0, t; }" : "=r"(a) : "l"(p));
    return a;
}
__device__ __forceinline__ void cpa16(uint32_t s, const void* g) {
    asm volatile("cp.async.cg.shared.global [%0], [%1], 16;" :: "r"(s), "l"(g));
}
__device__ __forceinline__ void ldsm_x4u(uint32_t* r, uint32_t a) {
    asm volatile("ldmatrix.sync.aligned.m8n8.x4.shared.b16 {%0,%1,%2,%3}, [%4];"
                 : "=r"(r[0]), "=r"(r[1]), "=r"(r[2]), "=r"(r[3]) : "r"(a));
}
__device__ __forceinline__ void ldsm_x4t_u(uint32_t* r, uint32_t a) {
    asm volatile("ldmatrix.sync.aligned.m8n8.x4.trans.shared.b16 {%0,%1,%2,%3}, [%4];"
                 : "=r"(r[0]), "=r"(r[1]), "=r"(r[2]), "=r"(r[3]) : "r"(a));
}
__device__ __forceinline__ void mma_f16(float* d, const uint32_t* a, const uint32_t* b) {
    asm volatile(
        "mma.sync.aligned.m16n8k16.row.col.f32.f16.f16.f32 "
        "{%0,%1,%2,%3}, {%4,%5,%6,%7}, {%8,%9}, {%0,%1,%2,%3};"
        : "+f"(d[0]), "+f"(d[1]), "+f"(d[2]), "+f"(d[3])
        : "r"(a[0]), "r"(a[1]), "r"(a[2]), "r"(a[3]), "r"(b[0]), "r"(b[1]));
}

// ---------------- conversions --------------------------------------------------
__global__ __launch_bounds__(256) void cvt_k(const float* __restrict__ src,
                                             __half* __restrict__ dst) {
    int i = blockIdx.x * 256 + threadIdx.x;
    float4 v = ((const float4*)src)[i];
    __half2* hp = (__half2*)dst;
    hp[2 * i]     = __halves2half2(__float2half(v.x), __float2half(v.y));
    hp[2 * i + 1] = __halves2half2(__float2half(v.z), __float2half(v.w));
}
__global__ __launch_bounds__(256) void zero_k(float* __restrict__ p) {
    p[blockIdx.x * 256 + threadIdx.x] = 0.f;
}
__global__ __launch_bounds__(256) void fixup_k(const float* __restrict__ sp,
                                               const float* __restrict__ mask,
                                               float* __restrict__ out) {
    int i = blockIdx.x * 256 + threadIdx.x;
    out[i] = (mask[i] > 0.f) ? sp[i] : -1e30f;
}

// ---------------- 3-stage single-pass fp16 GEMM + fused score -----------------
// C(half)[M,1024] = A[M,1024] @ Bh[1024,1024] (fp16 in, fp32 accumulate).
// Optional fused partials: SP[r] += sum_{c in CTA cols} wv[c]*tanh(acc + Qv[..,c])
// CTA 128x128, K-chunk 64, 3-stage cp.async (1 sync/chunk), 8 warps, 2 CTAs/SM.
// Stage: A 128x144B @0 (18432) | B 64x272B @18432 (17408) => 35840 B
#define STG 35840
__device__ __forceinline__ void load_chunk(uint32_t st,
                                           const __half* Ah, const __half* Bh,
                                           int row0, int col0, int k0, int tid) {
#pragma unroll
    for (int j = 0; j < 4; j++) {          // A: 128 rows x 64 halves
        int s = tid + j * 256;
        int r = s >> 3, c8 = s & 7;
        uint32_t so = (uint32_t)(r * 144 + c8 * 16);
        size_t go = (size_t)(row0 + r) * 1024 + k0 + c8 * 8;
        cpa16(st + so, Ah + go);
    }
#pragma unroll
    for (int j = 0; j < 4; j++) {          // B: 64 k-rows x 128 halves
        int s = tid + j * 256;
        int r = s >> 4, c8 = s & 15;
        uint32_t so = (uint32_t)(r * 272 + c8 * 16);
        size_t go = (size_t)(k0 + r) * 1024 + col0 + c8 * 8;
        cpa16(st + 18432 + so, Bh + go);
    }
    asm volatile("cp.async.commit_group;" ::: "memory");
}

__global__ __launch_bounds__(256, 2) void mma2_k(const __half* __restrict__ Ah,
                                                 const __half* __restrict__ Bh,
                                                 __half* __restrict__ C,
                                                 const float* __restrict__ wv,
                                                 const float* __restrict__ Qv,
                                                 float* __restrict__ SP,
                                                 int fuse) {
    extern __shared__ char dsm[];
    __shared__ float part[128];
    uint32_t sb  = smem_u32(dsm);
    uint32_t sba = (sb + 1023u) & ~1023u;
    const int tid = threadIdx.x;
    const int warp = tid >> 5, lane = tid & 31;
    const int wm = warp >> 2, wn = warp & 3;
    const int row0 = blockIdx.y * 128, col0 = blockIdx.x * 128;

    if (tid < 128) part[tid] = 0.f;

    float acc[4][4][4];
#pragma unroll
    for (int i = 0; i < 4; i++)
#pragma unroll
        for (int j = 0; j < 4; j++)
#pragma unroll
            for (int v = 0; v < 4; v++) acc[i][j][v] = 0.f;

    // prolog: 2 chunks in flight
    load_chunk(sba,       Ah, Bh, row0, col0, 0,  tid);
    load_chunk(sba + STG, Ah, Bh, row0, col0, 64, tid);

    for (int c = 0; c < 16; c++) {
        if (c < 15) asm volatile("cp.async.wait_group 1;" ::: "memory");
        else        asm volatile("cp.async.wait_group 0;" ::: "memory");
        __syncthreads();      // chunk c visible; all warps done with compute(c-1)
        if (c + 2 < 16)       // buffer (c+2)%3 freed by compute(c-1)
            load_chunk(sba + ((c + 2) % 3) * STG, Ah, Bh, row0, col0, (c + 2) * 64, tid);

        const uint32_t st  = sba + (c % 3) * STG;
        const uint32_t aB  = st;
        const uint32_t bB  = st + 18432;
        const int arow = lane & 15, acol = (lane >> 4) << 3;
        const int bkrl = lane & 15, bcb = wn * 32 + ((lane >> 4) << 3);
#pragma unroll
        for (int kk = 0; kk < 64; kk += 16) {
            uint32_t ah[4][4], bh[2][4];
#pragma unroll
            for (int mi = 0; mi < 4; mi++) {
                uint32_t off = (uint32_t)((wm * 64 + mi * 16 + arow) * 144 + (kk + acol) * 2);
                ldsm_x4u(ah[mi], aB + off);
            }
#pragma unroll
            for (int ni = 0; ni < 2; ni++) {
                uint32_t off = (uint32_t)((kk + bkrl) * 272 + (bcb + ni * 16) * 2);
                ldsm_x4t_u(bh[ni], bB + off);
            }
#pragma unroll
            for (int mi = 0; mi < 4; mi++)
#pragma unroll
                for (int nj = 0; nj < 4; nj++) {
                    int ni = nj >> 1, p = (nj & 1) * 2;
                    mma_f16(acc[mi][nj], ah[mi], &bh[ni][p]);
                }
        }
    }

    // ---- epilogue: store fp16 C (+ optional fused score partials) ----
    const int rbase = row0 + wm * 64, cbase = col0 + wn * 32;
    const int lr = lane >> 2, lc = (lane & 3) * 2;
#pragma unroll
    for (int mi = 0; mi < 4; mi++)
#pragma unroll
        for (int nj = 0; nj < 4; nj++) {
            int rr = rbase + mi * 16 + lr;
            int cc = cbase + nj * 8 + lc;
            *(__half2*)&C[(size_t)rr * 1024 + cc] =
                __floats2half2_rn(acc[mi][nj][0], acc[mi][nj][1]);
            *(__half2*)&C[(size_t)(rr + 8) * 1024 + cc] =
                __floats2half2_rn(acc[mi][nj][2], acc[mi][nj][3]);
        }

    if (fuse) {
        const float* q = Qv + ((size_t)(row0 >> 10) << 10);
        __syncthreads();
#pragma unroll
        for (int mi = 0; mi < 4; mi++) {
            float sA = 0.f, sB = 0.f;
#pragma unroll
            for (int nj = 0; nj < 4; nj++) {
                int cc = cbase + nj * 8 + lc;
                float w0 = wv[cc], w1 = wv[cc + 1];
                float q0 = q[cc],  q1v = q[cc + 1];
                sA += w0 * tanh_apx(acc[mi][nj][0] + q0) + w1 * tanh_apx(acc[mi][nj][1] + q1v);
                sB += w0 * tanh_apx(acc[mi][nj][2] + q0) + w1 * tanh_apx(acc[mi][nj][3] + q1v);
            }
            sA += __shfl_xor_sync(0xffffffffu, sA, 1);
            sA += __shfl_xor_sync(0xffffffffu, sA, 2);
            sB += __shfl_xor_sync(0xffffffffu, sB, 1);
            sB += __shfl_xor_sync(0xffffffffu, sB, 2);
            if ((lane & 3) == 0) {
                atomicAdd(&part[wm * 64 + mi * 16 + lr], sA);
                atomicAdd(&part[wm * 64 + mi * 16 + lr + 8], sB);
            }
        }
        __syncthreads();
        if (tid < 128) atomicAdd(&SP[row0 + tid], part[tid]);
    }
}

// ---------------- score over fp16 PK: warp-per-row -----------------------------
__global__ __launch_bounds__(256) void score_h_k(const __half* __restrict__ C,
                                                 const float* __restrict__ qterm,
                                                 const float* __restrict__ wv,
                                                 const float* __restrict__ mask,
                                                 float* __restrict__ outs, int per_row) {
    const int warp = threadIdx.x >> 5, lane = threadIdx.x & 31;
    const int r = blockIdx.x * 8 + warp;
    const __half* crow = C + (size_t)r * 1024;
    const float* q = per_row ? (qterm + (size_t)(r >> 10) * 1024) : qterm;
    float acc = 0.f;
#pragma unroll
    for (int i = 0; i < 4; i++) {
        int c0 = (lane + i * 32) * 8;
        uint4 v = *(const uint4*)(crow + c0);
        const __half2* h = (const __half2*)&v;
#pragma unroll
        for (int j = 0; j < 4; j++) {
            float2 f = __half22float2(h[j]);
            int c = c0 + j * 2;
            acc += wv[c]     * tanh_apx(f.x + q[c]);
            acc += wv[c + 1] * tanh_apx(f.y + q[c + 1]);
        }
    }
#pragma unroll
    for (int o = 16; o; o >>= 1) acc += __shfl_xor_sync(0xffffffffu, acc, o);
    if (lane == 0) outs[r] = (mask[r] > 0.f) ? acc : -1e30f;
}

__global__ __launch_bounds__(256) void softmax_k(const float* __restrict__ s,
                                                 float* __restrict__ alpha, int T) {
    const int b = blockIdx.x, tid = threadIdx.x;
    __shared__ float red[8];
    __shared__ float sh;
    const float* sb = s + (size_t)b * T;
    float mx = -3.0e38f;
    for (int t = tid; t < T; t += 256) mx = fmaxf(mx, sb[t]);
    for (int o = 16; o; o >>= 1) mx = fmaxf(mx, __shfl_xor_sync(0xffffffffu, mx, o));
    if ((tid & 31) == 0) red[tid >> 5] = mx;
    __syncthreads();
    if (tid == 0) {
        float v = red[0];
#pragma unroll
        for (int w = 1; w < 8; w++) v = fmaxf(v, red[w]);
        sh = v;
    }
    __syncthreads();
    mx = sh;
    float sum = 0.f;
    for (int t = tid; t < T; t += 256) {
        float e = expf(sb[t] - mx);
        alpha[(size_t)b * T + t] = e;
        sum += e;
    }
    for (int o = 16; o; o >>= 1) sum += __shfl_xor_sync(0xffffffffu, sum, o);
    __syncthreads();
    if ((tid & 31) == 0) red[tid >> 5] = sum;
    __syncthreads();
    if (tid == 0) {
        float v = 0.f;
#pragma unroll
        for (int w = 0; w < 8; w++) v += red[w];
        sh = 1.f / v;
    }
    __syncthreads();
    float inv = sh;
    for (int t = tid; t < T; t += 256) alpha[(size_t)b * T + t] *= inv;
}

// fp32 key pool (question)
__global__ __launch_bounds__(256) void pool_k(const float* __restrict__ key,
                                              const float* __restrict__ alpha,
                                              float* __restrict__ out, int T) {
    const int b = blockIdx.x;
    const int h = blockIdx.y * 256 + threadIdx.x;
    const float* kb = key + (size_t)b * T * 1024 + h;
    const float* ab = alpha + (size_t)b * T;
    float a0 = 0.f, a1 = 0.f, a2 = 0.f, a3 = 0.f;
    for (int t = 0; t < T; t += 4) {
        a0 += ab[t + 0] * kb[(size_t)(t + 0) * 1024];
        a1 += ab[t + 1] * kb[(size_t)(t + 1) * 1024];
        a2 += ab[t + 2] * kb[(size_t)(t + 2) * 1024];
        a3 += ab[t + 3] * kb[(size_t)(t + 3) * 1024];
    }
    out[(size_t)b * 1024 + h] = (a0 + a1) + (a2 + a3);
}

// fp16 key pool (passage) — halves the 256MB read
__global__ __launch_bounds__(256) void pool_h_k(const __half* __restrict__ key,
                                                const float* __restrict__ alpha,
                                                float* __restrict__ out, int T) {
    const int b = blockIdx.x;
    const int h = blockIdx.y * 256 + threadIdx.x;
    const __half* kb = key + (size_t)b * T * 1024 + h;
    const float* ab = alpha + (size_t)b * T;
    float a0 = 0.f, a1 = 0.f, a2 = 0.f, a3 = 0.f;
    for (int t = 0; t < T; t += 4) {
        a0 += ab[t + 0] * __half2float(kb[(size_t)(t + 0) * 1024]);
        a1 += ab[t + 1] * __half2float(kb[(size_t)(t + 1) * 1024]);
        a2 += ab[t + 2] * __half2float(kb[(size_t)(t + 2) * 1024]);
        a3 += ab[t + 3] * __half2float(kb[(size_t)(t + 3) * 1024]);
    }
    out[(size_t)b * 1024 + h] = (a0 + a1) + (a2 + a3);
}

__global__ __launch_bounds__(256) void xw_k(const float* __restrict__ x,
                                            const float* __restrict__ W,
                                            float* __restrict__ out) {
    const int b = blockIdx.y;
    const int j = blockIdx.x * 256 + threadIdx.x;
    __shared__ float xs[1024];
    for (int i = threadIdx.x; i < 1024; i += 256) xs[i] = x[(size_t)b * 1024 + i];
    __syncthreads();
    const float* Wc = W + j;
    float a0 = 0.f, a1 = 0.f, a2 = 0.f, a3 = 0.f;
    for (int h = 0; h < 1024; h += 4) {
        a0 += xs[h + 0] * Wc[(size_t)(h + 0) * 1024];
        a1 += xs[h + 1] * Wc[(size_t)(h + 1) * 1024];
        a2 += xs[h + 2] * Wc[(size_t)(h + 2) * 1024];
        a3 += xs[h + 3] * Wc[(size_t)(h + 3) * 1024];
    }
    out[(size_t)b * 1024 + j] = (a0 + a1) + (a2 + a3);
}

__global__ __launch_bounds__(256) void rowdot_k(const float* __restrict__ x,
                                                const float* __restrict__ W,
                                                const float* __restrict__ bias,
                                                float* __restrict__ out, int N) {
    const int b = blockIdx.y;
    const int w = threadIdx.x >> 5, lane = threadIdx.x & 31;
    const int j = blockIdx.x * 8 + w;
    const float* xr = x + (size_t)b * 1024;
    const float* wr = W + (size_t)j * 1024;
    float a0 = 0.f, a1 = 0.f;
    for (int h = lane; h < 1024; h += 64) {
        a0 += xr[h] * wr[h];
        a1 += xr[h + 32] * wr[h + 32];
    }
    float acc = a0 + a1;
    for (int o = 16; o; o >>= 1) acc += __shfl_xor_sync(0xffffffffu, acc, o);
    if (!lane) out[(size_t)b * N + j] = acc + bias[j];
}

__global__ __launch_bounds__(256) void gru_k() {
    const int i = blockIdx.x * 256 + threadIdx.x;
    const int b = i >> 10, h = i & 1023;
    const float* gi = g_gi + (size_t)b * 3072;
    const float* gh = g_gh + (size_t)b * 3072;
    float r = 1.f / (1.f + expf(-(gi[h] + gh[h])));
    float z = 1.f / (1.f + expf(-(gi[1024 + h] + gh[1024 + h])));
    float n = tanhf(gi[2048 + h] + r * gh[2048 + h]);
    g_gout[i] = (1.f - z) * n + z * g_hidden[i];
}

// ---------------- launch ------------------------------------------------------
extern "C" void kernel_launch(void* const* d_in, const int* in_sizes, int n_in,
                              void* d_out, int out_size) {
    const float* question = (const float*)d_in[0];
    const float* qmask    = (const float*)d_in[1];
    const float* passage  = (const float*)d_in[2];
    const float* pmask    = (const float*)d_in[3];
    const float* Vq       = (const float*)d_in[4];
    const float* Wk_q     = (const float*)d_in[5];
    const float* Wq_q     = (const float*)d_in[6];
    const float* w_q      = (const float*)d_in[7];
    const float* Wk_p     = (const float*)d_in[8];
    const float* Wq_p     = (const float*)d_in[9];
    const float* w_p      = (const float*)d_in[10];
    const float* W_ih     = (const float*)d_in[11];
    const float* W_hh     = (const float*)d_in[12];
    const float* b_ih     = (const float*)d_in[13];
    const float* b_hh     = (const float*)d_in[14];
    float* out = (float*)d_out;

    float *psp, *psq, *palpha, *phid, *pinp, *pgout, *pQ1, *pQ2, *pcq, *pgi, *pgh;
    __half *pPKh, *pAh, *pQh, *pBqh, *pBph;
    cudaGetSymbolAddress((void**)&pPKh,  g_PKh);
    cudaGetSymbolAddress((void**)&psp,   g_sp);
    cudaGetSymbolAddress((void**)&psq,   g_sq);
    cudaGetSymbolAddress((void**)&palpha,g_alpha);
    cudaGetSymbolAddress((void**)&phid,  g_hidden);
    cudaGetSymbolAddress((void**)&pinp,  g_inputs);
    cudaGetSymbolAddress((void**)&pgout, g_gout);
    cudaGetSymbolAddress((void**)&pQ1,   g_Q1);
    cudaGetSymbolAddress((void**)&pQ2,   g_Q2);
    cudaGetSymbolAddress((void**)&pcq,   g_cq);
    cudaGetSymbolAddress((void**)&pgi,   g_gi);
    cudaGetSymbolAddress((void**)&pgh,   g_gh);
    cudaGetSymbolAddress((void**)&pAh,   g_Ah);
    cudaGetSymbolAddress((void**)&pQh,   g_Qh);
    cudaGetSymbolAddress((void**)&pBqh,  g_Bqh);
    cudaGetSymbolAddress((void**)&pBph,  g_Bph);

    cudaFuncSetAttribute(mma2_k, cudaFuncAttributeMaxDynamicSharedMemorySize, 3 * STG + 1024);

    // conversions (all plain fp32 -> fp16)
    cvt_k<<<1024, 256>>>(Wk_q, pBqh);
    cvt_k<<<1024, 256>>>(Wk_p, pBph);
    cvt_k<<<4096, 256>>>(question, pQh);
    cvt_k<<<65536, 256>>>(passage, pAh);

    // question branch
    xw_k<<<dim3(4, 1), 256>>>(Vq, Wq_q, pcq);
    mma2_k<<<dim3(8, 32), 256, 3 * STG + 1024>>>(pQh, pBqh, pPKh, w_q, pcq, psp, 0);
    score_h_k<<<512, 256>>>(pPKh, pcq, w_q, qmask, psq, 0);
    softmax_k<<<64, 256>>>(psq, palpha, 64);
    pool_k<<<dim3(64, 4), 256>>>(question, palpha, phid, 64);
    xw_k<<<dim3(4, 64), 256>>>(phid, Wq_p, pQ1);
    rowdot_k<<<dim3(384, 64), 256>>>(phid, W_hh, b_hh, pgh, 3072);  // only needs hidden

    // passage GEMM with fused begin-score (computed once)
    zero_k<<<256, 256>>>(psp);
    mma2_k<<<dim3(8, 512), 256, 3 * STG + 1024>>>(pAh, pBph, pPKh, w_p, pQ1, psp, 1);
    fixup_k<<<256, 256>>>(psp, pmask, out);

    // softmax + pool (fp16 passage) -> GRU input
    softmax_k<<<64, 256>>>(out, palpha, 1024);
    pool_h_k<<<dim3(64, 4), 256>>>(pAh, palpha, pinp, 1024);

    // GRU + end logits
    rowdot_k<<<dim3(384, 64), 256>>>(pinp, W_ih, b_ih, pgi, 3072);
    gru_k<<<256, 256>>>();
    xw_k<<<dim3(4, 64), 256>>>(pgout, Wq_p, pQ2);
    score_h_k<<<8192, 256>>>(pPKh, pQ2, w_p, pmask, out + 65536, 1);
}

// round 11
// speedup vs baseline: 2.0937x; 1.1001x over previous
#include <cuda_runtime.h>
#include <cuda_fp16.h>
#include <math.h>
#include <stdint.h>

// Shapes (fixed): B=64, TQ=64, TP=1024, H=A=1024
#define NB  64
#define Hn  1024

// ---------------- scratch (__device__ globals) --------------------------------
__device__ __half g_PKh[67108864];               // 128MB logits-GEMM output (fp16)
__device__ __half g_Ah[67108864];                // passage fp16
__device__ __half g_Qh[4194304];                 // question fp16
__device__ __half g_Bqh[1048576];                // Wk_q fp16 [k][n]
__device__ __half g_Bph[1048576];                // Wk_p fp16 [k][n]
__device__ float g_WqpT[1048576];                // Wq_p transposed [j][h]
__device__ float g_zb[1024];                     // zero bias
__device__ float g_sp[65536];                    // fused begin-score partials
__device__ float g_sq[NB * 64];
__device__ float g_alpha[NB * 1024];
__device__ float g_hidden[NB * Hn];
__device__ float g_inputs[NB * Hn];
__device__ float g_gout[NB * Hn];
__device__ float g_Q1[NB * Hn];
__device__ float g_Q2[NB * Hn];
__device__ float g_cq[Hn];
__device__ float g_gi[NB * 3 * Hn];
__device__ float g_gh[NB * 3 * Hn];

// ---------------- helpers -----------------------------------------------------
__device__ __forceinline__ float tanh_apx(float x) {
    float y;
    asm("tanh.approx.f32 %0, %1;" : "=f"(y) : "f"(x));
    return y;
}
__device__ __forceinline__ uint32_t smem_u32(const void* p) {
    uint32_t a;
    asm("{ .reg .u64 t; cvta.to.shared.u64 t, %1; cvt.u32.u64 %0, t; }" : "=r"(a) : "l"(p));
    return a;
}
__device__ __forceinline__ void cpa16(uint32_t s, const void* g) {
    asm volatile("cp.async.cg.shared.global [%0], [%1], 16;" :: "r"(s), "l"(g));
}
__device__ __forceinline__ void ldsm_x4u(uint32_t* r, uint32_t a) {
    asm volatile("ldmatrix.sync.aligned.m8n8.x4.shared.b16 {%0,%1,%2,%3}, [%4];"
                 : "=r"(r[0]), "=r"(r[1]), "=r"(r[2]), "=r"(r[3]) : "r"(a));
}
__device__ __forceinline__ void ldsm_x4t_u(uint32_t* r, uint32_t a) {
    asm volatile("ldmatrix.sync.aligned.m8n8.x4.trans.shared.b16 {%0,%1,%2,%3}, [%4];"
                 : "=r"(r[0]), "=r"(r[1]), "=r"(r[2]), "=r"(r[3]) : "r"(a));
}
__device__ __forceinline__ void mma_f16(float* d, const uint32_t* a, const uint32_t* b) {
    asm volatile(
        "mma.sync.aligned.m16n8k16.row.col.f32.f16.f16.f32 "
        "{%0,%1,%2,%3}, {%4,%5,%6,%7}, {%8,%9}, {%0,%1,%2,%3};"
        : "+f"(d[0]), "+f"(d[1]), "+f"(d[2]), "+f"(d[3])
        : "r"(a[0]), "r"(a[1]), "r"(a[2]), "r"(a[3]), "r"(b[0]), "r"(b[1]));
}

// ---------------- conversions --------------------------------------------------
__global__ __launch_bounds__(256) void cvt_k(const float* __restrict__ src,
                                             __half* __restrict__ dst) {
    int i = blockIdx.x * 256 + threadIdx.x;
    float4 v = ((const float4*)src)[i];
    __half2* hp = (__half2*)dst;
    hp[2 * i]     = __halves2half2(__float2half(v.x), __float2half(v.y));
    hp[2 * i + 1] = __halves2half2(__float2half(v.z), __float2half(v.w));
}
__global__ __launch_bounds__(256) void zero_k(float* __restrict__ p) {
    p[blockIdx.x * 256 + threadIdx.x] = 0.f;
}
__global__ __launch_bounds__(256) void fixup_k(const float* __restrict__ sp,
                                               const float* __restrict__ mask,
                                               float* __restrict__ out) {
    int i = blockIdx.x * 256 + threadIdx.x;
    out[i] = (mask[i] > 0.f) ? sp[i] : -1e30f;
}
// 1024x1024 fp32 transpose: dst[j][h] = src[h][j]
__global__ __launch_bounds__(256) void transpose_k(const float* __restrict__ src,
                                                   float* __restrict__ dst) {
    __shared__ float t[32][33];
    int bx = blockIdx.x * 32, by = blockIdx.y * 32;
    int lx = threadIdx.x & 31, ly = threadIdx.x >> 5;
    for (int d = 0; d < 32; d += 8)
        t[ly + d][lx] = src[(size_t)(by + ly + d) * 1024 + bx + lx];
    __syncthreads();
    for (int d = 0; d < 32; d += 8)
        dst[(size_t)(bx + ly + d) * 1024 + by + lx] = t[lx][ly + d];
}

// ---------------- 3-stage single-pass fp16 GEMM + fused score -----------------
// C(half)[M,1024] = A[M,1024] @ Bh[1024,1024] (fp16 in, fp32 accumulate).
// Optional fused partials: SP[r] += sum_{c in CTA cols} wv[c]*tanh(acc + Qv[..,c])
// CTA 128x128, K-chunk 64, 3-stage cp.async (1 sync/chunk), 8 warps, 2 CTAs/SM.
#define STG 35840
__device__ __forceinline__ void load_chunk(uint32_t st,
                                           const __half* Ah, const __half* Bh,
                                           int row0, int col0, int k0, int tid) {
#pragma unroll
    for (int j = 0; j < 4; j++) {          // A: 128 rows x 64 halves
        int s = tid + j * 256;
        int r = s >> 3, c8 = s & 7;
        uint32_t so = (uint32_t)(r * 144 + c8 * 16);
        size_t go = (size_t)(row0 + r) * 1024 + k0 + c8 * 8;
        cpa16(st + so, Ah + go);
    }
#pragma unroll
    for (int j = 0; j < 4; j++) {          // B: 64 k-rows x 128 halves
        int s = tid + j * 256;
        int r = s >> 4, c8 = s & 15;
        uint32_t so = (uint32_t)(r * 272 + c8 * 16);
        size_t go = (size_t)(k0 + r) * 1024 + col0 + c8 * 8;
        cpa16(st + 18432 + so, Bh + go);
    }
    asm volatile("cp.async.commit_group;" ::: "memory");
}

__global__ __launch_bounds__(256, 2) void mma2_k(const __half* __restrict__ Ah,
                                                 const __half* __restrict__ Bh,
                                                 __half* __restrict__ C,
                                                 const float* __restrict__ wv,
                                                 const float* __restrict__ Qv,
                                                 float* __restrict__ SP,
                                                 int fuse) {
    extern __shared__ char dsm[];
    __shared__ float part[128];
    uint32_t sb  = smem_u32(dsm);
    uint32_t sba = (sb + 1023u) & ~1023u;
    const int tid = threadIdx.x;
    const int warp = tid >> 5, lane = tid & 31;
    const int wm = warp >> 2, wn = warp & 3;
    const int row0 = blockIdx.y * 128, col0 = blockIdx.x * 128;

    if (tid < 128) part[tid] = 0.f;

    float acc[4][4][4];
#pragma unroll
    for (int i = 0; i < 4; i++)
#pragma unroll
        for (int j = 0; j < 4; j++)
#pragma unroll
            for (int v = 0; v < 4; v++) acc[i][j][v] = 0.f;

    load_chunk(sba,       Ah, Bh, row0, col0, 0,  tid);
    load_chunk(sba + STG, Ah, Bh, row0, col0, 64, tid);

    for (int c = 0; c < 16; c++) {
        if (c < 15) asm volatile("cp.async.wait_group 1;" ::: "memory");
        else        asm volatile("cp.async.wait_group 0;" ::: "memory");
        __syncthreads();
        if (c + 2 < 16)
            load_chunk(sba + ((c + 2) % 3) * STG, Ah, Bh, row0, col0, (c + 2) * 64, tid);

        const uint32_t st  = sba + (c % 3) * STG;
        const uint32_t aB  = st;
        const uint32_t bB  = st + 18432;
        const int arow = lane & 15, acol = (lane >> 4) << 3;
        const int bkrl = lane & 15, bcb = wn * 32 + ((lane >> 4) << 3);
#pragma unroll
        for (int kk = 0; kk < 64; kk += 16) {
            uint32_t ah[4][4], bh[2][4];
#pragma unroll
            for (int mi = 0; mi < 4; mi++) {
                uint32_t off = (uint32_t)((wm * 64 + mi * 16 + arow) * 144 + (kk + acol) * 2);
                ldsm_x4u(ah[mi], aB + off);
            }
#pragma unroll
            for (int ni = 0; ni < 2; ni++) {
                uint32_t off = (uint32_t)((kk + bkrl) * 272 + (bcb + ni * 16) * 2);
                ldsm_x4t_u(bh[ni], bB + off);
            }
#pragma unroll
            for (int mi = 0; mi < 4; mi++)
#pragma unroll
                for (int nj = 0; nj < 4; nj++) {
                    int ni = nj >> 1, p = (nj & 1) * 2;
                    mma_f16(acc[mi][nj], ah[mi], &bh[ni][p]);
                }
        }
    }

    const int rbase = row0 + wm * 64, cbase = col0 + wn * 32;
    const int lr = lane >> 2, lc = (lane & 3) * 2;
#pragma unroll
    for (int mi = 0; mi < 4; mi++)
#pragma unroll
        for (int nj = 0; nj < 4; nj++) {
            int rr = rbase + mi * 16 + lr;
            int cc = cbase + nj * 8 + lc;
            *(__half2*)&C[(size_t)rr * 1024 + cc] =
                __floats2half2_rn(acc[mi][nj][0], acc[mi][nj][1]);
            *(__half2*)&C[(size_t)(rr + 8) * 1024 + cc] =
                __floats2half2_rn(acc[mi][nj][2], acc[mi][nj][3]);
        }

    if (fuse) {
        const float* q = Qv + ((size_t)(row0 >> 10) << 10);
        __syncthreads();
#pragma unroll
        for (int mi = 0; mi < 4; mi++) {
            float sA = 0.f, sB = 0.f;
#pragma unroll
            for (int nj = 0; nj < 4; nj++) {
                int cc = cbase + nj * 8 + lc;
                float w0 = wv[cc], w1 = wv[cc + 1];
                float q0 = q[cc],  q1v = q[cc + 1];
                sA += w0 * tanh_apx(acc[mi][nj][0] + q0) + w1 * tanh_apx(acc[mi][nj][1] + q1v);
                sB += w0 * tanh_apx(acc[mi][nj][2] + q0) + w1 * tanh_apx(acc[mi][nj][3] + q1v);
            }
            sA += __shfl_xor_sync(0xffffffffu, sA, 1);
            sA += __shfl_xor_sync(0xffffffffu, sA, 2);
            sB += __shfl_xor_sync(0xffffffffu, sB, 1);
            sB += __shfl_xor_sync(0xffffffffu, sB, 2);
            if ((lane & 3) == 0) {
                atomicAdd(&part[wm * 64 + mi * 16 + lr], sA);
                atomicAdd(&part[wm * 64 + mi * 16 + lr + 8], sB);
            }
        }
        __syncthreads();
        if (tid < 128) atomicAdd(&SP[row0 + tid], part[tid]);
    }
}

// ---------------- score over fp16 PK: warp-per-row -----------------------------
__global__ __launch_bounds__(256) void score_h_k(const __half* __restrict__ C,
                                                 const float* __restrict__ qterm,
                                                 const float* __restrict__ wv,
                                                 const float* __restrict__ mask,
                                                 float* __restrict__ outs, int per_row) {
    const int warp = threadIdx.x >> 5, lane = threadIdx.x & 31;
    const int r = blockIdx.x * 8 + warp;
    const __half* crow = C + (size_t)r * 1024;
    const float* q = per_row ? (qterm + (size_t)(r >> 10) * 1024) : qterm;
    float acc = 0.f;
#pragma unroll
    for (int i = 0; i < 4; i++) {
        int c0 = (lane + i * 32) * 8;
        uint4 v = *(const uint4*)(crow + c0);
        const __half2* h = (const __half2*)&v;
#pragma unroll
        for (int j = 0; j < 4; j++) {
            float2 f = __half22float2(h[j]);
            int c = c0 + j * 2;
            acc += wv[c]     * tanh_apx(f.x + q[c]);
            acc += wv[c + 1] * tanh_apx(f.y + q[c + 1]);
        }
    }
#pragma unroll
    for (int o = 16; o; o >>= 1) acc += __shfl_xor_sync(0xffffffffu, acc, o);
    if (lane == 0) outs[r] = (mask[r] > 0.f) ? acc : -1e30f;
}

__global__ __launch_bounds__(256) void softmax_k(const float* __restrict__ s,
                                                 float* __restrict__ alpha, int T) {
    const int b = blockIdx.x, tid = threadIdx.x;
    __shared__ float red[8];
    __shared__ float sh;
    const float* sb = s + (size_t)b * T;
    float mx = -3.0e38f;
    for (int t = tid; t < T; t += 256) mx = fmaxf(mx, sb[t]);
    for (int o = 16; o; o >>= 1) mx = fmaxf(mx, __shfl_xor_sync(0xffffffffu, mx, o));
    if ((tid & 31) == 0) red[tid >> 5] = mx;
    __syncthreads();
    if (tid == 0) {
        float v = red[0];
#pragma unroll
        for (int w = 1; w < 8; w++) v = fmaxf(v, red[w]);
        sh = v;
    }
    __syncthreads();
    mx = sh;
    float sum = 0.f;
    for (int t = tid; t < T; t += 256) {
        float e = expf(sb[t] - mx);
        alpha[(size_t)b * T + t] = e;
        sum += e;
    }
    for (int o = 16; o; o >>= 1) sum += __shfl_xor_sync(0xffffffffu, sum, o);
    __syncthreads();
    if ((tid & 31) == 0) red[tid >> 5] = sum;
    __syncthreads();
    if (tid == 0) {
        float v = 0.f;
#pragma unroll
        for (int w = 0; w < 8; w++) v += red[w];
        sh = 1.f / v;
    }
    __syncthreads();
    float inv = sh;
    for (int t = tid; t < T; t += 256) alpha[(size_t)b * T + t] *= inv;
}

// fp32 key pool (question)
__global__ __launch_bounds__(256) void pool_k(const float* __restrict__ key,
                                              const float* __restrict__ alpha,
                                              float* __restrict__ out, int T) {
    const int b = blockIdx.x;
    const int h = blockIdx.y * 256 + threadIdx.x;
    const float* kb = key + (size_t)b * T * 1024 + h;
    const float* ab = alpha + (size_t)b * T;
    float a0 = 0.f, a1 = 0.f, a2 = 0.f, a3 = 0.f;
    for (int t = 0; t < T; t += 4) {
        a0 += ab[t + 0] * kb[(size_t)(t + 0) * 1024];
        a1 += ab[t + 1] * kb[(size_t)(t + 1) * 1024];
        a2 += ab[t + 2] * kb[(size_t)(t + 2) * 1024];
        a3 += ab[t + 3] * kb[(size_t)(t + 3) * 1024];
    }
    out[(size_t)b * 1024 + h] = (a0 + a1) + (a2 + a3);
}

// fp16 key pool (passage)
__global__ __launch_bounds__(256) void pool_h_k(const __half* __restrict__ key,
                                                const float* __restrict__ alpha,
                                                float* __restrict__ out, int T) {
    const int b = blockIdx.x;
    const int h = blockIdx.y * 256 + threadIdx.x;
    const __half* kb = key + (size_t)b * T * 1024 + h;
    const float* ab = alpha + (size_t)b * T;
    float a0 = 0.f, a1 = 0.f, a2 = 0.f, a3 = 0.f;
    for (int t = 0; t < T; t += 4) {
        a0 += ab[t + 0] * __half2float(kb[(size_t)(t + 0) * 1024]);
        a1 += ab[t + 1] * __half2float(kb[(size_t)(t + 1) * 1024]);
        a2 += ab[t + 2] * __half2float(kb[(size_t)(t + 2) * 1024]);
        a3 += ab[t + 3] * __half2float(kb[(size_t)(t + 3) * 1024]);
    }
    out[(size_t)b * 1024 + h] = (a0 + a1) + (a2 + a3);
}

// small x@W for [1,H] vectors (pcq only)
__global__ __launch_bounds__(256) void xw_k(const float* __restrict__ x,
                                            const float* __restrict__ W,
                                            float* __restrict__ out) {
    const int b = blockIdx.y;
    const int j = blockIdx.x * 256 + threadIdx.x;
    __shared__ float xs[1024];
    for (int i = threadIdx.x; i < 1024; i += 256) xs[i] = x[(size_t)b * 1024 + i];
    __syncthreads();
    const float* Wc = W + j;
    float a0 = 0.f, a1 = 0.f, a2 = 0.f, a3 = 0.f;
    for (int h = 0; h < 1024; h += 4) {
        a0 += xs[h + 0] * Wc[(size_t)(h + 0) * 1024];
        a1 += xs[h + 1] * Wc[(size_t)(h + 1) * 1024];
        a2 += xs[h + 2] * Wc[(size_t)(h + 2) * 1024];
        a3 += xs[h + 3] * Wc[(size_t)(h + 3) * 1024];
    }
    out[(size_t)b * 1024 + j] = (a0 + a1) + (a2 + a3);
}

// batched out[b][j] = bias[j] + dot(x[b], W[j][:]) — W read ONCE (regs), x staged in smem
__global__ __launch_bounds__(256) void rowdotB_k(const float* __restrict__ x,
                                                 const float* __restrict__ W,
                                                 const float* __restrict__ bias,
                                                 float* __restrict__ out, int N) {
    __shared__ float xs[1024];
    const int warp = threadIdx.x >> 5, lane = threadIdx.x & 31;
    const int j = blockIdx.x * 8 + warp;
    float Wreg[32];
    const float* wr = W + (size_t)j * 1024;
#pragma unroll
    for (int i = 0; i < 32; i++) Wreg[i] = wr[lane + i * 32];
    const float bj = bias[j];
    for (int b = 0; b < 64; b++) {
        ((float4*)xs)[threadIdx.x] = ((const float4*)(x + (size_t)b * 1024))[threadIdx.x];
        __syncthreads();
        float acc = 0.f;
#pragma unroll
        for (int i = 0; i < 32; i++) acc += xs[lane + i * 32] * Wreg[i];
#pragma unroll
        for (int o = 16; o; o >>= 1) acc += __shfl_xor_sync(0xffffffffu, acc, o);
        if (!lane) out[(size_t)b * N + j] = acc + bj;
        __syncthreads();
    }
}

__global__ __launch_bounds__(256) void gru_k() {
    const int i = blockIdx.x * 256 + threadIdx.x;
    const int b = i >> 10, h = i & 1023;
    const float* gi = g_gi + (size_t)b * 3072;
    const float* gh = g_gh + (size_t)b * 3072;
    float r = 1.f / (1.f + expf(-(gi[h] + gh[h])));
    float z = 1.f / (1.f + expf(-(gi[1024 + h] + gh[1024 + h])));
    float n = tanhf(gi[2048 + h] + r * gh[2048 + h]);
    g_gout[i] = (1.f - z) * n + z * g_hidden[i];
}

// ---------------- launch ------------------------------------------------------
extern "C" void kernel_launch(void* const* d_in, const int* in_sizes, int n_in,
                              void* d_out, int out_size) {
    const float* question = (const float*)d_in[0];
    const float* qmask    = (const float*)d_in[1];
    const float* passage  = (const float*)d_in[2];
    const float* pmask    = (const float*)d_in[3];
    const float* Vq       = (const float*)d_in[4];
    const float* Wk_q     = (const float*)d_in[5];
    const float* Wq_q     = (const float*)d_in[6];
    const float* w_q      = (const float*)d_in[7];
    const float* Wk_p     = (const float*)d_in[8];
    const float* Wq_p     = (const float*)d_in[9];
    const float* w_p      = (const float*)d_in[10];
    const float* W_ih     = (const float*)d_in[11];
    const float* W_hh     = (const float*)d_in[12];
    const float* b_ih     = (const float*)d_in[13];
    const float* b_hh     = (const float*)d_in[14];
    float* out = (float*)d_out;

    float *psp, *psq, *palpha, *phid, *pinp, *pgout, *pQ1, *pQ2, *pcq, *pgi, *pgh;
    float *pWqpT, *pzb;
    __half *pPKh, *pAh, *pQh, *pBqh, *pBph;
    cudaGetSymbolAddress((void**)&pPKh,  g_PKh);
    cudaGetSymbolAddress((void**)&psp,   g_sp);
    cudaGetSymbolAddress((void**)&psq,   g_sq);
    cudaGetSymbolAddress((void**)&palpha,g_alpha);
    cudaGetSymbolAddress((void**)&phid,  g_hidden);
    cudaGetSymbolAddress((void**)&pinp,  g_inputs);
    cudaGetSymbolAddress((void**)&pgout, g_gout);
    cudaGetSymbolAddress((void**)&pQ1,   g_Q1);
    cudaGetSymbolAddress((void**)&pQ2,   g_Q2);
    cudaGetSymbolAddress((void**)&pcq,   g_cq);
    cudaGetSymbolAddress((void**)&pgi,   g_gi);
    cudaGetSymbolAddress((void**)&pgh,   g_gh);
    cudaGetSymbolAddress((void**)&pAh,   g_Ah);
    cudaGetSymbolAddress((void**)&pQh,   g_Qh);
    cudaGetSymbolAddress((void**)&pBqh,  g_Bqh);
    cudaGetSymbolAddress((void**)&pBph,  g_Bph);
    cudaGetSymbolAddress((void**)&pWqpT, g_WqpT);
    cudaGetSymbolAddress((void**)&pzb,   g_zb);

    cudaFuncSetAttribute(mma2_k, cudaFuncAttributeMaxDynamicSharedMemorySize, 3 * STG + 1024);

    // conversions + weight prep
    cvt_k<<<1024, 256>>>(Wk_q, pBqh);
    cvt_k<<<1024, 256>>>(Wk_p, pBph);
    cvt_k<<<4096, 256>>>(question, pQh);
    cvt_k<<<65536, 256>>>(passage, pAh);
    transpose_k<<<dim3(32, 32), 256>>>(Wq_p, pWqpT);
    zero_k<<<4, 256>>>(pzb);

    // question branch
    xw_k<<<dim3(4, 1), 256>>>(Vq, Wq_q, pcq);
    mma2_k<<<dim3(8, 32), 256, 3 * STG + 1024>>>(pQh, pBqh, pPKh, w_q, pcq, psp, 0);
    score_h_k<<<512, 256>>>(pPKh, pcq, w_q, qmask, psq, 0);
    softmax_k<<<64, 256>>>(psq, palpha, 64);
    pool_k<<<dim3(64, 4), 256>>>(question, palpha, phid, 64);
    rowdotB_k<<<128, 256>>>(phid, pWqpT, pzb, pQ1, 1024);          // Q1 = hidden @ Wq_p
    rowdotB_k<<<384, 256>>>(phid, W_hh, b_hh, pgh, 3072);          // gh (needs only hidden)

    // passage GEMM with fused begin-score (computed once)
    zero_k<<<256, 256>>>(psp);
    mma2_k<<<dim3(8, 512), 256, 3 * STG + 1024>>>(pAh, pBph, pPKh, w_p, pQ1, psp, 1);
    fixup_k<<<256, 256>>>(psp, pmask, out);

    // softmax + pool (fp16 passage) -> GRU input
    softmax_k<<<64, 256>>>(out, palpha, 1024);
    pool_h_k<<<dim3(64, 4), 256>>>(pAh, palpha, pinp, 1024);

    // GRU + end logits
    rowdotB_k<<<384, 256>>>(pinp, W_ih, b_ih, pgi, 3072);
    gru_k<<<256, 256>>>();
    rowdotB_k<<<128, 256>>>(pgout, pWqpT, pzb, pQ2, 1024);         // Q2 = gru_out @ Wq_p
    score_h_k<<<8192, 256>>>(pPKh, pQ2, w_p, pmask, out + 65536, 1);
}

// round 12
// speedup vs baseline: 2.1670x; 1.0350x over previous
#include <cuda_runtime.h>
#include <cuda_fp16.h>
#include <math.h>
#include <stdint.h>

// Shapes (fixed): B=64, TQ=64, TP=1024, H=A=1024
#define NB  64
#define Hn  1024

// ---------------- scratch (__device__ globals) --------------------------------
__device__ __half g_PKh[67108864];               // 128MB logits-GEMM output (fp16)
__device__ __half g_Ah[67108864];                // passage fp16
__device__ __half g_Qh[4194304];                 // question fp16
__device__ __half g_Bqh[1048576];                // Wk_q fp16 [k][n]
__device__ __half g_Bph[1048576];                // Wk_p fp16 [k][n]
__device__ float g_WqpT[1048576];                // Wq_p transposed [j][h]
__device__ float g_zb[1024];                     // zero bias
__device__ float g_sp[65536];                    // fused begin-score partials
__device__ float g_sq[NB * 64];
__device__ float g_alpha[NB * 1024];
__device__ float g_hidden[NB * Hn];
__device__ float g_inputs[NB * Hn];
__device__ float g_gout[NB * Hn];
__device__ float g_Q1[NB * Hn];
__device__ float g_Q2[NB * Hn];
__device__ float g_cq[Hn];
__device__ float g_gi[NB * 3 * Hn];
__device__ float g_gh[NB * 3 * Hn];

// ---------------- helpers -----------------------------------------------------
__device__ __forceinline__ float tanh_apx(float x) {
    float y;
    asm("tanh.approx.f32 %0, %1;" : "=f"(y) : "f"(x));
    return y;
}
__device__ __forceinline__ uint32_t smem_u32(const void* p) {
    uint32_t a;
    asm("{ .reg .u64 t; cvta.to.shared.u64 t, %1; cvt.u32.u64 %0, t; }" : "=r"(a) : "l"(p));
    return a;
}
__device__ __forceinline__ void cpa16(uint32_t s, const void* g) {
    asm volatile("cp.async.cg.shared.global [%0], [%1], 16;" :: "r"(s), "l"(g));
}
__device__ __forceinline__ void ldsm_x4u(uint32_t* r, uint32_t a) {
    asm volatile("ldmatrix.sync.aligned.m8n8.x4.shared.b16 {%0,%1,%2,%3}, [%4];"
                 : "=r"(r[0]), "=r"(r[1]), "=r"(r[2]), "=r"(r[3]) : "r"(a));
}
__device__ __forceinline__ void ldsm_x4t_u(uint32_t* r, uint32_t a) {
    asm volatile("ldmatrix.sync.aligned.m8n8.x4.trans.shared.b16 {%0,%1,%2,%3}, [%4];"
                 : "=r"(r[0]), "=r"(r[1]), "=r"(r[2]), "=r"(r[3]) : "r"(a));
}
__device__ __forceinline__ void mma_f16(float* d, const uint32_t* a, const uint32_t* b) {
    asm volatile(
        "mma.sync.aligned.m16n8k16.row.col.f32.f16.f16.f32 "
        "{%0,%1,%2,%3}, {%4,%5,%6,%7}, {%8,%9}, {%0,%1,%2,%3};"
        : "+f"(d[0]), "+f"(d[1]), "+f"(d[2]), "+f"(d[3])
        : "r"(a[0]), "r"(a[1]), "r"(a[2]), "r"(a[3]), "r"(b[0]), "r"(b[1]));
}

// ---------------- conversions --------------------------------------------------
__global__ __launch_bounds__(256) void cvt_k(const float* __restrict__ src,
                                             __half* __restrict__ dst) {
    int i = blockIdx.x * 256 + threadIdx.x;
    float4 v = ((const float4*)src)[i];
    __half2* hp = (__half2*)dst;
    hp[2 * i]     = __halves2half2(__float2half(v.x), __float2half(v.y));
    hp[2 * i + 1] = __halves2half2(__float2half(v.z), __float2half(v.w));
}
// merged convert: [0,1024)->Wk_q, [1024,2048)->Wk_p, [2048,6144)->question
__global__ __launch_bounds__(256) void cvt3_k(const float* __restrict__ s0, __half* __restrict__ d0,
                                              const float* __restrict__ s1, __half* __restrict__ d1,
                                              const float* __restrict__ s2, __half* __restrict__ d2) {
    int blk = blockIdx.x;
    const float* src; __half* dst; int base;
    if (blk < 1024)      { src = s0; dst = d0; base = blk; }
    else if (blk < 2048) { src = s1; dst = d1; base = blk - 1024; }
    else                 { src = s2; dst = d2; base = blk - 2048; }
    int i = base * 256 + threadIdx.x;
    float4 v = ((const float4*)src)[i];
    __half2* hp = (__half2*)dst;
    hp[2 * i]     = __halves2half2(__float2half(v.x), __float2half(v.y));
    hp[2 * i + 1] = __halves2half2(__float2half(v.z), __float2half(v.w));
}
__global__ __launch_bounds__(256) void zero_k(float* __restrict__ p) {
    p[blockIdx.x * 256 + threadIdx.x] = 0.f;
}
// 1024x1024 fp32 transpose: dst[j][h] = src[h][j]
__global__ __launch_bounds__(256) void transpose_k(const float* __restrict__ src,
                                                   float* __restrict__ dst) {
    __shared__ float t[32][33];
    int bx = blockIdx.x * 32, by = blockIdx.y * 32;
    int lx = threadIdx.x & 31, ly = threadIdx.x >> 5;
    for (int d = 0; d < 32; d += 8)
        t[ly + d][lx] = src[(size_t)(by + ly + d) * 1024 + bx + lx];
    __syncthreads();
    for (int d = 0; d < 32; d += 8)
        dst[(size_t)(bx + ly + d) * 1024 + by + lx] = t[lx][ly + d];
}

// ---------------- 3-stage single-pass fp16 GEMM + fused score -----------------
#define STG 35840
__device__ __forceinline__ void load_chunk(uint32_t st,
                                           const __half* Ah, const __half* Bh,
                                           int row0, int col0, int k0, int tid) {
#pragma unroll
    for (int j = 0; j < 4; j++) {          // A: 128 rows x 64 halves
        int s = tid + j * 256;
        int r = s >> 3, c8 = s & 7;
        uint32_t so = (uint32_t)(r * 144 + c8 * 16);
        size_t go = (size_t)(row0 + r) * 1024 + k0 + c8 * 8;
        cpa16(st + so, Ah + go);
    }
#pragma unroll
    for (int j = 0; j < 4; j++) {          // B: 64 k-rows x 128 halves
        int s = tid + j * 256;
        int r = s >> 4, c8 = s & 15;
        uint32_t so = (uint32_t)(r * 272 + c8 * 16);
        size_t go = (size_t)(k0 + r) * 1024 + col0 + c8 * 8;
        cpa16(st + 18432 + so, Bh + go);
    }
    asm volatile("cp.async.commit_group;" ::: "memory");
}

__global__ __launch_bounds__(256, 2) void mma2_k(const __half* __restrict__ Ah,
                                                 const __half* __restrict__ Bh,
                                                 __half* __restrict__ C,
                                                 const float* __restrict__ wv,
                                                 const float* __restrict__ Qv,
                                                 float* __restrict__ SP,
                                                 int fuse) {
    extern __shared__ char dsm[];
    __shared__ float part[128];
    uint32_t sb  = smem_u32(dsm);
    uint32_t sba = (sb + 1023u) & ~1023u;
    const int tid = threadIdx.x;
    const int warp = tid >> 5, lane = tid & 31;
    const int wm = warp >> 2, wn = warp & 3;
    const int row0 = blockIdx.y * 128, col0 = blockIdx.x * 128;

    if (tid < 128) part[tid] = 0.f;

    float acc[4][4][4];
#pragma unroll
    for (int i = 0; i < 4; i++)
#pragma unroll
        for (int j = 0; j < 4; j++)
#pragma unroll
            for (int v = 0; v < 4; v++) acc[i][j][v] = 0.f;

    load_chunk(sba,       Ah, Bh, row0, col0, 0,  tid);
    load_chunk(sba + STG, Ah, Bh, row0, col0, 64, tid);

    for (int c = 0; c < 16; c++) {
        if (c < 15) asm volatile("cp.async.wait_group 1;" ::: "memory");
        else        asm volatile("cp.async.wait_group 0;" ::: "memory");
        __syncthreads();
        if (c + 2 < 16)
            load_chunk(sba + ((c + 2) % 3) * STG, Ah, Bh, row0, col0, (c + 2) * 64, tid);

        const uint32_t st  = sba + (c % 3) * STG;
        const uint32_t aB  = st;
        const uint32_t bB  = st + 18432;
        const int arow = lane & 15, acol = (lane >> 4) << 3;
        const int bkrl = lane & 15, bcb = wn * 32 + ((lane >> 4) << 3);
#pragma unroll
        for (int kk = 0; kk < 64; kk += 16) {
            uint32_t ah[4][4], bh[2][4];
#pragma unroll
            for (int mi = 0; mi < 4; mi++) {
                uint32_t off = (uint32_t)((wm * 64 + mi * 16 + arow) * 144 + (kk + acol) * 2);
                ldsm_x4u(ah[mi], aB + off);
            }
#pragma unroll
            for (int ni = 0; ni < 2; ni++) {
                uint32_t off = (uint32_t)((kk + bkrl) * 272 + (bcb + ni * 16) * 2);
                ldsm_x4t_u(bh[ni], bB + off);
            }
#pragma unroll
            for (int mi = 0; mi < 4; mi++)
#pragma unroll
                for (int nj = 0; nj < 4; nj++) {
                    int ni = nj >> 1, p = (nj & 1) * 2;
                    mma_f16(acc[mi][nj], ah[mi], &bh[ni][p]);
                }
        }
    }

    const int rbase = row0 + wm * 64, cbase = col0 + wn * 32;
    const int lr = lane >> 2, lc = (lane & 3) * 2;
#pragma unroll
    for (int mi = 0; mi < 4; mi++)
#pragma unroll
        for (int nj = 0; nj < 4; nj++) {
            int rr = rbase + mi * 16 + lr;
            int cc = cbase + nj * 8 + lc;
            *(__half2*)&C[(size_t)rr * 1024 + cc] =
                __floats2half2_rn(acc[mi][nj][0], acc[mi][nj][1]);
            *(__half2*)&C[(size_t)(rr + 8) * 1024 + cc] =
                __floats2half2_rn(acc[mi][nj][2], acc[mi][nj][3]);
        }

    if (fuse) {
        const float* q = Qv + ((size_t)(row0 >> 10) << 10);
        __syncthreads();
#pragma unroll
        for (int mi = 0; mi < 4; mi++) {
            float sA = 0.f, sB = 0.f;
#pragma unroll
            for (int nj = 0; nj < 4; nj++) {
                int cc = cbase + nj * 8 + lc;
                float w0 = wv[cc], w1 = wv[cc + 1];
                float q0 = q[cc],  q1v = q[cc + 1];
                sA += w0 * tanh_apx(acc[mi][nj][0] + q0) + w1 * tanh_apx(acc[mi][nj][1] + q1v);
                sB += w0 * tanh_apx(acc[mi][nj][2] + q0) + w1 * tanh_apx(acc[mi][nj][3] + q1v);
            }
            sA += __shfl_xor_sync(0xffffffffu, sA, 1);
            sA += __shfl_xor_sync(0xffffffffu, sA, 2);
            sB += __shfl_xor_sync(0xffffffffu, sB, 1);
            sB += __shfl_xor_sync(0xffffffffu, sB, 2);
            if ((lane & 3) == 0) {
                atomicAdd(&part[wm * 64 + mi * 16 + lr], sA);
                atomicAdd(&part[wm * 64 + mi * 16 + lr + 8], sB);
            }
        }
        __syncthreads();
        if (tid < 128) atomicAdd(&SP[row0 + tid], part[tid]);
    }
}

// ---------------- score over fp16 PK: warp-per-row -----------------------------
__global__ __launch_bounds__(256) void score_h_k(const __half* __restrict__ C,
                                                 const float* __restrict__ qterm,
                                                 const float* __restrict__ wv,
                                                 const float* __restrict__ mask,
                                                 float* __restrict__ outs, int per_row) {
    const int warp = threadIdx.x >> 5, lane = threadIdx.x & 31;
    const int r = blockIdx.x * 8 + warp;
    const __half* crow = C + (size_t)r * 1024;
    const float* q = per_row ? (qterm + (size_t)(r >> 10) * 1024) : qterm;
    float acc = 0.f;
#pragma unroll
    for (int i = 0; i < 4; i++) {
        int c0 = (lane + i * 32) * 8;
        uint4 v = *(const uint4*)(crow + c0);
        const __half2* h = (const __half2*)&v;
#pragma unroll
        for (int j = 0; j < 4; j++) {
            float2 f = __half22float2(h[j]);
            int c = c0 + j * 2;
            acc += wv[c]     * tanh_apx(f.x + q[c]);
            acc += wv[c + 1] * tanh_apx(f.y + q[c + 1]);
        }
    }
#pragma unroll
    for (int o = 16; o; o >>= 1) acc += __shfl_xor_sync(0xffffffffu, acc, o);
    if (lane == 0) outs[r] = (mask[r] > 0.f) ? acc : -1e30f;
}

// plain masked softmax (question branch)
__global__ __launch_bounds__(256) void softmax_k(const float* __restrict__ s,
                                                 float* __restrict__ alpha, int T) {
    const int b = blockIdx.x, tid = threadIdx.x;
    __shared__ float red[8];
    __shared__ float sh;
    const float* sb = s + (size_t)b * T;
    float mx = -3.0e38f;
    for (int t = tid; t < T; t += 256) mx = fmaxf(mx, sb[t]);
    for (int o = 16; o; o >>= 1) mx = fmaxf(mx, __shfl_xor_sync(0xffffffffu, mx, o));
    if ((tid & 31) == 0) red[tid >> 5] = mx;
    __syncthreads();
    if (tid == 0) {
        float v = red[0];
#pragma unroll
        for (int w = 1; w < 8; w++) v = fmaxf(v, red[w]);
        sh = v;
    }
    __syncthreads();
    mx = sh;
    float sum = 0.f;
    for (int t = tid; t < T; t += 256) {
        float e = expf(sb[t] - mx);
        alpha[(size_t)b * T + t] = e;
        sum += e;
    }
    for (int o = 16; o; o >>= 1) sum += __shfl_xor_sync(0xffffffffu, sum, o);
    __syncthreads();
    if ((tid & 31) == 0) red[tid >> 5] = sum;
    __syncthreads();
    if (tid == 0) {
        float v = 0.f;
#pragma unroll
        for (int w = 0; w < 8; w++) v += red[w];
        sh = 1.f / v;
    }
    __syncthreads();
    float inv = sh;
    for (int t = tid; t < T; t += 256) alpha[(size_t)b * T + t] *= inv;
}

// fused: masked logits (out) + softmax alpha from raw partials (passage branch)
__global__ __launch_bounds__(256) void softmaxM_k(const float* __restrict__ sp,
                                                  const float* __restrict__ mask,
                                                  float* __restrict__ out,
                                                  float* __restrict__ alpha) {
    const int b = blockIdx.x, tid = threadIdx.x;
    __shared__ float red[8];
    __shared__ float sh;
    float v4[4];
    float mx = -3.0e38f;
#pragma unroll
    for (int i = 0; i < 4; i++) {
        int t = tid + i * 256;
        float s = (mask[b * 1024 + t] > 0.f) ? sp[b * 1024 + t] : -1e30f;
        out[b * 1024 + t] = s;
        v4[i] = s;
        mx = fmaxf(mx, s);
    }
    for (int o = 16; o; o >>= 1) mx = fmaxf(mx, __shfl_xor_sync(0xffffffffu, mx, o));
    if ((tid & 31) == 0) red[tid >> 5] = mx;
    __syncthreads();
    if (tid == 0) {
        float v = red[0];
#pragma unroll
        for (int w = 1; w < 8; w++) v = fmaxf(v, red[w]);
        sh = v;
    }
    __syncthreads();
    mx = sh;
    float sum = 0.f;
#pragma unroll
    for (int i = 0; i < 4; i++) {
        v4[i] = expf(v4[i] - mx);
        sum += v4[i];
    }
    for (int o = 16; o; o >>= 1) sum += __shfl_xor_sync(0xffffffffu, sum, o);
    __syncthreads();
    if ((tid & 31) == 0) red[tid >> 5] = sum;
    __syncthreads();
    if (tid == 0) {
        float v = 0.f;
#pragma unroll
        for (int w = 0; w < 8; w++) v += red[w];
        sh = 1.f / v;
    }
    __syncthreads();
    float inv = sh;
#pragma unroll
    for (int i = 0; i < 4; i++)
        alpha[b * 1024 + tid + i * 256] = v4[i] * inv;
}

// fp32 key pool (question)
__global__ __launch_bounds__(256) void pool_k(const float* __restrict__ key,
                                              const float* __restrict__ alpha,
                                              float* __restrict__ out, int T) {
    const int b = blockIdx.x;
    const int h = blockIdx.y * 256 + threadIdx.x;
    const float* kb = key + (size_t)b * T * 1024 + h;
    const float* ab = alpha + (size_t)b * T;
    float a0 = 0.f, a1 = 0.f, a2 = 0.f, a3 = 0.f;
    for (int t = 0; t < T; t += 4) {
        a0 += ab[t + 0] * kb[(size_t)(t + 0) * 1024];
        a1 += ab[t + 1] * kb[(size_t)(t + 1) * 1024];
        a2 += ab[t + 2] * kb[(size_t)(t + 2) * 1024];
        a3 += ab[t + 3] * kb[(size_t)(t + 3) * 1024];
    }
    out[(size_t)b * 1024 + h] = (a0 + a1) + (a2 + a3);
}

// fp16 key pool (passage)
__global__ __launch_bounds__(256) void pool_h_k(const __half* __restrict__ key,
                                                const float* __restrict__ alpha,
                                                float* __restrict__ out, int T) {
    const int b = blockIdx.x;
    const int h = blockIdx.y * 256 + threadIdx.x;
    const __half* kb = key + (size_t)b * T * 1024 + h;
    const float* ab = alpha + (size_t)b * T;
    float a0 = 0.f, a1 = 0.f, a2 = 0.f, a3 = 0.f;
    for (int t = 0; t < T; t += 4) {
        a0 += ab[t + 0] * __half2float(kb[(size_t)(t + 0) * 1024]);
        a1 += ab[t + 1] * __half2float(kb[(size_t)(t + 1) * 1024]);
        a2 += ab[t + 2] * __half2float(kb[(size_t)(t + 2) * 1024]);
        a3 += ab[t + 3] * __half2float(kb[(size_t)(t + 3) * 1024]);
    }
    out[(size_t)b * 1024 + h] = (a0 + a1) + (a2 + a3);
}

// small x@W for [1,H] vectors (pcq only)
__global__ __launch_bounds__(256) void xw_k(const float* __restrict__ x,
                                            const float* __restrict__ W,
                                            float* __restrict__ out) {
    const int b = blockIdx.y;
    const int j = blockIdx.x * 256 + threadIdx.x;
    __shared__ float xs[1024];
    for (int i = threadIdx.x; i < 1024; i += 256) xs[i] = x[(size_t)b * 1024 + i];
    __syncthreads();
    const float* Wc = W + j;
    float a0 = 0.f, a1 = 0.f, a2 = 0.f, a3 = 0.f;
    for (int h = 0; h < 1024; h += 4) {
        a0 += xs[h + 0] * Wc[(size_t)(h + 0) * 1024];
        a1 += xs[h + 1] * Wc[(size_t)(h + 1) * 1024];
        a2 += xs[h + 2] * Wc[(size_t)(h + 2) * 1024];
        a3 += xs[h + 3] * Wc[(size_t)(h + 3) * 1024];
    }
    out[(size_t)b * 1024 + j] = (a0 + a1) + (a2 + a3);
}

// batched out[b][j] = bias[j] + dot(x[b], W[j][:]) — W in regs (read once);
// x processed in 8-row chunks to amortize load latency.
__global__ __launch_bounds__(256) void rowdotB_k(const float* __restrict__ x,
                                                 const float* __restrict__ W,
                                                 const float* __restrict__ bias,
                                                 float* __restrict__ out, int N) {
    __shared__ float xs[8][1024];
    const int warp = threadIdx.x >> 5, lane = threadIdx.x & 31;
    const int j = blockIdx.x * 8 + warp;
    float Wreg[32];
    const float* wr = W + (size_t)j * 1024;
#pragma unroll
    for (int i = 0; i < 32; i++) Wreg[i] = wr[lane + i * 32];
    const float bj = bias[j];
    for (int bb = 0; bb < 8; bb++) {
        __syncthreads();
#pragma unroll
        for (int jj = 0; jj < 8; jj++) {
            int f = threadIdx.x + jj * 256;        // 2048 float4 = 8 rows x 1024 f
            int row = f >> 8, c4 = f & 255;
            ((float4*)&xs[row][0])[c4] =
                ((const float4*)(x + (size_t)(bb * 8 + row) * 1024))[c4];
        }
        __syncthreads();
#pragma unroll
        for (int r = 0; r < 8; r++) {
            float acc = 0.f;
#pragma unroll
            for (int i = 0; i < 32; i++) acc += xs[r][lane + i * 32] * Wreg[i];
#pragma unroll
            for (int o = 16; o; o >>= 1) acc += __shfl_xor_sync(0xffffffffu, acc, o);
            if (!lane) out[(size_t)(bb * 8 + r) * N + j] = acc + bj;
        }
    }
}

__global__ __launch_bounds__(256) void gru_k() {
    const int i = blockIdx.x * 256 + threadIdx.x;
    const int b = i >> 10, h = i & 1023;
    const float* gi = g_gi + (size_t)b * 3072;
    const float* gh = g_gh + (size_t)b * 3072;
    float r = 1.f / (1.f + expf(-(gi[h] + gh[h])));
    float z = 1.f / (1.f + expf(-(gi[1024 + h] + gh[1024 + h])));
    float n = tanhf(gi[2048 + h] + r * gh[2048 + h]);
    g_gout[i] = (1.f - z) * n + z * g_hidden[i];
}

// ---------------- launch ------------------------------------------------------
extern "C" void kernel_launch(void* const* d_in, const int* in_sizes, int n_in,
                              void* d_out, int out_size) {
    const float* question = (const float*)d_in[0];
    const float* qmask    = (const float*)d_in[1];
    const float* passage  = (const float*)d_in[2];
    const float* pmask    = (const float*)d_in[3];
    const float* Vq       = (const float*)d_in[4];
    const float* Wk_q     = (const float*)d_in[5];
    const float* Wq_q     = (const float*)d_in[6];
    const float* w_q      = (const float*)d_in[7];
    const float* Wk_p     = (const float*)d_in[8];
    const float* Wq_p     = (const float*)d_in[9];
    const float* w_p      = (const float*)d_in[10];
    const float* W_ih     = (const float*)d_in[11];
    const float* W_hh     = (const float*)d_in[12];
    const float* b_ih     = (const float*)d_in[13];
    const float* b_hh     = (const float*)d_in[14];
    float* out = (float*)d_out;

    float *psp, *psq, *palpha, *phid, *pinp, *pgout, *pQ1, *pQ2, *pcq, *pgi, *pgh;
    float *pWqpT, *pzb;
    __half *pPKh, *pAh, *pQh, *pBqh, *pBph;
    cudaGetSymbolAddress((void**)&pPKh,  g_PKh);
    cudaGetSymbolAddress((void**)&psp,   g_sp);
    cudaGetSymbolAddress((void**)&psq,   g_sq);
    cudaGetSymbolAddress((void**)&palpha,g_alpha);
    cudaGetSymbolAddress((void**)&phid,  g_hidden);
    cudaGetSymbolAddress((void**)&pinp,  g_inputs);
    cudaGetSymbolAddress((void**)&pgout, g_gout);
    cudaGetSymbolAddress((void**)&pQ1,   g_Q1);
    cudaGetSymbolAddress((void**)&pQ2,   g_Q2);
    cudaGetSymbolAddress((void**)&pcq,   g_cq);
    cudaGetSymbolAddress((void**)&pgi,   g_gi);
    cudaGetSymbolAddress((void**)&pgh,   g_gh);
    cudaGetSymbolAddress((void**)&pAh,   g_Ah);
    cudaGetSymbolAddress((void**)&pQh,   g_Qh);
    cudaGetSymbolAddress((void**)&pBqh,  g_Bqh);
    cudaGetSymbolAddress((void**)&pBph,  g_Bph);
    cudaGetSymbolAddress((void**)&pWqpT, g_WqpT);
    cudaGetSymbolAddress((void**)&pzb,   g_zb);

    cudaFuncSetAttribute(mma2_k, cudaFuncAttributeMaxDynamicSharedMemorySize, 3 * STG + 1024);

    // independent prep (front-loaded)
    zero_k<<<256, 256>>>(psp);
    zero_k<<<4, 256>>>(pzb);
    cvt3_k<<<6144, 256>>>(Wk_q, pBqh, Wk_p, pBph, question, pQh);
    cvt_k<<<65536, 256>>>(passage, pAh);
    transpose_k<<<dim3(32, 32), 256>>>(Wq_p, pWqpT);

    // question branch
    xw_k<<<dim3(4, 1), 256>>>(Vq, Wq_q, pcq);
    mma2_k<<<dim3(8, 32), 256, 3 * STG + 1024>>>(pQh, pBqh, pPKh, w_q, pcq, psp, 0);
    score_h_k<<<512, 256>>>(pPKh, pcq, w_q, qmask, psq, 0);
    softmax_k<<<64, 256>>>(psq, palpha, 64);
    pool_k<<<dim3(64, 4), 256>>>(question, palpha, phid, 64);
    rowdotB_k<<<128, 256>>>(phid, pWqpT, pzb, pQ1, 1024);          // Q1 = hidden @ Wq_p
    rowdotB_k<<<384, 256>>>(phid, W_hh, b_hh, pgh, 3072);          // gh (needs only hidden)

    // passage GEMM with fused begin-score (computed once)
    mma2_k<<<dim3(8, 512), 256, 3 * STG + 1024>>>(pAh, pBph, pPKh, w_p, pQ1, psp, 1);

    // fused mask-fixup + softmax, then pool (fp16 passage) -> GRU input
    softmaxM_k<<<64, 256>>>(psp, pmask, out, palpha);
    pool_h_k<<<dim3(64, 4), 256>>>(pAh, palpha, pinp, 1024);

    // GRU + end logits
    rowdotB_k<<<384, 256>>>(pinp, W_ih, b_ih, pgi, 3072);
    gru_k<<<256, 256>>>();
    rowdotB_k<<<128, 256>>>(pgout, pWqpT, pzb, pQ2, 1024);         // Q2 = gru_out @ Wq_p
    score_h_k<<<8192, 256>>>(pPKh, pQ2, w_p, pmask, out + 65536, 1);
}

// round 13
// speedup vs baseline: 2.2718x; 1.0483x over previous
#include <cuda_runtime.h>
#include <cuda_fp16.h>
#include <math.h>
#include <stdint.h>

// Shapes (fixed): B=64, TQ=64, TP=1024, H=A=1024
#define NB  64
#define Hn  1024

// ---------------- scratch (__device__ globals) --------------------------------
__device__ __half g_PKh[67108864];               // 128MB logits-GEMM output (fp16)
__device__ __half g_Ah[67108864];                // passage fp16
__device__ __half g_Qh[4194304];                 // question fp16
__device__ __half g_Bqh[1048576];                // Wk_q fp16 [k][n]
__device__ __half g_Bph[1048576];                // Wk_p fp16 [k][n]
__device__ float g_WqpT[1048576];                // Wq_p transposed [j][h]
__device__ float g_zb[1024];                     // zero bias
__device__ float g_sp[65536];                    // fused begin-score partials
__device__ float g_sq[NB * 64];
__device__ float g_alpha[NB * 1024];
__device__ float g_hidden[NB * Hn];
__device__ float g_inputs[NB * Hn];
__device__ float g_gout[NB * Hn];
__device__ float g_Q1[NB * Hn];
__device__ float g_Q2[NB * Hn];
__device__ float g_cq[Hn];
__device__ float g_gi[NB * 3 * Hn];
__device__ float g_gh[NB * 3 * Hn];

// ---------------- helpers -----------------------------------------------------
__device__ __forceinline__ float tanh_apx(float x) {
    float y;
    asm("tanh.approx.f32 %0, %1;" : "=f"(y) : "f"(x));
    return y;
}
__device__ __forceinline__ uint32_t smem_u32(const void* p) {
    uint32_t a;
    asm("{ .reg .u64 t; cvta.to.shared.u64 t, %1; cvt.u32.u64 %0, t; }" : "=r"(a) : "l"(p));
    return a;
}
__device__ __forceinline__ void cpa16(uint32_t s, const void* g) {
    asm volatile("cp.async.cg.shared.global [%0], [%1], 16;" :: "r"(s), "l"(g));
}
__device__ __forceinline__ void ldsm_x4u(uint32_t* r, uint32_t a) {
    asm volatile("ldmatrix.sync.aligned.m8n8.x4.shared.b16 {%0,%1,%2,%3}, [%4];"
                 : "=r"(r[0]), "=r"(r[1]), "=r"(r[2]), "=r"(r[3]) : "r"(a));
}
__device__ __forceinline__ void ldsm_x4t_u(uint32_t* r, uint32_t a) {
    asm volatile("ldmatrix.sync.aligned.m8n8.x4.trans.shared.b16 {%0,%1,%2,%3}, [%4];"
                 : "=r"(r[0]), "=r"(r[1]), "=r"(r[2]), "=r"(r[3]) : "r"(a));
}
__device__ __forceinline__ void mma_f16(float* d, const uint32_t* a, const uint32_t* b) {
    asm volatile(
        "mma.sync.aligned.m16n8k16.row.col.f32.f16.f16.f32 "
        "{%0,%1,%2,%3}, {%4,%5,%6,%7}, {%8,%9}, {%0,%1,%2,%3};"
        : "+f"(d[0]), "+f"(d[1]), "+f"(d[2]), "+f"(d[3])
        : "r"(a[0]), "r"(a[1]), "r"(a[2]), "r"(a[3]), "r"(b[0]), "r"(b[1]));
}

// ---------------- conversions --------------------------------------------------
// merged convert: [0,1024)->Wk_q, [1024,2048)->Wk_p, [2048,6144)->question
__global__ __launch_bounds__(256) void cvt3_k(const float* __restrict__ s0, __half* __restrict__ d0,
                                              const float* __restrict__ s1, __half* __restrict__ d1,
                                              const float* __restrict__ s2, __half* __restrict__ d2) {
    int blk = blockIdx.x;
    const float* src; __half* dst; int base;
    if (blk < 1024)      { src = s0; dst = d0; base = blk; }
    else if (blk < 2048) { src = s1; dst = d1; base = blk - 1024; }
    else                 { src = s2; dst = d2; base = blk - 2048; }
    int i = base * 256 + threadIdx.x;
    float4 v = ((const float4*)src)[i];
    __half2* hp = (__half2*)dst;
    hp[2 * i]     = __halves2half2(__float2half(v.x), __float2half(v.y));
    hp[2 * i + 1] = __halves2half2(__float2half(v.z), __float2half(v.w));
}
__global__ __launch_bounds__(256) void zero_k(float* __restrict__ p) {
    p[blockIdx.x * 256 + threadIdx.x] = 0.f;
}
// 1024x1024 fp32 transpose: dst[j][h] = src[h][j]
__global__ __launch_bounds__(256) void transpose_k(const float* __restrict__ src,
                                                   float* __restrict__ dst) {
    __shared__ float t[32][33];
    int bx = blockIdx.x * 32, by = blockIdx.y * 32;
    int lx = threadIdx.x & 31, ly = threadIdx.x >> 5;
    for (int d = 0; d < 32; d += 8)
        t[ly + d][lx] = src[(size_t)(by + ly + d) * 1024 + bx + lx];
    __syncthreads();
    for (int d = 0; d < 32; d += 8)
        dst[(size_t)(bx + ly + d) * 1024 + by + lx] = t[lx][ly + d];
}
// cq[j] += sum_{h in block chunk} Vq[h] * W[h][j]   (grid 4 x 8, atomic combine)
__global__ __launch_bounds__(256) void xwA_k(const float* __restrict__ x,
                                             const float* __restrict__ W,
                                             float* __restrict__ out) {
    __shared__ float xs[128];
    const int j = blockIdx.x * 256 + threadIdx.x;
    const int h0 = blockIdx.y * 128;
    if (threadIdx.x < 128) xs[threadIdx.x] = x[h0 + threadIdx.x];
    __syncthreads();
    const float* Wc = W + (size_t)h0 * 1024 + j;
    float a0 = 0.f, a1 = 0.f, a2 = 0.f, a3 = 0.f;
    for (int h = 0; h < 128; h += 4) {
        a0 += xs[h + 0] * Wc[(size_t)(h + 0) * 1024];
        a1 += xs[h + 1] * Wc[(size_t)(h + 1) * 1024];
        a2 += xs[h + 2] * Wc[(size_t)(h + 2) * 1024];
        a3 += xs[h + 3] * Wc[(size_t)(h + 3) * 1024];
    }
    atomicAdd(&out[j], (a0 + a1) + (a2 + a3));
}

// ---------------- GEMM pieces --------------------------------------------------
#define STG 35840
__device__ __forceinline__ void load_chunk(uint32_t st,
                                           const __half* Ah, const __half* Bh,
                                           int row0, int col0, int k0, int tid) {
#pragma unroll
    for (int j = 0; j < 4; j++) {          // A: 128 rows x 64 halves
        int s = tid + j * 256;
        int r = s >> 3, c8 = s & 7;
        uint32_t so = (uint32_t)(r * 144 + c8 * 16);
        size_t go = (size_t)(row0 + r) * 1024 + k0 + c8 * 8;
        cpa16(st + so, Ah + go);
    }
#pragma unroll
    for (int j = 0; j < 4; j++) {          // B: 64 k-rows x 128 halves
        int s = tid + j * 256;
        int r = s >> 4, c8 = s & 15;
        uint32_t so = (uint32_t)(r * 272 + c8 * 16);
        size_t go = (size_t)(k0 + r) * 1024 + col0 + c8 * 8;
        cpa16(st + 18432 + so, Bh + go);
    }
    asm volatile("cp.async.commit_group;" ::: "memory");
}

// shared GEMM mainloop + fp16 store; returns with acc live for caller epilogue
__device__ __forceinline__ void gemm_body(const __half* Ah, const __half* Bh,
                                          __half* C, int row0, int col0,
                                          uint32_t sba, int tid,
                                          float acc[4][4][4]) {
    const int warp = tid >> 5, lane = tid & 31;
    const int wm = warp >> 2, wn = warp & 3;
#pragma unroll
    for (int i = 0; i < 4; i++)
#pragma unroll
        for (int j = 0; j < 4; j++)
#pragma unroll
            for (int v = 0; v < 4; v++) acc[i][j][v] = 0.f;

    load_chunk(sba,       Ah, Bh, row0, col0, 0,  tid);
    load_chunk(sba + STG, Ah, Bh, row0, col0, 64, tid);

    for (int c = 0; c < 16; c++) {
        if (c < 15) asm volatile("cp.async.wait_group 1;" ::: "memory");
        else        asm volatile("cp.async.wait_group 0;" ::: "memory");
        __syncthreads();
        if (c + 2 < 16)
            load_chunk(sba + ((c + 2) % 3) * STG, Ah, Bh, row0, col0, (c + 2) * 64, tid);

        const uint32_t st  = sba + (c % 3) * STG;
        const uint32_t aB  = st;
        const uint32_t bB  = st + 18432;
        const int arow = lane & 15, acol = (lane >> 4) << 3;
        const int bkrl = lane & 15, bcb = wn * 32 + ((lane >> 4) << 3);
#pragma unroll
        for (int kk = 0; kk < 64; kk += 16) {
            uint32_t ah[4][4], bh[2][4];
#pragma unroll
            for (int mi = 0; mi < 4; mi++) {
                uint32_t off = (uint32_t)((wm * 64 + mi * 16 + arow) * 144 + (kk + acol) * 2);
                ldsm_x4u(ah[mi], aB + off);
            }
#pragma unroll
            for (int ni = 0; ni < 2; ni++) {
                uint32_t off = (uint32_t)((kk + bkrl) * 272 + (bcb + ni * 16) * 2);
                ldsm_x4t_u(bh[ni], bB + off);
            }
#pragma unroll
            for (int mi = 0; mi < 4; mi++)
#pragma unroll
                for (int nj = 0; nj < 4; nj++) {
                    int ni = nj >> 1, p = (nj & 1) * 2;
                    mma_f16(acc[mi][nj], ah[mi], &bh[ni][p]);
                }
        }
    }

    const int rbase = row0 + wm * 64, cbase = col0 + wn * 32;
    const int lr = lane >> 2, lc = (lane & 3) * 2;
#pragma unroll
    for (int mi = 0; mi < 4; mi++)
#pragma unroll
        for (int nj = 0; nj < 4; nj++) {
            int rr = rbase + mi * 16 + lr;
            int cc = cbase + nj * 8 + lc;
            *(__half2*)&C[(size_t)rr * 1024 + cc] =
                __floats2half2_rn(acc[mi][nj][0], acc[mi][nj][1]);
            *(__half2*)&C[(size_t)(rr + 8) * 1024 + cc] =
                __floats2half2_rn(acc[mi][nj][2], acc[mi][nj][3]);
        }
}

// passage GEMM with fused begin-score epilogue
__global__ __launch_bounds__(256, 2) void mma2_k(const __half* __restrict__ Ah,
                                                 const __half* __restrict__ Bh,
                                                 __half* __restrict__ C,
                                                 const float* __restrict__ wv,
                                                 const float* __restrict__ Qv,
                                                 float* __restrict__ SP) {
    extern __shared__ char dsm[];
    __shared__ float part[128];
    uint32_t sba = (smem_u32(dsm) + 1023u) & ~1023u;
    const int tid = threadIdx.x;
    const int warp = tid >> 5, lane = tid & 31;
    const int wm = warp >> 2, wn = warp & 3;
    const int row0 = blockIdx.y * 128, col0 = blockIdx.x * 128;
    if (tid < 128) part[tid] = 0.f;

    float acc[4][4][4];
    gemm_body(Ah, Bh, C, row0, col0, sba, tid, acc);

    const int cbase = col0 + wn * 32;
    const int lr = lane >> 2, lc = (lane & 3) * 2;
    const float* q = Qv + ((size_t)(row0 >> 10) << 10);
    __syncthreads();
#pragma unroll
    for (int mi = 0; mi < 4; mi++) {
        float sA = 0.f, sB = 0.f;
#pragma unroll
        for (int nj = 0; nj < 4; nj++) {
            int cc = cbase + nj * 8 + lc;
            float w0 = wv[cc], w1 = wv[cc + 1];
            float q0 = q[cc],  q1v = q[cc + 1];
            sA += w0 * tanh_apx(acc[mi][nj][0] + q0) + w1 * tanh_apx(acc[mi][nj][1] + q1v);
            sB += w0 * tanh_apx(acc[mi][nj][2] + q0) + w1 * tanh_apx(acc[mi][nj][3] + q1v);
        }
        sA += __shfl_xor_sync(0xffffffffu, sA, 1);
        sA += __shfl_xor_sync(0xffffffffu, sA, 2);
        sB += __shfl_xor_sync(0xffffffffu, sB, 1);
        sB += __shfl_xor_sync(0xffffffffu, sB, 2);
        if ((lane & 3) == 0) {
            atomicAdd(&part[wm * 64 + mi * 16 + lr], sA);
            atomicAdd(&part[wm * 64 + mi * 16 + lr + 8], sB);
        }
    }
    __syncthreads();
    if (tid < 128) atomicAdd(&SP[row0 + tid], part[tid]);
}

// hybrid: blocks [0,256) question GEMM; blocks [256,2304) passage fp32->fp16 cvt
__global__ __launch_bounds__(256, 2) void gemmq_cvt_k(const __half* __restrict__ Aq,
                                                      const __half* __restrict__ Bq,
                                                      __half* __restrict__ Cq,
                                                      const float* __restrict__ psrc,
                                                      __half* __restrict__ pdst) {
    extern __shared__ char dsm[];
    const int tid = threadIdx.x;
    if (blockIdx.x < 256) {
        uint32_t sba = (smem_u32(dsm) + 1023u) & ~1023u;
        const int col0 = (blockIdx.x & 7) * 128;
        const int row0 = (blockIdx.x >> 3) * 128;
        float acc[4][4][4];
        gemm_body(Aq, Bq, Cq, row0, col0, sba, tid, acc);
    } else {
        const size_t base = (size_t)(blockIdx.x - 256) * 8192;
        const float4* s = (const float4*)psrc;
        __half2* hp = (__half2*)pdst;
#pragma unroll 1
        for (int jo = 0; jo < 8; jo++) {
            float4 v[4];
#pragma unroll
            for (int ji = 0; ji < 4; ji++)
                v[ji] = s[base + (size_t)(jo * 4 + ji) * 256 + tid];
#pragma unroll
            for (int ji = 0; ji < 4; ji++) {
                size_t i = base + (size_t)(jo * 4 + ji) * 256 + tid;
                hp[2 * i]     = __halves2half2(__float2half(v[ji].x), __float2half(v[ji].y));
                hp[2 * i + 1] = __halves2half2(__float2half(v[ji].z), __float2half(v[ji].w));
            }
        }
    }
}

// ---------------- score over fp16 PK: warp-per-row -----------------------------
__global__ __launch_bounds__(256) void score_h_k(const __half* __restrict__ C,
                                                 const float* __restrict__ qterm,
                                                 const float* __restrict__ wv,
                                                 const float* __restrict__ mask,
                                                 float* __restrict__ outs, int per_row) {
    const int warp = threadIdx.x >> 5, lane = threadIdx.x & 31;
    const int r = blockIdx.x * 8 + warp;
    const __half* crow = C + (size_t)r * 1024;
    const float* q = per_row ? (qterm + (size_t)(r >> 10) * 1024) : qterm;
    float acc = 0.f;
#pragma unroll
    for (int i = 0; i < 4; i++) {
        int c0 = (lane + i * 32) * 8;
        uint4 v = *(const uint4*)(crow + c0);
        const __half2* h = (const __half2*)&v;
#pragma unroll
        for (int j = 0; j < 4; j++) {
            float2 f = __half22float2(h[j]);
            int c = c0 + j * 2;
            acc += wv[c]     * tanh_apx(f.x + q[c]);
            acc += wv[c + 1] * tanh_apx(f.y + q[c + 1]);
        }
    }
#pragma unroll
    for (int o = 16; o; o >>= 1) acc += __shfl_xor_sync(0xffffffffu, acc, o);
    if (lane == 0) outs[r] = (mask[r] > 0.f) ? acc : -1e30f;
}

// plain masked softmax (question branch)
__global__ __launch_bounds__(256) void softmax_k(const float* __restrict__ s,
                                                 float* __restrict__ alpha, int T) {
    const int b = blockIdx.x, tid = threadIdx.x;
    __shared__ float red[8];
    __shared__ float sh;
    const float* sb = s + (size_t)b * T;
    float mx = -3.0e38f;
    for (int t = tid; t < T; t += 256) mx = fmaxf(mx, sb[t]);
    for (int o = 16; o; o >>= 1) mx = fmaxf(mx, __shfl_xor_sync(0xffffffffu, mx, o));
    if ((tid & 31) == 0) red[tid >> 5] = mx;
    __syncthreads();
    if (tid == 0) {
        float v = red[0];
#pragma unroll
        for (int w = 1; w < 8; w++) v = fmaxf(v, red[w]);
        sh = v;
    }
    __syncthreads();
    mx = sh;
    float sum = 0.f;
    for (int t = tid; t < T; t += 256) {
        float e = expf(sb[t] - mx);
        alpha[(size_t)b * T + t] = e;
        sum += e;
    }
    for (int o = 16; o; o >>= 1) sum += __shfl_xor_sync(0xffffffffu, sum, o);
    __syncthreads();
    if ((tid & 31) == 0) red[tid >> 5] = sum;
    __syncthreads();
    if (tid == 0) {
        float v = 0.f;
#pragma unroll
        for (int w = 0; w < 8; w++) v += red[w];
        sh = 1.f / v;
    }
    __syncthreads();
    float inv = sh;
    for (int t = tid; t < T; t += 256) alpha[(size_t)b * T + t] *= inv;
}

// fused: masked logits (out) + softmax alpha from raw partials (passage branch)
__global__ __launch_bounds__(256) void softmaxM_k(const float* __restrict__ sp,
                                                  const float* __restrict__ mask,
                                                  float* __restrict__ out,
                                                  float* __restrict__ alpha) {
    const int b = blockIdx.x, tid = threadIdx.x;
    __shared__ float red[8];
    __shared__ float sh;
    float v4[4];
    float mx = -3.0e38f;
#pragma unroll
    for (int i = 0; i < 4; i++) {
        int t = tid + i * 256;
        float s = (mask[b * 1024 + t] > 0.f) ? sp[b * 1024 + t] : -1e30f;
        out[b * 1024 + t] = s;
        v4[i] = s;
        mx = fmaxf(mx, s);
    }
    for (int o = 16; o; o >>= 1) mx = fmaxf(mx, __shfl_xor_sync(0xffffffffu, mx, o));
    if ((tid & 31) == 0) red[tid >> 5] = mx;
    __syncthreads();
    if (tid == 0) {
        float v = red[0];
#pragma unroll
        for (int w = 1; w < 8; w++) v = fmaxf(v, red[w]);
        sh = v;
    }
    __syncthreads();
    mx = sh;
    float sum = 0.f;
#pragma unroll
    for (int i = 0; i < 4; i++) {
        v4[i] = expf(v4[i] - mx);
        sum += v4[i];
    }
    for (int o = 16; o; o >>= 1) sum += __shfl_xor_sync(0xffffffffu, sum, o);
    __syncthreads();
    if ((tid & 31) == 0) red[tid >> 5] = sum;
    __syncthreads();
    if (tid == 0) {
        float v = 0.f;
#pragma unroll
        for (int w = 0; w < 8; w++) v += red[w];
        sh = 1.f / v;
    }
    __syncthreads();
    float inv = sh;
#pragma unroll
    for (int i = 0; i < 4; i++)
        alpha[b * 1024 + tid + i * 256] = v4[i] * inv;
}

// fp32 key pool (question)
__global__ __launch_bounds__(256) void pool_k(const float* __restrict__ key,
                                              const float* __restrict__ alpha,
                                              float* __restrict__ out, int T) {
    const int b = blockIdx.x;
    const int h = blockIdx.y * 256 + threadIdx.x;
    const float* kb = key + (size_t)b * T * 1024 + h;
    const float* ab = alpha + (size_t)b * T;
    float a0 = 0.f, a1 = 0.f, a2 = 0.f, a3 = 0.f;
    for (int t = 0; t < T; t += 4) {
        a0 += ab[t + 0] * kb[(size_t)(t + 0) * 1024];
        a1 += ab[t + 1] * kb[(size_t)(t + 1) * 1024];
        a2 += ab[t + 2] * kb[(size_t)(t + 2) * 1024];
        a3 += ab[t + 3] * kb[(size_t)(t + 3) * 1024];
    }
    out[(size_t)b * 1024 + h] = (a0 + a1) + (a2 + a3);
}

// fp16 key pool (passage)
__global__ __launch_bounds__(256) void pool_h_k(const __half* __restrict__ key,
                                                const float* __restrict__ alpha,
                                                float* __restrict__ out, int T) {
    const int b = blockIdx.x;
    const int h = blockIdx.y * 256 + threadIdx.x;
    const __half* kb = key + (size_t)b * T * 1024 + h;
    const float* ab = alpha + (size_t)b * T;
    float a0 = 0.f, a1 = 0.f, a2 = 0.f, a3 = 0.f;
    for (int t = 0; t < T; t += 4) {
        a0 += ab[t + 0] * __half2float(kb[(size_t)(t + 0) * 1024]);
        a1 += ab[t + 1] * __half2float(kb[(size_t)(t + 1) * 1024]);
        a2 += ab[t + 2] * __half2float(kb[(size_t)(t + 2) * 1024]);
        a3 += ab[t + 3] * __half2float(kb[(size_t)(t + 3) * 1024]);
    }
    out[(size_t)b * 1024 + h] = (a0 + a1) + (a2 + a3);
}

// batched out[b][j] = bias[j] + dot(x[b], W[j][:]) — W in regs, 8-row chunks
__global__ __launch_bounds__(256) void rowdotB_k(const float* __restrict__ x,
                                                 const float* __restrict__ W,
                                                 const float* __restrict__ bias,
                                                 float* __restrict__ out, int N) {
    __shared__ float xs[8][1024];
    const int warp = threadIdx.x >> 5, lane = threadIdx.x & 31;
    const int j = blockIdx.x * 8 + warp;
    float Wreg[32];
    const float* wr = W + (size_t)j * 1024;
#pragma unroll
    for (int i = 0; i < 32; i++) Wreg[i] = wr[lane + i * 32];
    const float bj = bias[j];
    for (int bb = 0; bb < 8; bb++) {
        __syncthreads();
#pragma unroll
        for (int jj = 0; jj < 8; jj++) {
            int f = threadIdx.x + jj * 256;
            int row = f >> 8, c4 = f & 255;
            ((float4*)&xs[row][0])[c4] =
                ((const float4*)(x + (size_t)(bb * 8 + row) * 1024))[c4];
        }
        __syncthreads();
#pragma unroll
        for (int r = 0; r < 8; r++) {
            float acc = 0.f;
#pragma unroll
            for (int i = 0; i < 32; i++) acc += xs[r][lane + i * 32] * Wreg[i];
#pragma unroll
            for (int o = 16; o; o >>= 1) acc += __shfl_xor_sync(0xffffffffu, acc, o);
            if (!lane) out[(size_t)(bb * 8 + r) * N + j] = acc + bj;
        }
    }
}

__global__ __launch_bounds__(256) void gru_k() {
    const int i = blockIdx.x * 256 + threadIdx.x;
    const int b = i >> 10, h = i & 1023;
    const float* gi = g_gi + (size_t)b * 3072;
    const float* gh = g_gh + (size_t)b * 3072;
    float r = 1.f / (1.f + expf(-(gi[h] + gh[h])));
    float z = 1.f / (1.f + expf(-(gi[1024 + h] + gh[1024 + h])));
    float n = tanhf(gi[2048 + h] + r * gh[2048 + h]);
    g_gout[i] = (1.f - z) * n + z * g_hidden[i];
}

// ---------------- launch ------------------------------------------------------
extern "C" void kernel_launch(void* const* d_in, const int* in_sizes, int n_in,
                              void* d_out, int out_size) {
    const float* question = (const float*)d_in[0];
    const float* qmask    = (const float*)d_in[1];
    const float* passage  = (const float*)d_in[2];
    const float* pmask    = (const float*)d_in[3];
    const float* Vq       = (const float*)d_in[4];
    const float* Wk_q     = (const float*)d_in[5];
    const float* Wq_q     = (const float*)d_in[6];
    const float* w_q      = (const float*)d_in[7];
    const float* Wk_p     = (const float*)d_in[8];
    const float* Wq_p     = (const float*)d_in[9];
    const float* w_p      = (const float*)d_in[10];
    const float* W_ih     = (const float*)d_in[11];
    const float* W_hh     = (const float*)d_in[12];
    const float* b_ih     = (const float*)d_in[13];
    const float* b_hh     = (const float*)d_in[14];
    float* out = (float*)d_out;

    float *psp, *psq, *palpha, *phid, *pinp, *pgout, *pQ1, *pQ2, *pcq, *pgi, *pgh;
    float *pWqpT, *pzb;
    __half *pPKh, *pAh, *pQh, *pBqh, *pBph;
    cudaGetSymbolAddress((void**)&pPKh,  g_PKh);
    cudaGetSymbolAddress((void**)&psp,   g_sp);
    cudaGetSymbolAddress((void**)&psq,   g_sq);
    cudaGetSymbolAddress((void**)&palpha,g_alpha);
    cudaGetSymbolAddress((void**)&phid,  g_hidden);
    cudaGetSymbolAddress((void**)&pinp,  g_inputs);
    cudaGetSymbolAddress((void**)&pgout, g_gout);
    cudaGetSymbolAddress((void**)&pQ1,   g_Q1);
    cudaGetSymbolAddress((void**)&pQ2,   g_Q2);
    cudaGetSymbolAddress((void**)&pcq,   g_cq);
    cudaGetSymbolAddress((void**)&pgi,   g_gi);
    cudaGetSymbolAddress((void**)&pgh,   g_gh);
    cudaGetSymbolAddress((void**)&pAh,   g_Ah);
    cudaGetSymbolAddress((void**)&pQh,   g_Qh);
    cudaGetSymbolAddress((void**)&pBqh,  g_Bqh);
    cudaGetSymbolAddress((void**)&pBph,  g_Bph);
    cudaGetSymbolAddress((void**)&pWqpT, g_WqpT);
    cudaGetSymbolAddress((void**)&pzb,   g_zb);

    cudaFuncSetAttribute(mma2_k,      cudaFuncAttributeMaxDynamicSharedMemorySize, 3 * STG + 1024);
    cudaFuncSetAttribute(gemmq_cvt_k, cudaFuncAttributeMaxDynamicSharedMemorySize, 3 * STG + 1024);

    // independent prep (front-loaded)
    zero_k<<<256, 256>>>(psp);
    zero_k<<<4, 256>>>(pzb);
    zero_k<<<4, 256>>>(pcq);
    cvt3_k<<<6144, 256>>>(Wk_q, pBqh, Wk_p, pBph, question, pQh);
    transpose_k<<<dim3(32, 32), 256>>>(Wq_p, pWqpT);
    xwA_k<<<dim3(4, 8), 256>>>(Vq, Wq_q, pcq);

    // HYBRID: question GEMM (blocks 0..255) + passage cvt (blocks 256..2303)
    gemmq_cvt_k<<<2304, 256, 3 * STG + 1024>>>(pQh, pBqh, pPKh, passage, pAh);

    // question branch tail
    score_h_k<<<512, 256>>>(pPKh, pcq, w_q, qmask, psq, 0);
    softmax_k<<<64, 256>>>(psq, palpha, 64);
    pool_k<<<dim3(64, 4), 256>>>(question, palpha, phid, 64);
    rowdotB_k<<<128, 256>>>(phid, pWqpT, pzb, pQ1, 1024);          // Q1 = hidden @ Wq_p
    rowdotB_k<<<384, 256>>>(phid, W_hh, b_hh, pgh, 3072);          // gh (needs only hidden)

    // passage GEMM with fused begin-score (computed once)
    mma2_k<<<dim3(8, 512), 256, 3 * STG + 1024>>>(pAh, pBph, pPKh, w_p, pQ1, psp);

    // fused mask-fixup + softmax, then pool (fp16 passage) -> GRU input
    softmaxM_k<<<64, 256>>>(psp, pmask, out, palpha);
    pool_h_k<<<dim3(64, 4), 256>>>(pAh, palpha, pinp, 1024);

    // GRU + end logits
    rowdotB_k<<<384, 256>>>(pinp, W_ih, b_ih, pgi, 3072);
    gru_k<<<256, 256>>>();
    rowdotB_k<<<128, 256>>>(pgout, pWqpT, pzb, pQ2, 1024);         // Q2 = gru_out @ Wq_p
    score_h_k<<<8192, 256>>>(pPKh, pQ2, w_p, pmask, out + 65536, 1);
}

// round 14
// speedup vs baseline: 2.4425x; 1.0752x over previous
#include <cuda_runtime.h>
#include <cuda_fp16.h>
#include <math.h>
#include <stdint.h>

// Shapes (fixed): B=64, TQ=64, TP=1024, H=A=1024
#define NB  64
#define Hn  1024

// ---------------- scratch (__device__ globals) --------------------------------
__device__ __half g_PKh[67108864];               // 128MB logits-GEMM output (fp16)
__device__ __half g_Ah[67108864];                // passage fp16
__device__ __half g_Qh[4194304];                 // question fp16
__device__ __half g_Bqh[1048576];                // Wk_q fp16 [k][n]
__device__ __half g_Bph[1048576];                // Wk_p fp16 [k][n]
__device__ float g_WqpT[1048576];                // Wq_p transposed [j][h]
__device__ float g_zb[1024];                     // zero bias
__device__ float g_sp[65536];                    // fused begin-score partials
__device__ float g_sq[NB * 64];
__device__ float g_alpha[NB * 1024];
__device__ float g_hidden[NB * Hn];
__device__ float g_inputs[NB * Hn];
__device__ float g_gout[NB * Hn];
__device__ float g_Q1[NB * Hn];
__device__ float g_Q2[NB * Hn];
__device__ float g_cq[Hn];
__device__ float g_gi[NB * 3 * Hn];
__device__ float g_gh[NB * 3 * Hn];

// ---------------- helpers -----------------------------------------------------
__device__ __forceinline__ float tanh_apx(float x) {
    float y;
    asm("tanh.approx.f32 %0, %1;" : "=f"(y) : "f"(x));
    return y;
}
__device__ __forceinline__ uint32_t smem_u32(const void* p) {
    uint32_t a;
    asm("{ .reg .u64 t; cvta.to.shared.u64 t, %1; cvt.u32.u64 %0, t; }" : "=r"(a) : "l"(p));
    return a;
}
__device__ __forceinline__ void cpa16(uint32_t s, const void* g) {
    asm volatile("cp.async.cg.shared.global [%0], [%1], 16;" :: "r"(s), "l"(g));
}
__device__ __forceinline__ void ldsm_x4u(uint32_t* r, uint32_t a) {
    asm volatile("ldmatrix.sync.aligned.m8n8.x4.shared.b16 {%0,%1,%2,%3}, [%4];"
                 : "=r"(r[0]), "=r"(r[1]), "=r"(r[2]), "=r"(r[3]) : "r"(a));
}
__device__ __forceinline__ void ldsm_x4t_u(uint32_t* r, uint32_t a) {
    asm volatile("ldmatrix.sync.aligned.m8n8.x4.trans.shared.b16 {%0,%1,%2,%3}, [%4];"
                 : "=r"(r[0]), "=r"(r[1]), "=r"(r[2]), "=r"(r[3]) : "r"(a));
}
__device__ __forceinline__ void mma_f16(float* d, const uint32_t* a, const uint32_t* b) {
    asm volatile(
        "mma.sync.aligned.m16n8k16.row.col.f32.f16.f16.f32 "
        "{%0,%1,%2,%3}, {%4,%5,%6,%7}, {%8,%9}, {%0,%1,%2,%3};"
        : "+f"(d[0]), "+f"(d[1]), "+f"(d[2]), "+f"(d[3])
        : "r"(a[0]), "r"(a[1]), "r"(a[2]), "r"(a[3]), "r"(b[0]), "r"(b[1]));
}

// ---------------- conversions --------------------------------------------------
__global__ __launch_bounds__(256) void cvt3_k(const float* __restrict__ s0, __half* __restrict__ d0,
                                              const float* __restrict__ s1, __half* __restrict__ d1,
                                              const float* __restrict__ s2, __half* __restrict__ d2) {
    int blk = blockIdx.x;
    const float* src; __half* dst; int base;
    if (blk < 1024)      { src = s0; dst = d0; base = blk; }
    else if (blk < 2048) { src = s1; dst = d1; base = blk - 1024; }
    else                 { src = s2; dst = d2; base = blk - 2048; }
    int i = base * 256 + threadIdx.x;
    float4 v = ((const float4*)src)[i];
    __half2* hp = (__half2*)dst;
    hp[2 * i]     = __halves2half2(__float2half(v.x), __float2half(v.y));
    hp[2 * i + 1] = __halves2half2(__float2half(v.z), __float2half(v.w));
}
__global__ __launch_bounds__(256) void zero_k(float* __restrict__ p) {
    p[blockIdx.x * 256 + threadIdx.x] = 0.f;
}
__global__ __launch_bounds__(256) void transpose_k(const float* __restrict__ src,
                                                   float* __restrict__ dst) {
    __shared__ float t[32][33];
    int bx = blockIdx.x * 32, by = blockIdx.y * 32;
    int lx = threadIdx.x & 31, ly = threadIdx.x >> 5;
    for (int d = 0; d < 32; d += 8)
        t[ly + d][lx] = src[(size_t)(by + ly + d) * 1024 + bx + lx];
    __syncthreads();
    for (int d = 0; d < 32; d += 8)
        dst[(size_t)(bx + ly + d) * 1024 + by + lx] = t[lx][ly + d];
}
// cq[j] += sum_{h in block chunk} Vq[h] * W[h][j]   (grid 4 x 8, atomic combine)
__global__ __launch_bounds__(256) void xwA_k(const float* __restrict__ x,
                                             const float* __restrict__ W,
                                             float* __restrict__ out) {
    __shared__ float xs[128];
    const int j = blockIdx.x * 256 + threadIdx.x;
    const int h0 = blockIdx.y * 128;
    if (threadIdx.x < 128) xs[threadIdx.x] = x[h0 + threadIdx.x];
    __syncthreads();
    const float* Wc = W + (size_t)h0 * 1024 + j;
    float a0 = 0.f, a1 = 0.f, a2 = 0.f, a3 = 0.f;
    for (int h = 0; h < 128; h += 4) {
        a0 += xs[h + 0] * Wc[(size_t)(h + 0) * 1024];
        a1 += xs[h + 1] * Wc[(size_t)(h + 1) * 1024];
        a2 += xs[h + 2] * Wc[(size_t)(h + 2) * 1024];
        a3 += xs[h + 3] * Wc[(size_t)(h + 3) * 1024];
    }
    atomicAdd(&out[j], (a0 + a1) + (a2 + a3));
}

// ---------------- GEMM pieces --------------------------------------------------
#define STG 35840
__device__ __forceinline__ void load_chunk(uint32_t st,
                                           const __half* Ah, const __half* Bh,
                                           int row0, int col0, int k0, int tid) {
#pragma unroll
    for (int j = 0; j < 4; j++) {          // A: 128 rows x 64 halves
        int s = tid + j * 256;
        int r = s >> 3, c8 = s & 7;
        uint32_t so = (uint32_t)(r * 144 + c8 * 16);
        size_t go = (size_t)(row0 + r) * 1024 + k0 + c8 * 8;
        cpa16(st + so, Ah + go);
    }
#pragma unroll
    for (int j = 0; j < 4; j++) {          // B: 64 k-rows x 128 halves
        int s = tid + j * 256;
        int r = s >> 4, c8 = s & 15;
        uint32_t so = (uint32_t)(r * 272 + c8 * 16);
        size_t go = (size_t)(k0 + r) * 1024 + col0 + c8 * 8;
        cpa16(st + 18432 + so, Bh + go);
    }
    asm volatile("cp.async.commit_group;" ::: "memory");
}

__device__ __forceinline__ void gemm_body(const __half* Ah, const __half* Bh,
                                          __half* C, int row0, int col0,
                                          uint32_t sba, int tid,
                                          float acc[4][4][4]) {
    const int warp = tid >> 5, lane = tid & 31;
    const int wm = warp >> 2, wn = warp & 3;
#pragma unroll
    for (int i = 0; i < 4; i++)
#pragma unroll
        for (int j = 0; j < 4; j++)
#pragma unroll
            for (int v = 0; v < 4; v++) acc[i][j][v] = 0.f;

    load_chunk(sba,       Ah, Bh, row0, col0, 0,  tid);
    load_chunk(sba + STG, Ah, Bh, row0, col0, 64, tid);

    for (int c = 0; c < 16; c++) {
        if (c < 15) asm volatile("cp.async.wait_group 1;" ::: "memory");
        else        asm volatile("cp.async.wait_group 0;" ::: "memory");
        __syncthreads();
        if (c + 2 < 16)
            load_chunk(sba + ((c + 2) % 3) * STG, Ah, Bh, row0, col0, (c + 2) * 64, tid);

        const uint32_t st  = sba + (c % 3) * STG;
        const uint32_t aB  = st;
        const uint32_t bB  = st + 18432;
        const int arow = lane & 15, acol = (lane >> 4) << 3;
        const int bkrl = lane & 15, bcb = wn * 32 + ((lane >> 4) << 3);
#pragma unroll
        for (int kk = 0; kk < 64; kk += 16) {
            uint32_t ah[4][4], bh[2][4];
#pragma unroll
            for (int mi = 0; mi < 4; mi++) {
                uint32_t off = (uint32_t)((wm * 64 + mi * 16 + arow) * 144 + (kk + acol) * 2);
                ldsm_x4u(ah[mi], aB + off);
            }
#pragma unroll
            for (int ni = 0; ni < 2; ni++) {
                uint32_t off = (uint32_t)((kk + bkrl) * 272 + (bcb + ni * 16) * 2);
                ldsm_x4t_u(bh[ni], bB + off);
            }
#pragma unroll
            for (int mi = 0; mi < 4; mi++)
#pragma unroll
                for (int nj = 0; nj < 4; nj++) {
                    int ni = nj >> 1, p = (nj & 1) * 2;
                    mma_f16(acc[mi][nj], ah[mi], &bh[ni][p]);
                }
        }
    }

    const int rbase = row0 + wm * 64, cbase = col0 + wn * 32;
    const int lr = lane >> 2, lc = (lane & 3) * 2;
#pragma unroll
    for (int mi = 0; mi < 4; mi++)
#pragma unroll
        for (int nj = 0; nj < 4; nj++) {
            int rr = rbase + mi * 16 + lr;
            int cc = cbase + nj * 8 + lc;
            *(__half2*)&C[(size_t)rr * 1024 + cc] =
                __floats2half2_rn(acc[mi][nj][0], acc[mi][nj][1]);
            *(__half2*)&C[(size_t)(rr + 8) * 1024 + cc] =
                __floats2half2_rn(acc[mi][nj][2], acc[mi][nj][3]);
        }
}

// passage GEMM with fused begin-score epilogue
__global__ __launch_bounds__(256, 2) void mma2_k(const __half* __restrict__ Ah,
                                                 const __half* __restrict__ Bh,
                                                 __half* __restrict__ C,
                                                 const float* __restrict__ wv,
                                                 const float* __restrict__ Qv,
                                                 float* __restrict__ SP) {
    extern __shared__ char dsm[];
    __shared__ float part[128];
    uint32_t sba = (smem_u32(dsm) + 1023u) & ~1023u;
    const int tid = threadIdx.x;
    const int warp = tid >> 5, lane = tid & 31;
    const int wm = warp >> 2, wn = warp & 3;
    const int row0 = blockIdx.y * 128, col0 = blockIdx.x * 128;
    if (tid < 128) part[tid] = 0.f;

    float acc[4][4][4];
    gemm_body(Ah, Bh, C, row0, col0, sba, tid, acc);

    const int cbase = col0 + wn * 32;
    const int lr = lane >> 2, lc = (lane & 3) * 2;
    const float* q = Qv + ((size_t)(row0 >> 10) << 10);
    __syncthreads();
#pragma unroll
    for (int mi = 0; mi < 4; mi++) {
        float sA = 0.f, sB = 0.f;
#pragma unroll
        for (int nj = 0; nj < 4; nj++) {
            int cc = cbase + nj * 8 + lc;
            float w0 = wv[cc], w1 = wv[cc + 1];
            float q0 = q[cc],  q1v = q[cc + 1];
            sA += w0 * tanh_apx(acc[mi][nj][0] + q0) + w1 * tanh_apx(acc[mi][nj][1] + q1v);
            sB += w0 * tanh_apx(acc[mi][nj][2] + q0) + w1 * tanh_apx(acc[mi][nj][3] + q1v);
        }
        sA += __shfl_xor_sync(0xffffffffu, sA, 1);
        sA += __shfl_xor_sync(0xffffffffu, sA, 2);
        sB += __shfl_xor_sync(0xffffffffu, sB, 1);
        sB += __shfl_xor_sync(0xffffffffu, sB, 2);
        if ((lane & 3) == 0) {
            atomicAdd(&part[wm * 64 + mi * 16 + lr], sA);
            atomicAdd(&part[wm * 64 + mi * 16 + lr + 8], sB);
        }
    }
    __syncthreads();
    if (tid < 128) atomicAdd(&SP[row0 + tid], part[tid]);
}

// hybrid: blocks [0,256) question GEMM; blocks [256,2304) passage fp32->fp16 cvt
__global__ __launch_bounds__(256, 2) void gemmq_cvt_k(const __half* __restrict__ Aq,
                                                      const __half* __restrict__ Bq,
                                                      __half* __restrict__ Cq,
                                                      const float* __restrict__ psrc,
                                                      __half* __restrict__ pdst) {
    extern __shared__ char dsm[];
    const int tid = threadIdx.x;
    if (blockIdx.x < 256) {
        uint32_t sba = (smem_u32(dsm) + 1023u) & ~1023u;
        const int col0 = (blockIdx.x & 7) * 128;
        const int row0 = (blockIdx.x >> 3) * 128;
        float acc[4][4][4];
        gemm_body(Aq, Bq, Cq, row0, col0, sba, tid, acc);
    } else {
        const size_t base = (size_t)(blockIdx.x - 256) * 8192;
        const float4* s = (const float4*)psrc;
        __half2* hp = (__half2*)pdst;
#pragma unroll 1
        for (int jo = 0; jo < 8; jo++) {
            float4 v[4];
#pragma unroll
            for (int ji = 0; ji < 4; ji++)
                v[ji] = s[base + (size_t)(jo * 4 + ji) * 256 + tid];
#pragma unroll
            for (int ji = 0; ji < 4; ji++) {
                size_t i = base + (size_t)(jo * 4 + ji) * 256 + tid;
                hp[2 * i]     = __halves2half2(__float2half(v[ji].x), __float2half(v[ji].y));
                hp[2 * i + 1] = __halves2half2(__float2half(v[ji].z), __float2half(v[ji].w));
            }
        }
    }
}

// ---------------- score over fp16 PK: warp-per-row -----------------------------
__global__ __launch_bounds__(256) void score_h_k(const __half* __restrict__ C,
                                                 const float* __restrict__ qterm,
                                                 const float* __restrict__ wv,
                                                 const float* __restrict__ mask,
                                                 float* __restrict__ outs, int per_row) {
    const int warp = threadIdx.x >> 5, lane = threadIdx.x & 31;
    const int r = blockIdx.x * 8 + warp;
    const __half* crow = C + (size_t)r * 1024;
    const float* q = per_row ? (qterm + (size_t)(r >> 10) * 1024) : qterm;
    float acc = 0.f;
#pragma unroll
    for (int i = 0; i < 4; i++) {
        int c0 = (lane + i * 32) * 8;
        uint4 v = *(const uint4*)(crow + c0);
        const __half2* h = (const __half2*)&v;
#pragma unroll
        for (int j = 0; j < 4; j++) {
            float2 f = __half22float2(h[j]);
            int c = c0 + j * 2;
            acc += wv[c]     * tanh_apx(f.x + q[c]);
            acc += wv[c + 1] * tanh_apx(f.y + q[c + 1]);
        }
    }
#pragma unroll
    for (int o = 16; o; o >>= 1) acc += __shfl_xor_sync(0xffffffffu, acc, o);
    if (lane == 0) outs[r] = (mask[r] > 0.f) ? acc : -1e30f;
}

// plain masked softmax (question branch)
__global__ __launch_bounds__(256) void softmax_k(const float* __restrict__ s,
                                                 float* __restrict__ alpha, int T) {
    const int b = blockIdx.x, tid = threadIdx.x;
    __shared__ float red[8];
    __shared__ float sh;
    const float* sb = s + (size_t)b * T;
    float mx = -3.0e38f;
    for (int t = tid; t < T; t += 256) mx = fmaxf(mx, sb[t]);
    for (int o = 16; o; o >>= 1) mx = fmaxf(mx, __shfl_xor_sync(0xffffffffu, mx, o));
    if ((tid & 31) == 0) red[tid >> 5] = mx;
    __syncthreads();
    if (tid == 0) {
        float v = red[0];
#pragma unroll
        for (int w = 1; w < 8; w++) v = fmaxf(v, red[w]);
        sh = v;
    }
    __syncthreads();
    mx = sh;
    float sum = 0.f;
    for (int t = tid; t < T; t += 256) {
        float e = expf(sb[t] - mx);
        alpha[(size_t)b * T + t] = e;
        sum += e;
    }
    for (int o = 16; o; o >>= 1) sum += __shfl_xor_sync(0xffffffffu, sum, o);
    __syncthreads();
    if ((tid & 31) == 0) red[tid >> 5] = sum;
    __syncthreads();
    if (tid == 0) {
        float v = 0.f;
#pragma unroll
        for (int w = 0; w < 8; w++) v += red[w];
        sh = 1.f / v;
    }
    __syncthreads();
    float inv = sh;
    for (int t = tid; t < T; t += 256) alpha[(size_t)b * T + t] *= inv;
}

// fp16 key pool (shared by question T=64 and any fp16 pooling)
__global__ __launch_bounds__(256) void pool_h_k(const __half* __restrict__ key,
                                                const float* __restrict__ alpha,
                                                float* __restrict__ out, int T) {
    const int b = blockIdx.x;
    const int h = blockIdx.y * 256 + threadIdx.x;
    const __half* kb = key + (size_t)b * T * 1024 + h;
    const float* ab = alpha + (size_t)b * T;
    float a0 = 0.f, a1 = 0.f, a2 = 0.f, a3 = 0.f;
    for (int t = 0; t < T; t += 4) {
        a0 += ab[t + 0] * __half2float(kb[(size_t)(t + 0) * 1024]);
        a1 += ab[t + 1] * __half2float(kb[(size_t)(t + 1) * 1024]);
        a2 += ab[t + 2] * __half2float(kb[(size_t)(t + 2) * 1024]);
        a3 += ab[t + 3] * __half2float(kb[(size_t)(t + 3) * 1024]);
    }
    out[(size_t)b * 1024 + h] = (a0 + a1) + (a2 + a3);
}

// fused passage epilogue: per-(b,hchunk) block — local mask+softmax on the 4KB sp
// row, write masked logits (hchunk 0 only), then pool fp16 passage directly.
__global__ __launch_bounds__(256) void poolS_h_k(const float* __restrict__ sp,
                                                 const float* __restrict__ mask,
                                                 const __half* __restrict__ key,
                                                 float* __restrict__ out,
                                                 float* __restrict__ pooled) {
    __shared__ float sa[1024];
    __shared__ float red[8];
    __shared__ float sh;
    const int b = blockIdx.x, tid = threadIdx.x;
    float v4[4];
    float mx = -3.0e38f;
#pragma unroll
    for (int i = 0; i < 4; i++) {
        int t = tid + i * 256;
        float s = (mask[b * 1024 + t] > 0.f) ? sp[b * 1024 + t] : -1e30f;
        if (blockIdx.y == 0) out[b * 1024 + t] = s;
        v4[i] = s;
        mx = fmaxf(mx, s);
    }
    for (int o = 16; o; o >>= 1) mx = fmaxf(mx, __shfl_xor_sync(0xffffffffu, mx, o));
    if ((tid & 31) == 0) red[tid >> 5] = mx;
    __syncthreads();
    if (tid == 0) {
        float v = red[0];
#pragma unroll
        for (int w = 1; w < 8; w++) v = fmaxf(v, red[w]);
        sh = v;
    }
    __syncthreads();
    mx = sh;
    float sum = 0.f;
#pragma unroll
    for (int i = 0; i < 4; i++) {
        v4[i] = expf(v4[i] - mx);
        sum += v4[i];
    }
    for (int o = 16; o; o >>= 1) sum += __shfl_xor_sync(0xffffffffu, sum, o);
    __syncthreads();
    if ((tid & 31) == 0) red[tid >> 5] = sum;
    __syncthreads();
    if (tid == 0) {
        float v = 0.f;
#pragma unroll
        for (int w = 0; w < 8; w++) v += red[w];
        sh = 1.f / v;
    }
    __syncthreads();
    float inv = sh;
#pragma unroll
    for (int i = 0; i < 4; i++) sa[tid + i * 256] = v4[i] * inv;
    __syncthreads();

    // pool over this block's h-chunk
    const int h = blockIdx.y * 256 + tid;
    const __half* kb = key + (size_t)b * 1048576 + h;
    float a0 = 0.f, a1 = 0.f, a2 = 0.f, a3 = 0.f;
    for (int t = 0; t < 1024; t += 4) {
        a0 += sa[t + 0] * __half2float(kb[(size_t)(t + 0) * 1024]);
        a1 += sa[t + 1] * __half2float(kb[(size_t)(t + 1) * 1024]);
        a2 += sa[t + 2] * __half2float(kb[(size_t)(t + 2) * 1024]);
        a3 += sa[t + 3] * __half2float(kb[(size_t)(t + 3) * 1024]);
    }
    pooled[(size_t)b * 1024 + h] = (a0 + a1) + (a2 + a3);
}

// merged batched linear: blocks [0,128) Q1 = x@WqpT (no bias, N=1024);
// blocks [128,512) gh = x@W_hh + b_hh (N=3072). Same x for both.
__global__ __launch_bounds__(256) void rowdot2_k(const float* __restrict__ x,
                                                 const float* __restrict__ W1,
                                                 float* __restrict__ out1,
                                                 const float* __restrict__ W2,
                                                 const float* __restrict__ bias2,
                                                 float* __restrict__ out2) {
    __shared__ float xs[8][1024];
    const int warp = threadIdx.x >> 5, lane = threadIdx.x & 31;
    const int isQ1 = (blockIdx.x < 128);
    const int j = (isQ1 ? blockIdx.x : (blockIdx.x - 128)) * 8 + warp;
    const float* wr = (isQ1 ? W1 : W2) + (size_t)j * 1024;
    float* outp = isQ1 ? out1 : out2;
    const int N = isQ1 ? 1024 : 3072;
    float Wreg[32];
#pragma unroll
    for (int i = 0; i < 32; i++) Wreg[i] = wr[lane + i * 32];
    const float bj = isQ1 ? 0.f : bias2[j];
    for (int bb = 0; bb < 8; bb++) {
        __syncthreads();
#pragma unroll
        for (int jj = 0; jj < 8; jj++) {
            int f = threadIdx.x + jj * 256;
            int row = f >> 8, c4 = f & 255;
            ((float4*)&xs[row][0])[c4] =
                ((const float4*)(x + (size_t)(bb * 8 + row) * 1024))[c4];
        }
        __syncthreads();
#pragma unroll
        for (int r = 0; r < 8; r++) {
            float acc = 0.f;
#pragma unroll
            for (int i = 0; i < 32; i++) acc += xs[r][lane + i * 32] * Wreg[i];
#pragma unroll
            for (int o = 16; o; o >>= 1) acc += __shfl_xor_sync(0xffffffffu, acc, o);
            if (!lane) outp[(size_t)(bb * 8 + r) * N + j] = acc + bj;
        }
    }
}

// batched out[b][j] = bias[j] + dot(x[b], W[j][:]) — W in regs, 8-row chunks
__global__ __launch_bounds__(256) void rowdotB_k(const float* __restrict__ x,
                                                 const float* __restrict__ W,
                                                 const float* __restrict__ bias,
                                                 float* __restrict__ out, int N) {
    __shared__ float xs[8][1024];
    const int warp = threadIdx.x >> 5, lane = threadIdx.x & 31;
    const int j = blockIdx.x * 8 + warp;
    float Wreg[32];
    const float* wr = W + (size_t)j * 1024;
#pragma unroll
    for (int i = 0; i < 32; i++) Wreg[i] = wr[lane + i * 32];
    const float bj = bias[j];
    for (int bb = 0; bb < 8; bb++) {
        __syncthreads();
#pragma unroll
        for (int jj = 0; jj < 8; jj++) {
            int f = threadIdx.x + jj * 256;
            int row = f >> 8, c4 = f & 255;
            ((float4*)&xs[row][0])[c4] =
                ((const float4*)(x + (size_t)(bb * 8 + row) * 1024))[c4];
        }
        __syncthreads();
#pragma unroll
        for (int r = 0; r < 8; r++) {
            float acc = 0.f;
#pragma unroll
            for (int i = 0; i < 32; i++) acc += xs[r][lane + i * 32] * Wreg[i];
#pragma unroll
            for (int o = 16; o; o >>= 1) acc += __shfl_xor_sync(0xffffffffu, acc, o);
            if (!lane) out[(size_t)(bb * 8 + r) * N + j] = acc + bj;
        }
    }
}

__global__ __launch_bounds__(256) void gru_k() {
    const int i = blockIdx.x * 256 + threadIdx.x;
    const int b = i >> 10, h = i & 1023;
    const float* gi = g_gi + (size_t)b * 3072;
    const float* gh = g_gh + (size_t)b * 3072;
    float r = 1.f / (1.f + expf(-(gi[h] + gh[h])));
    float z = 1.f / (1.f + expf(-(gi[1024 + h] + gh[1024 + h])));
    float n = tanhf(gi[2048 + h] + r * gh[2048 + h]);
    g_gout[i] = (1.f - z) * n + z * g_hidden[i];
}

// ---------------- launch ------------------------------------------------------
extern "C" void kernel_launch(void* const* d_in, const int* in_sizes, int n_in,
                              void* d_out, int out_size) {
    const float* question = (const float*)d_in[0];
    const float* qmask    = (const float*)d_in[1];
    const float* passage  = (const float*)d_in[2];
    const float* pmask    = (const float*)d_in[3];
    const float* Vq       = (const float*)d_in[4];
    const float* Wk_q     = (const float*)d_in[5];
    const float* Wq_q     = (const float*)d_in[6];
    const float* w_q      = (const float*)d_in[7];
    const float* Wk_p     = (const float*)d_in[8];
    const float* Wq_p     = (const float*)d_in[9];
    const float* w_p      = (const float*)d_in[10];
    const float* W_ih     = (const float*)d_in[11];
    const float* W_hh     = (const float*)d_in[12];
    const float* b_ih     = (const float*)d_in[13];
    const float* b_hh     = (const float*)d_in[14];
    float* out = (float*)d_out;

    float *psp, *psq, *palpha, *phid, *pinp, *pgout, *pQ1, *pQ2, *pcq, *pgi, *pgh;
    float *pWqpT, *pzb;
    __half *pPKh, *pAh, *pQh, *pBqh, *pBph;
    cudaGetSymbolAddress((void**)&pPKh,  g_PKh);
    cudaGetSymbolAddress((void**)&psp,   g_sp);
    cudaGetSymbolAddress((void**)&psq,   g_sq);
    cudaGetSymbolAddress((void**)&palpha,g_alpha);
    cudaGetSymbolAddress((void**)&phid,  g_hidden);
    cudaGetSymbolAddress((void**)&pinp,  g_inputs);
    cudaGetSymbolAddress((void**)&pgout, g_gout);
    cudaGetSymbolAddress((void**)&pQ1,   g_Q1);
    cudaGetSymbolAddress((void**)&pQ2,   g_Q2);
    cudaGetSymbolAddress((void**)&pcq,   g_cq);
    cudaGetSymbolAddress((void**)&pgi,   g_gi);
    cudaGetSymbolAddress((void**)&pgh,   g_gh);
    cudaGetSymbolAddress((void**)&pAh,   g_Ah);
    cudaGetSymbolAddress((void**)&pQh,   g_Qh);
    cudaGetSymbolAddress((void**)&pBqh,  g_Bqh);
    cudaGetSymbolAddress((void**)&pBph,  g_Bph);
    cudaGetSymbolAddress((void**)&pWqpT, g_WqpT);
    cudaGetSymbolAddress((void**)&pzb,   g_zb);

    cudaFuncSetAttribute(mma2_k,      cudaFuncAttributeMaxDynamicSharedMemorySize, 3 * STG + 1024);
    cudaFuncSetAttribute(gemmq_cvt_k, cudaFuncAttributeMaxDynamicSharedMemorySize, 3 * STG + 1024);

    // independent prep (front-loaded)
    zero_k<<<256, 256>>>(psp);
    zero_k<<<4, 256>>>(pzb);
    zero_k<<<4, 256>>>(pcq);
    cvt3_k<<<6144, 256>>>(Wk_q, pBqh, Wk_p, pBph, question, pQh);
    transpose_k<<<dim3(32, 32), 256>>>(Wq_p, pWqpT);
    xwA_k<<<dim3(4, 8), 256>>>(Vq, Wq_q, pcq);

    // HYBRID: question GEMM (blocks 0..255) + passage cvt (blocks 256..2303)
    gemmq_cvt_k<<<2304, 256, 3 * STG + 1024>>>(pQh, pBqh, pPKh, passage, pAh);

    // question branch tail
    score_h_k<<<512, 256>>>(pPKh, pcq, w_q, qmask, psq, 0);
    softmax_k<<<64, 256>>>(psq, palpha, 64);
    pool_h_k<<<dim3(64, 4), 256>>>(pQh, palpha, phid, 64);
    rowdot2_k<<<512, 256>>>(phid, pWqpT, pQ1, W_hh, b_hh, pgh);    // Q1 + gh, one launch

    // passage GEMM with fused begin-score (computed once)
    mma2_k<<<dim3(8, 512), 256, 3 * STG + 1024>>>(pAh, pBph, pPKh, w_p, pQ1, psp);

    // fused mask + softmax + out-write + pool -> GRU input
    poolS_h_k<<<dim3(64, 4), 256>>>(psp, pmask, pAh, out, pinp);

    // GRU + end logits
    rowdotB_k<<<384, 256>>>(pinp, W_ih, b_ih, pgi, 3072);
    gru_k<<<256, 256>>>();
    rowdotB_k<<<128, 256>>>(pgout, pWqpT, pzb, pQ2, 1024);         // Q2 = gru_out @ Wq_p
    score_h_k<<<8192, 256>>>(pPKh, pQ2, w_p, pmask, out + 65536, 1);
}